// round 2
// baseline (speedup 1.0000x reference)
#include <cuda_runtime.h>
#include <math.h>

#define NV 117000
#define NE 468000
#define EMB 300
#define IN_DIM 768
#define BATCH 4096
#define HID 500
#define FCK (EMB + IN_DIM)   // 1068

// ---------------- device scratch (allocation-free) ----------------
__device__ float g_deg[NV];
__device__ float g_dinv[NV];
__device__ float g_vals[NE];
__device__ float g_bufA[(size_t)NV * EMB];   // 140.4 MB
__device__ float g_bufB[(size_t)NV * EMB];   // 140.4 MB
__device__ float g_fc[(size_t)BATCH * FCK];
__device__ float g_h1[BATCH * HID];
__device__ float g_h2[BATCH * HID];

// ---------------- small kernels ----------------
__global__ void zero_scalar_kernel(float* p, int n) {
    int i = blockIdx.x * blockDim.x + threadIdx.x;
    if (i < n) p[i] = 0.0f;
}

__global__ void zero_vec_kernel(float4* p, int n4) {
    for (int i = blockIdx.x * blockDim.x + threadIdx.x; i < n4;
         i += gridDim.x * blockDim.x)
        p[i] = make_float4(0.f, 0.f, 0.f, 0.f);
}

__global__ void deg_kernel(const int* __restrict__ erow) {
    int e = blockIdx.x * blockDim.x + threadIdx.x;
    if (e < NE) atomicAdd(&g_deg[erow[e]], 1.0f);
}

__global__ void dinv_kernel() {
    int i = blockIdx.x * blockDim.x + threadIdx.x;
    if (i < NV) {
        float d = g_deg[i];
        g_dinv[i] = (d > 0.0f) ? rsqrtf(d) : 0.0f;
    }
}

__global__ void vals_kernel(const int* __restrict__ erow, const int* __restrict__ ecol) {
    int e = blockIdx.x * blockDim.x + threadIdx.x;
    if (e < NE) g_vals[e] = g_dinv[erow[e]] * g_dinv[ecol[e]];
}

// SpMM: out[row] += vals[e] * X[col]   (one warp per edge, EMB=300 = 75 float4)
__global__ void spmm_kernel(const float* __restrict__ X,
                            const int* __restrict__ erow,
                            const int* __restrict__ ecol,
                            float* __restrict__ out) {
    int warp = (blockIdx.x * blockDim.x + threadIdx.x) >> 5;
    int lane = threadIdx.x & 31;
    if (warp >= NE) return;
    int r = erow[warp];
    int c = ecol[warp];
    float v = g_vals[warp];
    const float4* x4 = reinterpret_cast<const float4*>(X + (size_t)c * EMB);
    float* o = out + (size_t)r * EMB;
#pragma unroll
    for (int i = lane; i < 75; i += 32) {
        float4 x = x4[i];
        atomicAdd(o + i * 4 + 0, x.x * v);
        atomicAdd(o + i * 4 + 1, x.y * v);
        atomicAdd(o + i * 4 + 2, x.z * v);
        atomicAdd(o + i * 4 + 3, x.w * v);
    }
}

__global__ void sigmoid_kernel(float4* p, int n4) {
    for (int i = blockIdx.x * blockDim.x + threadIdx.x; i < n4;
         i += gridDim.x * blockDim.x) {
        float4 v = p[i];
        v.x = 1.0f / (1.0f + __expf(-v.x));
        v.y = 1.0f / (1.0f + __expf(-v.y));
        v.z = 1.0f / (1.0f + __expf(-v.z));
        v.w = 1.0f / (1.0f + __expf(-v.w));
        p[i] = v;
    }
}

// build fc = concat(H2[node], input)  -> [BATCH, FCK]
// NOTE: node is int32 (JAX without x64 coerces int64 -> int32).
__global__ void fc_build_kernel(const float* __restrict__ H2,
                                const int* __restrict__ node,
                                const float* __restrict__ input) {
    int idx = blockIdx.x * blockDim.x + threadIdx.x;
    if (idx >= BATCH * FCK) return;
    int b = idx / FCK;
    int j = idx - b * FCK;
    float v;
    if (j < EMB) {
        size_t n = (size_t)node[b];
        v = H2[n * EMB + j];
    } else {
        v = input[(size_t)b * IN_DIM + (j - EMB)];
    }
    g_fc[idx] = v;
}

// ---------------- tiled SGEMM: C[M,N] = A[M,K] @ B[K,N] (+bias, +sigmoid) ---
// BM=128, BN=64, BK=16, 256 threads, 8x4 per-thread microtile.
#define BM 128
#define BN 64
#define BK 16

__global__ void __launch_bounds__(256)
sgemm_kernel(const float* __restrict__ A, const float* __restrict__ B,
             const float* __restrict__ bias, float* __restrict__ C,
             int M, int N, int K, int act) {
    __shared__ __align__(16) float As[BK][BM];   // transposed A tile
    __shared__ __align__(16) float Bs[BK][BN];

    int tid = threadIdx.x;
    int bm = blockIdx.y * BM;
    int bn = blockIdx.x * BN;

    int tx = tid & 15;     // col group (0..15) -> 4 cols each
    int ty = tid >> 4;     // row group (0..15) -> 8 rows each
    int row0 = ty * 8;
    int col0 = tx * 4;

    float acc[8][4];
#pragma unroll
    for (int i = 0; i < 8; i++)
#pragma unroll
        for (int j = 0; j < 4; j++) acc[i][j] = 0.0f;

    for (int k0 = 0; k0 < K; k0 += BK) {
        // ---- load A tile (128x16) : 512 float4, 2 per thread ----
#pragma unroll
        for (int it = 0; it < 2; it++) {
            int f = tid + it * 256;
            int r = f >> 2;            // 0..127
            int kq = (f & 3) * 4;      // 0,4,8,12
            int gr = bm + r;
            int gk = k0 + kq;
            float4 v = make_float4(0.f, 0.f, 0.f, 0.f);
            if (gr < M) {
                if (gk + 3 < K) {
                    v = *reinterpret_cast<const float4*>(A + (size_t)gr * K + gk);
                } else {
                    float t0 = (gk + 0 < K) ? A[(size_t)gr * K + gk + 0] : 0.f;
                    float t1 = (gk + 1 < K) ? A[(size_t)gr * K + gk + 1] : 0.f;
                    float t2 = (gk + 2 < K) ? A[(size_t)gr * K + gk + 2] : 0.f;
                    float t3 = (gk + 3 < K) ? A[(size_t)gr * K + gk + 3] : 0.f;
                    v = make_float4(t0, t1, t2, t3);
                }
            }
            As[kq + 0][r] = v.x;
            As[kq + 1][r] = v.y;
            As[kq + 2][r] = v.z;
            As[kq + 3][r] = v.w;
        }
        // ---- load B tile (16x64): 256 float4, 1 per thread ----
        {
            int kr = tid >> 4;          // 0..15
            int nq = (tid & 15) * 4;    // 0..60
            int gk = k0 + kr;
            int gn = bn + nq;
            float4 v = make_float4(0.f, 0.f, 0.f, 0.f);
            if (gk < K) {
                if (gn + 3 < N) {
                    v = *reinterpret_cast<const float4*>(B + (size_t)gk * N + gn);
                } else {
                    float t0 = (gn + 0 < N) ? B[(size_t)gk * N + gn + 0] : 0.f;
                    float t1 = (gn + 1 < N) ? B[(size_t)gk * N + gn + 1] : 0.f;
                    float t2 = (gn + 2 < N) ? B[(size_t)gk * N + gn + 2] : 0.f;
                    float t3 = (gn + 3 < N) ? B[(size_t)gk * N + gn + 3] : 0.f;
                    v = make_float4(t0, t1, t2, t3);
                }
            }
            *reinterpret_cast<float4*>(&Bs[kr][nq]) = v;
        }
        __syncthreads();

#pragma unroll
        for (int k = 0; k < BK; k++) {
            const float4* As4 = reinterpret_cast<const float4*>(&As[k][0]);
            const float4* Bs4 = reinterpret_cast<const float4*>(&Bs[k][0]);
            float4 a0 = As4[ty * 2 + 0];
            float4 a1 = As4[ty * 2 + 1];
            float4 b0 = Bs4[tx];
            float a[8] = {a0.x, a0.y, a0.z, a0.w, a1.x, a1.y, a1.z, a1.w};
            float b[4] = {b0.x, b0.y, b0.z, b0.w};
#pragma unroll
            for (int i = 0; i < 8; i++)
#pragma unroll
                for (int j = 0; j < 4; j++) acc[i][j] += a[i] * b[j];
        }
        __syncthreads();
    }

    // ---- epilogue ----
#pragma unroll
    for (int i = 0; i < 8; i++) {
        int gr = bm + row0 + i;
        if (gr >= M) continue;
#pragma unroll
        for (int j = 0; j < 4; j++) {
            int gn = bn + col0 + j;
            if (gn >= N) continue;
            float c = acc[i][j];
            if (bias) c += bias[gn];
            if (act) c = 1.0f / (1.0f + __expf(-c));
            C[(size_t)gr * N + gn] = c;
        }
    }
}

// final layer: out[b, 0:2] = h2[b] @ Wc + bc   (one warp per row)
__global__ void final_kernel(const float* __restrict__ h,
                             const float* __restrict__ Wc,
                             const float* __restrict__ bc,
                             float* __restrict__ out) {
    int warp = (blockIdx.x * blockDim.x + threadIdx.x) >> 5;
    int lane = threadIdx.x & 31;
    if (warp >= BATCH) return;
    const float* hr = h + (size_t)warp * HID;
    float a0 = 0.f, a1 = 0.f;
    for (int k = lane; k < HID; k += 32) {
        float hv = hr[k];
        a0 += hv * Wc[k * 2 + 0];
        a1 += hv * Wc[k * 2 + 1];
    }
#pragma unroll
    for (int o = 16; o > 0; o >>= 1) {
        a0 += __shfl_down_sync(0xFFFFFFFFu, a0, o);
        a1 += __shfl_down_sync(0xFFFFFFFFu, a1, o);
    }
    if (lane == 0) {
        out[warp * 2 + 0] = a0 + bc[0];
        out[warp * 2 + 1] = a1 + bc[1];
    }
}

// ---------------- host launch ----------------
extern "C" void kernel_launch(void* const* d_in, const int* in_sizes, int n_in,
                              void* d_out, int out_size) {
    const float*      input = (const float*)d_in[0];
    const int*        node  = (const int*)d_in[1];   // int32 (JAX x64 disabled)
    const int*        erow  = (const int*)d_in[2];
    const int*        ecol  = (const int*)d_in[3];
    const float*      H0    = (const float*)d_in[4];
    const float*      W1    = (const float*)d_in[5];
    const float*      W2    = (const float*)d_in[6];
    const float*      Wa    = (const float*)d_in[7];
    const float*      ba    = (const float*)d_in[8];
    const float*      Wb    = (const float*)d_in[9];
    const float*      bb    = (const float*)d_in[10];
    const float*      Wc    = (const float*)d_in[11];
    const float*      bc    = (const float*)d_in[12];
    float*            out   = (float*)d_out;

    void *p_deg, *p_bufA, *p_bufB, *p_fc, *p_h1, *p_h2;
    cudaGetSymbolAddress(&p_deg,  g_deg);
    cudaGetSymbolAddress(&p_bufA, g_bufA);
    cudaGetSymbolAddress(&p_bufB, g_bufB);
    cudaGetSymbolAddress(&p_fc,   g_fc);
    cudaGetSymbolAddress(&p_h1,   g_h1);
    cudaGetSymbolAddress(&p_h2,   g_h2);

    float* bufA = (float*)p_bufA;
    float* bufB = (float*)p_bufB;
    float* fc   = (float*)p_fc;
    float* h1   = (float*)p_h1;
    float* h2   = (float*)p_h2;

    const int TPB = 256;
    const int nEmb = NV * EMB;            // 35,100,000 (divisible by 4)
    const int nEmb4 = nEmb / 4;

    // 1) degree + normalization values
    zero_scalar_kernel<<<(NV + TPB - 1) / TPB, TPB>>>((float*)p_deg, NV);
    deg_kernel<<<(NE + TPB - 1) / TPB, TPB>>>(erow);
    dinv_kernel<<<(NV + TPB - 1) / TPB, TPB>>>();
    vals_kernel<<<(NE + TPB - 1) / TPB, TPB>>>(erow, ecol);

    // 2) X1 = H0 @ W1
    dim3 gemmBig((EMB + BN - 1) / BN, (NV + BM - 1) / BM);
    sgemm_kernel<<<gemmBig, TPB>>>(H0, W1, nullptr, bufA, NV, EMB, EMB, 0);

    // 3) H1 = sigmoid(spmm(X1))
    zero_vec_kernel<<<2048, TPB>>>((float4*)bufB, nEmb4);
    spmm_kernel<<<(NE * 32 + TPB - 1) / TPB, TPB>>>(bufA, erow, ecol, bufB);
    sigmoid_kernel<<<2048, TPB>>>((float4*)bufB, nEmb4);

    // 4) X2 = H1 @ W2
    sgemm_kernel<<<gemmBig, TPB>>>(bufB, W2, nullptr, bufA, NV, EMB, EMB, 0);

    // 5) H2 = sigmoid(spmm(X2))
    zero_vec_kernel<<<2048, TPB>>>((float4*)bufB, nEmb4);
    spmm_kernel<<<(NE * 32 + TPB - 1) / TPB, TPB>>>(bufA, erow, ecol, bufB);
    sigmoid_kernel<<<2048, TPB>>>((float4*)bufB, nEmb4);

    // 6) fc = concat(H2[node], input)
    fc_build_kernel<<<(BATCH * FCK + TPB - 1) / TPB, TPB>>>(bufB, node, input);

    // 7) h1 = sigmoid(fc @ Wa + ba)
    dim3 gemmA((HID + BN - 1) / BN, (BATCH + BM - 1) / BM);
    sgemm_kernel<<<gemmA, TPB>>>(fc, Wa, ba, h1, BATCH, HID, FCK, 1);

    // 8) h2 = sigmoid(h1 @ Wb + bb)
    sgemm_kernel<<<gemmA, TPB>>>(h1, Wb, bb, h2, BATCH, HID, HID, 1);

    // 9) out = h2 @ Wc + bc
    final_kernel<<<(BATCH * 32 + TPB - 1) / TPB, TPB>>>(h2, Wc, bc, out);
}

// round 4
// speedup vs baseline: 1.7993x; 1.7993x over previous
#include <cuda_runtime.h>
#include <cuda_bf16.h>
#include <math.h>
#include <cstdint>

#define NV 117000
#define NE 468000
#define EMB 300
#define IN_DIM 768
#define BATCH 4096
#define HID 500
#define FCK (EMB + IN_DIM)   // 1068
#define NBLK_SCAN ((NV + 1023) / 1024)   // 115

// ---------------- device scratch (allocation-free) ----------------
__device__ float g_dinv[NV];
__device__ float g_vals[NE];
__device__ int   g_cnt[NV];
__device__ int   g_rowstart[NV + 1];
__device__ int   g_tot[256];
__device__ int   g_cursor[NV];
__device__ int   g_scol[NE];
__device__ float g_sval[NE];
__device__ float g_bufA[(size_t)NV * EMB];
__device__ float g_bufB[(size_t)NV * EMB];
__device__ float g_fc[(size_t)BATCH * FCK];
__device__ float g_h1[BATCH * HID];
__device__ float g_h2[BATCH * HID];

// ================= bf16 split helpers =================
__device__ __forceinline__ void split_bf16(float x, uint16_t& hi, uint16_t& lo) {
    __nv_bfloat16 h = __float2bfloat16_rn(x);
    float r = x - __bfloat162float(h);
    __nv_bfloat16 l = __float2bfloat16_rn(r);
    hi = *reinterpret_cast<uint16_t*>(&h);
    lo = *reinterpret_cast<uint16_t*>(&l);
}

// mma.sync m16n8k16 row.col f32 += bf16*bf16
__device__ __forceinline__ void mma16816(float* c, const uint32_t* a, const uint32_t* b) {
    asm volatile(
        "mma.sync.aligned.m16n8k16.row.col.f32.bf16.bf16.f32 "
        "{%0,%1,%2,%3}, {%4,%5,%6,%7}, {%8,%9}, {%0,%1,%2,%3};"
        : "+f"(c[0]), "+f"(c[1]), "+f"(c[2]), "+f"(c[3])
        : "r"(a[0]), "r"(a[1]), "r"(a[2]), "r"(a[3]),
          "r"(b[0]), "r"(b[1]));
}

// ================= tensor-core GEMM (mma.sync, bf16-split) =================
// C[M,N] = A[M,K] @ W[K,N] (+bias)(+sigmoid). fp32 in/out.
// BM=128, BN=64, BK=32. 256 threads = 8 warps, each warp 32x32.
#define BM 128
#define BN 64
#define BK 32
#define SA 40   // padded stride (u16 elems) for A tiles
#define SB 40   // padded stride for B tiles (stored transposed [n][k])

__global__ void __launch_bounds__(256, 2)
gemm_mma_kernel(const float* __restrict__ A, const float* __restrict__ W,
                const float* __restrict__ bias, float* __restrict__ C,
                int M, int N, int K, int act) {
    __shared__ __align__(16) uint16_t Ahi[BM * SA];
    __shared__ __align__(16) uint16_t Alo[BM * SA];
    __shared__ __align__(16) uint16_t Bhi[BN * SB];
    __shared__ __align__(16) uint16_t Blo[BN * SB];

    int tid = threadIdx.x;
    int w = tid >> 5;
    int lane = tid & 31;
    int g = lane >> 2;
    int t2 = (lane & 3) * 2;

    int bm = blockIdx.y * BM;
    int bn = blockIdx.x * BN;
    int m0 = (w & 3) * 32;
    int n0 = (w >> 2) * 32;

    float acc[2][4][4];
#pragma unroll
    for (int i = 0; i < 2; i++)
#pragma unroll
        for (int j = 0; j < 4; j++)
#pragma unroll
            for (int q = 0; q < 4; q++) acc[i][j][q] = 0.0f;

    for (int k0 = 0; k0 < K; k0 += BK) {
        // ---- A tile: BM x BK fp32 -> hi/lo bf16, 1024 float4 / 256 thr ----
#pragma unroll
        for (int it = 0; it < 4; it++) {
            int v = tid + it * 256;        // 0..1023
            int r = v >> 3;                // row 0..127
            int c4 = v & 7;                // float4 col 0..7
            int gr = bm + r;
            int gk = k0 + c4 * 4;
            float4 x = make_float4(0.f, 0.f, 0.f, 0.f);
            if (gr < M && gk < K)          // K % 4 == 0 always
                x = *reinterpret_cast<const float4*>(A + (size_t)gr * K + gk);
            uint16_t h0, l0, h1, l1, h2, l2, h3, l3;
            split_bf16(x.x, h0, l0);
            split_bf16(x.y, h1, l1);
            split_bf16(x.z, h2, l2);
            split_bf16(x.w, h3, l3);
            int base = r * SA + c4 * 4;
            *reinterpret_cast<uint32_t*>(&Ahi[base])     = (uint32_t)h0 | ((uint32_t)h1 << 16);
            *reinterpret_cast<uint32_t*>(&Ahi[base + 2]) = (uint32_t)h2 | ((uint32_t)h3 << 16);
            *reinterpret_cast<uint32_t*>(&Alo[base])     = (uint32_t)l0 | ((uint32_t)l1 << 16);
            *reinterpret_cast<uint32_t*>(&Alo[base + 2]) = (uint32_t)l2 | ((uint32_t)l3 << 16);
        }
        // ---- B tile: W[k0:+32, bn:+64] -> transposed [n][k] hi/lo ----
#pragma unroll
        for (int it = 0; it < 2; it++) {
            int v = tid + it * 256;        // 0..511
            int kk = v >> 4;               // 0..31
            int n4 = (v & 15) * 4;         // 0..60
            int gk = k0 + kk;
            int gn = bn + n4;
            float4 x = make_float4(0.f, 0.f, 0.f, 0.f);
            if (gk < K && gn < N)          // N % 4 == 0 always
                x = *reinterpret_cast<const float4*>(W + (size_t)gk * N + gn);
            uint16_t h, l;
            split_bf16(x.x, h, l); Bhi[(n4 + 0) * SB + kk] = h; Blo[(n4 + 0) * SB + kk] = l;
            split_bf16(x.y, h, l); Bhi[(n4 + 1) * SB + kk] = h; Blo[(n4 + 1) * SB + kk] = l;
            split_bf16(x.z, h, l); Bhi[(n4 + 2) * SB + kk] = h; Blo[(n4 + 2) * SB + kk] = l;
            split_bf16(x.w, h, l); Bhi[(n4 + 3) * SB + kk] = h; Blo[(n4 + 3) * SB + kk] = l;
        }
        __syncthreads();

#pragma unroll
        for (int kc = 0; kc < BK; kc += 16) {
            uint32_t ah[2][4], al[2][4], bh[4][2], bl[4][2];
#pragma unroll
            for (int i = 0; i < 2; i++) {
                int rm = m0 + i * 16;
                ah[i][0] = *reinterpret_cast<const uint32_t*>(&Ahi[(rm + g)     * SA + kc + t2]);
                ah[i][1] = *reinterpret_cast<const uint32_t*>(&Ahi[(rm + g + 8) * SA + kc + t2]);
                ah[i][2] = *reinterpret_cast<const uint32_t*>(&Ahi[(rm + g)     * SA + kc + t2 + 8]);
                ah[i][3] = *reinterpret_cast<const uint32_t*>(&Ahi[(rm + g + 8) * SA + kc + t2 + 8]);
                al[i][0] = *reinterpret_cast<const uint32_t*>(&Alo[(rm + g)     * SA + kc + t2]);
                al[i][1] = *reinterpret_cast<const uint32_t*>(&Alo[(rm + g + 8) * SA + kc + t2]);
                al[i][2] = *reinterpret_cast<const uint32_t*>(&Alo[(rm + g)     * SA + kc + t2 + 8]);
                al[i][3] = *reinterpret_cast<const uint32_t*>(&Alo[(rm + g + 8) * SA + kc + t2 + 8]);
            }
#pragma unroll
            for (int j = 0; j < 4; j++) {
                int rn = n0 + j * 8;
                bh[j][0] = *reinterpret_cast<const uint32_t*>(&Bhi[(rn + g) * SB + kc + t2]);
                bh[j][1] = *reinterpret_cast<const uint32_t*>(&Bhi[(rn + g) * SB + kc + t2 + 8]);
                bl[j][0] = *reinterpret_cast<const uint32_t*>(&Blo[(rn + g) * SB + kc + t2]);
                bl[j][1] = *reinterpret_cast<const uint32_t*>(&Blo[(rn + g) * SB + kc + t2 + 8]);
            }
#pragma unroll
            for (int i = 0; i < 2; i++)
#pragma unroll
                for (int j = 0; j < 4; j++) {
                    mma16816(acc[i][j], ah[i], bh[j]);
                    mma16816(acc[i][j], ah[i], bl[j]);
                    mma16816(acc[i][j], al[i], bh[j]);
                }
        }
        __syncthreads();
    }

    // ---- epilogue ----
#pragma unroll
    for (int i = 0; i < 2; i++) {
#pragma unroll
        for (int j = 0; j < 4; j++) {
            int gn = bn + n0 + j * 8 + t2;
            if (gn >= N) continue;          // N even; covers gn+1 too
#pragma unroll
            for (int half = 0; half < 2; half++) {
                int gr = bm + m0 + i * 16 + g + half * 8;
                if (gr >= M) continue;
                float2 o;
                o.x = acc[i][j][half * 2 + 0];
                o.y = acc[i][j][half * 2 + 1];
                if (bias) { o.x += bias[gn]; o.y += bias[gn + 1]; }
                if (act) {
                    o.x = 1.0f / (1.0f + __expf(-o.x));
                    o.y = 1.0f / (1.0f + __expf(-o.y));
                }
                *reinterpret_cast<float2*>(C + (size_t)gr * N + gn) = o;
            }
        }
    }
}

// ================= graph preprocessing =================
__global__ void zero_int_kernel(int* p, int n) {
    int i = blockIdx.x * blockDim.x + threadIdx.x;
    if (i < n) p[i] = 0;
}

__global__ void count_kernel(const int* __restrict__ erow) {
    int e = blockIdx.x * blockDim.x + threadIdx.x;
    if (e < NE) atomicAdd(&g_cnt[erow[e]], 1);
}

__global__ void dinv_kernel() {
    int i = blockIdx.x * blockDim.x + threadIdx.x;
    if (i < NV) {
        int d = g_cnt[i];
        g_dinv[i] = (d > 0) ? rsqrtf((float)d) : 0.0f;
    }
}

__global__ void vals_kernel(const int* __restrict__ erow, const int* __restrict__ ecol) {
    int e = blockIdx.x * blockDim.x + threadIdx.x;
    if (e < NE) g_vals[e] = g_dinv[erow[e]] * g_dinv[ecol[e]];
}

__global__ void scanA_kernel() {
    __shared__ int s[1024];
    int i = blockIdx.x * 1024 + threadIdx.x;
    int v = (i < NV) ? g_cnt[i] : 0;
    s[threadIdx.x] = v;
    __syncthreads();
    for (int o = 1; o < 1024; o <<= 1) {
        int t = 0;
        if (threadIdx.x >= o) t = s[threadIdx.x - o];
        __syncthreads();
        if (threadIdx.x >= o) s[threadIdx.x] += t;
        __syncthreads();
    }
    if (i < NV) g_rowstart[i] = s[threadIdx.x] - v;   // exclusive
    if (threadIdx.x == 1023) g_tot[blockIdx.x] = s[1023];
}

__global__ void scanB_kernel() {
    __shared__ int s[128];
    int v = (threadIdx.x < NBLK_SCAN) ? g_tot[threadIdx.x] : 0;
    s[threadIdx.x] = v;
    __syncthreads();
    for (int o = 1; o < 128; o <<= 1) {
        int t = 0;
        if (threadIdx.x >= o) t = s[threadIdx.x - o];
        __syncthreads();
        if (threadIdx.x >= o) s[threadIdx.x] += t;
        __syncthreads();
    }
    if (threadIdx.x < NBLK_SCAN) g_tot[threadIdx.x] = s[threadIdx.x] - v;
}

__global__ void scanC_kernel() {
    int i = blockIdx.x * blockDim.x + threadIdx.x;
    if (i < NV) g_rowstart[i] += g_tot[i >> 10];
    if (i == 0) g_rowstart[NV] = NE;
}

__global__ void scatter_kernel(const int* __restrict__ erow, const int* __restrict__ ecol) {
    int e = blockIdx.x * blockDim.x + threadIdx.x;
    if (e >= NE) return;
    int r = erow[e];
    int pos = g_rowstart[r] + atomicAdd(&g_cursor[r], 1);
    g_scol[pos] = ecol[e];
    g_sval[pos] = g_vals[e];
}

// ================= pull SpMM + fused sigmoid =================
// out[r] = sigmoid( sum_j val_j * X[col_j] ), one warp per row, EMB=300=75 float4
__global__ void spmm_pull_kernel(const float* __restrict__ X, float* __restrict__ out) {
    int warp = (blockIdx.x * blockDim.x + threadIdx.x) >> 5;
    int lane = threadIdx.x & 31;
    if (warp >= NV) return;
    int s = g_rowstart[warp];
    int e = g_rowstart[warp + 1];
    float4 a0 = make_float4(0.f, 0.f, 0.f, 0.f);
    float4 a1 = make_float4(0.f, 0.f, 0.f, 0.f);
    float4 a2 = make_float4(0.f, 0.f, 0.f, 0.f);
    for (int j = s; j < e; j++) {
        int c = g_scol[j];
        float v = g_sval[j];
        const float4* x4 = reinterpret_cast<const float4*>(X + (size_t)c * EMB);
        float4 t0 = x4[lane];
        a0.x += v * t0.x; a0.y += v * t0.y; a0.z += v * t0.z; a0.w += v * t0.w;
        float4 t1 = x4[lane + 32];
        a1.x += v * t1.x; a1.y += v * t1.y; a1.z += v * t1.z; a1.w += v * t1.w;
        if (lane < 11) {
            float4 t2 = x4[lane + 64];
            a2.x += v * t2.x; a2.y += v * t2.y; a2.z += v * t2.z; a2.w += v * t2.w;
        }
    }
    a0.x = 1.0f / (1.0f + __expf(-a0.x)); a0.y = 1.0f / (1.0f + __expf(-a0.y));
    a0.z = 1.0f / (1.0f + __expf(-a0.z)); a0.w = 1.0f / (1.0f + __expf(-a0.w));
    a1.x = 1.0f / (1.0f + __expf(-a1.x)); a1.y = 1.0f / (1.0f + __expf(-a1.y));
    a1.z = 1.0f / (1.0f + __expf(-a1.z)); a1.w = 1.0f / (1.0f + __expf(-a1.w));
    a2.x = 1.0f / (1.0f + __expf(-a2.x)); a2.y = 1.0f / (1.0f + __expf(-a2.y));
    a2.z = 1.0f / (1.0f + __expf(-a2.z)); a2.w = 1.0f / (1.0f + __expf(-a2.w));
    float4* o4 = reinterpret_cast<float4*>(out + (size_t)warp * EMB);
    o4[lane] = a0;
    o4[lane + 32] = a1;
    if (lane < 11) o4[lane + 64] = a2;
}

// build fc = concat(H2[node], input)
__global__ void fc_build_kernel(const float* __restrict__ H2,
                                const int* __restrict__ node,
                                const float* __restrict__ input) {
    int idx = blockIdx.x * blockDim.x + threadIdx.x;
    if (idx >= BATCH * FCK) return;
    int b = idx / FCK;
    int j = idx - b * FCK;
    float v;
    if (j < EMB) {
        size_t n = (size_t)node[b];
        v = H2[n * EMB + j];
    } else {
        v = input[(size_t)b * IN_DIM + (j - EMB)];
    }
    g_fc[idx] = v;
}

// final layer: out[b, 0:2] = h2[b] @ Wc + bc   (one warp per row)
__global__ void final_kernel(const float* __restrict__ h,
                             const float* __restrict__ Wc,
                             const float* __restrict__ bc,
                             float* __restrict__ out) {
    int warp = (blockIdx.x * blockDim.x + threadIdx.x) >> 5;
    int lane = threadIdx.x & 31;
    if (warp >= BATCH) return;
    const float* hr = h + (size_t)warp * HID;
    float a0 = 0.f, a1 = 0.f;
    for (int k = lane; k < HID; k += 32) {
        float hv = hr[k];
        a0 += hv * Wc[k * 2 + 0];
        a1 += hv * Wc[k * 2 + 1];
    }
#pragma unroll
    for (int o = 16; o > 0; o >>= 1) {
        a0 += __shfl_down_sync(0xFFFFFFFFu, a0, o);
        a1 += __shfl_down_sync(0xFFFFFFFFu, a1, o);
    }
    if (lane == 0) {
        out[warp * 2 + 0] = a0 + bc[0];
        out[warp * 2 + 1] = a1 + bc[1];
    }
}

// ================= host launch =================
extern "C" void kernel_launch(void* const* d_in, const int* in_sizes, int n_in,
                              void* d_out, int out_size) {
    const float* input = (const float*)d_in[0];
    const int*   node  = (const int*)d_in[1];
    const int*   erow  = (const int*)d_in[2];
    const int*   ecol  = (const int*)d_in[3];
    const float* H0    = (const float*)d_in[4];
    const float* W1    = (const float*)d_in[5];
    const float* W2    = (const float*)d_in[6];
    const float* Wa    = (const float*)d_in[7];
    const float* ba    = (const float*)d_in[8];
    const float* Wb    = (const float*)d_in[9];
    const float* bb    = (const float*)d_in[10];
    const float* Wc    = (const float*)d_in[11];
    const float* bc    = (const float*)d_in[12];
    float*       out   = (float*)d_out;

    void *p_cnt, *p_cursor, *p_bufA, *p_bufB, *p_fc, *p_h1, *p_h2;
    cudaGetSymbolAddress(&p_cnt,    g_cnt);
    cudaGetSymbolAddress(&p_cursor, g_cursor);
    cudaGetSymbolAddress(&p_bufA,   g_bufA);
    cudaGetSymbolAddress(&p_bufB,   g_bufB);
    cudaGetSymbolAddress(&p_fc,     g_fc);
    cudaGetSymbolAddress(&p_h1,     g_h1);
    cudaGetSymbolAddress(&p_h2,     g_h2);

    float* bufA = (float*)p_bufA;
    float* bufB = (float*)p_bufB;
    float* fc   = (float*)p_fc;
    float* h1   = (float*)p_h1;
    float* h2   = (float*)p_h2;

    const int TPB = 256;

    // ---- CSR build + normalization ----
    zero_int_kernel<<<(NV + TPB - 1) / TPB, TPB>>>((int*)p_cnt, NV);
    count_kernel<<<(NE + TPB - 1) / TPB, TPB>>>(erow);
    dinv_kernel<<<(NV + TPB - 1) / TPB, TPB>>>();
    vals_kernel<<<(NE + TPB - 1) / TPB, TPB>>>(erow, ecol);
    scanA_kernel<<<NBLK_SCAN, 1024>>>();
    scanB_kernel<<<1, 128>>>();
    scanC_kernel<<<(NV + TPB - 1) / TPB, TPB>>>();
    zero_int_kernel<<<(NV + TPB - 1) / TPB, TPB>>>((int*)p_cursor, NV);
    scatter_kernel<<<(NE + TPB - 1) / TPB, TPB>>>(erow, ecol);

    // ---- GCN layer 1 ----
    dim3 gemmBig((EMB + BN - 1) / BN, (NV + BM - 1) / BM);
    gemm_mma_kernel<<<gemmBig, 256>>>(H0, W1, nullptr, bufA, NV, EMB, EMB, 0);
    spmm_pull_kernel<<<(NV * 32 + TPB - 1) / TPB, TPB>>>(bufA, bufB);  // H1

    // ---- GCN layer 2 ----
    gemm_mma_kernel<<<gemmBig, 256>>>(bufB, W2, nullptr, bufA, NV, EMB, EMB, 0);
    spmm_pull_kernel<<<(NV * 32 + TPB - 1) / TPB, TPB>>>(bufA, bufB);  // H2

    // ---- MLP head ----
    fc_build_kernel<<<(BATCH * FCK + TPB - 1) / TPB, TPB>>>(bufB, node, input);

    dim3 gemmA((HID + BN - 1) / BN, (BATCH + BM - 1) / BM);
    gemm_mma_kernel<<<gemmA, 256>>>(fc, Wa, ba, h1, BATCH, HID, FCK, 1);
    gemm_mma_kernel<<<gemmA, 256>>>(h1, Wb, bb, h2, BATCH, HID, HID, 1);

    final_kernel<<<(BATCH * 32 + TPB - 1) / TPB, TPB>>>(h2, Wc, bc, out);
}

// round 5
// speedup vs baseline: 2.2441x; 1.2472x over previous
#include <cuda_runtime.h>
#include <cuda_bf16.h>
#include <math.h>
#include <cstdint>

#define NV 117000
#define NE 468000
#define EMB 300
#define IN_DIM 768
#define BATCH 4096
#define HID 500
#define FCK (EMB + IN_DIM)   // 1068
#define NBLK_SCAN ((NV + 1023) / 1024)   // 115
#define AP 320               // padded bf16 stride for presplit activations / weights

// ---------------- device scratch (allocation-free, zero-initialized) -------
__device__ float g_dinv[NV];
__device__ float g_vals[NE];
__device__ int   g_cnt[NV];
__device__ int   g_rowstart[NV + 1];
__device__ int   g_tot[256];
__device__ int   g_cursor[NV];
__device__ int   g_scol[NE];
__device__ float g_sval[NE];
__device__ float g_bufA[(size_t)NV * EMB];
__device__ float g_bufB[(size_t)NV * EMB];
__device__ float g_fc[(size_t)BATCH * FCK];
__device__ float g_h1[BATCH * HID];
__device__ float g_h2[BATCH * HID];
// presplit bf16 buffers (pads stay statically zero — never written)
__device__ uint16_t g_ahi[(size_t)NV * AP];
__device__ uint16_t g_alo[(size_t)NV * AP];
__device__ uint16_t g_w1thi[AP * AP];
__device__ uint16_t g_w1tlo[AP * AP];
__device__ uint16_t g_w2thi[AP * AP];
__device__ uint16_t g_w2tlo[AP * AP];

// ================= helpers =================
__device__ __forceinline__ void split_bf16(float x, uint16_t& hi, uint16_t& lo) {
    __nv_bfloat16 h = __float2bfloat16_rn(x);
    float r = x - __bfloat162float(h);
    __nv_bfloat16 l = __float2bfloat16_rn(r);
    hi = *reinterpret_cast<uint16_t*>(&h);
    lo = *reinterpret_cast<uint16_t*>(&l);
}

__device__ __forceinline__ void mma16816(float* c, const uint32_t* a, const uint32_t* b) {
    asm volatile(
        "mma.sync.aligned.m16n8k16.row.col.f32.bf16.bf16.f32 "
        "{%0,%1,%2,%3}, {%4,%5,%6,%7}, {%8,%9}, {%0,%1,%2,%3};"
        : "+f"(c[0]), "+f"(c[1]), "+f"(c[2]), "+f"(c[3])
        : "r"(a[0]), "r"(a[1]), "r"(a[2]), "r"(a[3]),
          "r"(b[0]), "r"(b[1]));
}

__device__ __forceinline__ uint32_t cvta_shared_u32(const void* p) {
    uint32_t a;
    asm("{ .reg .u64 t; cvta.to.shared.u64 t, %1; cvt.u32.u64 %0, t; }"
        : "=r"(a) : "l"(p));
    return a;
}

__device__ __forceinline__ void cp_async16(uint32_t dst, const void* src) {
    asm volatile("cp.async.ca.shared.global [%0], [%1], 16;" :: "r"(dst), "l"(src));
}
__device__ __forceinline__ void cp_commit() {
    asm volatile("cp.async.commit_group;");
}
__device__ __forceinline__ void cp_wait0() {
    asm volatile("cp.async.wait_group 0;");
}

// ================= presplit kernels =================
// H0 fp32 [NV,300] -> g_ahi/g_alo bf16 [NV,320] (pads already zero)
__global__ void presplit_act_kernel(const float* __restrict__ X) {
    int idx = blockIdx.x * blockDim.x + threadIdx.x;   // over NV*75 float4
    if (idx >= NV * 75) return;
    int r = idx / 75;
    int q = idx - r * 75;
    float4 v = reinterpret_cast<const float4*>(X)[ (size_t)r * 75 + q ];
    uint16_t h0,l0,h1,l1,h2,l2,h3,l3;
    split_bf16(v.x,h0,l0); split_bf16(v.y,h1,l1);
    split_bf16(v.z,h2,l2); split_bf16(v.w,h3,l3);
    size_t o = (size_t)r * AP + q * 4;
    *reinterpret_cast<uint2*>(&g_ahi[o]) =
        make_uint2((uint32_t)h0 | ((uint32_t)h1 << 16), (uint32_t)h2 | ((uint32_t)h3 << 16));
    *reinterpret_cast<uint2*>(&g_alo[o]) =
        make_uint2((uint32_t)l0 | ((uint32_t)l1 << 16), (uint32_t)l2 | ((uint32_t)l3 << 16));
}

// W [300,300] row-major -> transposed bf16 [n*320+k]
__global__ void presplit_w_kernel(const float* __restrict__ W,
                                  uint16_t* __restrict__ thi, uint16_t* __restrict__ tlo) {
    int idx = blockIdx.x * blockDim.x + threadIdx.x;
    if (idx >= EMB * EMB) return;
    int k = idx / EMB;
    int n = idx - k * EMB;
    uint16_t h, l;
    split_bf16(W[idx], h, l);
    thi[n * AP + k] = h;
    tlo[n * AP + k] = l;
}

// ================= big tensor-core GEMM (pre-split bf16 in, fp32 out) ======
// C[M,300] = A[M,300] @ W[300,300]; A from (ahi,alo) stride 320, W from
// transposed (wthi,wtlo) [320][320]. BM=128, BN=160, BK=32, 512 threads.
#define GB_SM_ABUF 20480                 // bytes per A double-buffer slot (hi+lo)
#define GB_SM_BBUF 25600                 // bytes per B slot (hi+lo)
#define GB_SM_BOFF (2 * GB_SM_ABUF)      // 40960
#define GB_SM_TOTAL (GB_SM_BOFF + 2 * GB_SM_BBUF)   // 92160

__global__ void __launch_bounds__(512, 1)
gemm_big_kernel(const uint16_t* __restrict__ ahi, const uint16_t* __restrict__ alo,
                const uint16_t* __restrict__ bthi, const uint16_t* __restrict__ btlo,
                float* __restrict__ C, int M) {
    extern __shared__ __align__(16) char sm[];
    int tid = threadIdx.x;
    int w = tid >> 5;
    int lane = tid & 31;
    int g = lane >> 2;
    int t2 = (lane & 3) * 2;

    int bm = blockIdx.y * 128;
    int bn = blockIdx.x * 160;
    int m0 = (w & 3) * 32;
    int n0 = (w >> 2) * 40;

    float acc[2][5][4];
#pragma unroll
    for (int i = 0; i < 2; i++)
#pragma unroll
        for (int j = 0; j < 5; j++)
#pragma unroll
            for (int q = 0; q < 4; q++) acc[i][j][q] = 0.0f;

    // prefetch lambda (ch: 0..9, buf: 0/1)
    auto prefetch = [&](int ch, int buf) {
        int k0 = ch * 32;
        {   // A: 128 rows x 32 bf16 = 512 x 16B (hi) + 512 (lo); 1 each/thread
            int r = tid >> 2;
            int c = tid & 3;
            int gr = bm + r;
            if (gr > M - 1) gr = M - 1;   // clamp: garbage rows never stored
            size_t so = (size_t)gr * AP + k0 + c * 8;
            uint32_t d = cvta_shared_u32(sm + buf * GB_SM_ABUF + (r * 40 + c * 8) * 2);
            cp_async16(d, ahi + so);
            cp_async16(d + 10240, alo + so);
        }
#pragma unroll
        for (int it = 0; it < 2; it++) {  // B: 160 rows x 32 bf16 = 640 x 16B
            int idx = tid + it * 512;
            if (idx < 640) {
                int r = idx >> 2;
                int c = idx & 3;
                size_t so = (size_t)(bn + r) * AP + k0 + c * 8;
                uint32_t d = cvta_shared_u32(sm + GB_SM_BOFF + buf * GB_SM_BBUF +
                                             (r * 40 + c * 8) * 2);
                cp_async16(d, bthi + so);
                cp_async16(d + 12800, btlo + so);
            }
        }
    };

    prefetch(0, 0);
    cp_commit();

    for (int ch = 0; ch < 10; ch++) {
        int buf = ch & 1;
        cp_wait0();
        __syncthreads();
        if (ch < 9) {
            prefetch(ch + 1, buf ^ 1);
            cp_commit();
        }
        const uint16_t* Ah = reinterpret_cast<const uint16_t*>(sm + buf * GB_SM_ABUF);
        const uint16_t* Al = Ah + 5120;
        const uint16_t* Bh = reinterpret_cast<const uint16_t*>(sm + GB_SM_BOFF + buf * GB_SM_BBUF);
        const uint16_t* Bl = Bh + 6400;

#pragma unroll
        for (int kc = 0; kc < 32; kc += 16) {
            uint32_t ah[2][4], al[2][4];
#pragma unroll
            for (int i = 0; i < 2; i++) {
                int rm = m0 + i * 16;
                ah[i][0] = *reinterpret_cast<const uint32_t*>(&Ah[(rm + g)     * 40 + kc + t2]);
                ah[i][1] = *reinterpret_cast<const uint32_t*>(&Ah[(rm + g + 8) * 40 + kc + t2]);
                ah[i][2] = *reinterpret_cast<const uint32_t*>(&Ah[(rm + g)     * 40 + kc + t2 + 8]);
                ah[i][3] = *reinterpret_cast<const uint32_t*>(&Ah[(rm + g + 8) * 40 + kc + t2 + 8]);
                al[i][0] = *reinterpret_cast<const uint32_t*>(&Al[(rm + g)     * 40 + kc + t2]);
                al[i][1] = *reinterpret_cast<const uint32_t*>(&Al[(rm + g + 8) * 40 + kc + t2]);
                al[i][2] = *reinterpret_cast<const uint32_t*>(&Al[(rm + g)     * 40 + kc + t2 + 8]);
                al[i][3] = *reinterpret_cast<const uint32_t*>(&Al[(rm + g + 8) * 40 + kc + t2 + 8]);
            }
#pragma unroll
            for (int j = 0; j < 5; j++) {
                int rn = n0 + j * 8;
                uint32_t bh[2], bl[2];
                bh[0] = *reinterpret_cast<const uint32_t*>(&Bh[(rn + g) * 40 + kc + t2]);
                bh[1] = *reinterpret_cast<const uint32_t*>(&Bh[(rn + g) * 40 + kc + t2 + 8]);
                bl[0] = *reinterpret_cast<const uint32_t*>(&Bl[(rn + g) * 40 + kc + t2]);
                bl[1] = *reinterpret_cast<const uint32_t*>(&Bl[(rn + g) * 40 + kc + t2 + 8]);
#pragma unroll
                for (int i = 0; i < 2; i++) {
                    mma16816(acc[i][j], ah[i], bh);
                    mma16816(acc[i][j], ah[i], bl);
                    mma16816(acc[i][j], al[i], bh);
                }
            }
        }
        __syncthreads();
    }

    // epilogue: fp32 out, stride 300
#pragma unroll
    for (int i = 0; i < 2; i++) {
#pragma unroll
        for (int j = 0; j < 5; j++) {
            int gn = bn + n0 + j * 8 + t2;
            if (gn >= EMB) continue;      // EMB even, gn even -> gn+1 safe
#pragma unroll
            for (int half = 0; half < 2; half++) {
                int gr = bm + m0 + i * 16 + g + half * 8;
                if (gr >= M) continue;
                float2 o;
                o.x = acc[i][j][half * 2 + 0];
                o.y = acc[i][j][half * 2 + 1];
                *reinterpret_cast<float2*>(C + (size_t)gr * EMB + gn) = o;
            }
        }
    }
}

// ================= MLP GEMM (mma.sync, in-kernel split) — from R4 ==========
#define BM 128
#define BN 64
#define BK 32
#define SA 40
#define SB 40

__global__ void __launch_bounds__(256, 2)
gemm_mma_kernel(const float* __restrict__ A, const float* __restrict__ W,
                const float* __restrict__ bias, float* __restrict__ C,
                int M, int N, int K, int act) {
    __shared__ __align__(16) uint16_t Ahi[BM * SA];
    __shared__ __align__(16) uint16_t Alo[BM * SA];
    __shared__ __align__(16) uint16_t Bhi[BN * SB];
    __shared__ __align__(16) uint16_t Blo[BN * SB];

    int tid = threadIdx.x;
    int w = tid >> 5;
    int lane = tid & 31;
    int g = lane >> 2;
    int t2 = (lane & 3) * 2;

    int bm = blockIdx.y * BM;
    int bn = blockIdx.x * BN;
    int m0 = (w & 3) * 32;
    int n0 = (w >> 2) * 32;

    float acc[2][4][4];
#pragma unroll
    for (int i = 0; i < 2; i++)
#pragma unroll
        for (int j = 0; j < 4; j++)
#pragma unroll
            for (int q = 0; q < 4; q++) acc[i][j][q] = 0.0f;

    for (int k0 = 0; k0 < K; k0 += BK) {
#pragma unroll
        for (int it = 0; it < 4; it++) {
            int v = tid + it * 256;
            int r = v >> 3;
            int c4 = v & 7;
            int gr = bm + r;
            int gk = k0 + c4 * 4;
            float4 x = make_float4(0.f, 0.f, 0.f, 0.f);
            if (gr < M && gk < K)
                x = *reinterpret_cast<const float4*>(A + (size_t)gr * K + gk);
            uint16_t h0,l0,h1,l1,h2,l2,h3,l3;
            split_bf16(x.x,h0,l0); split_bf16(x.y,h1,l1);
            split_bf16(x.z,h2,l2); split_bf16(x.w,h3,l3);
            int base = r * SA + c4 * 4;
            *reinterpret_cast<uint32_t*>(&Ahi[base])     = (uint32_t)h0 | ((uint32_t)h1 << 16);
            *reinterpret_cast<uint32_t*>(&Ahi[base + 2]) = (uint32_t)h2 | ((uint32_t)h3 << 16);
            *reinterpret_cast<uint32_t*>(&Alo[base])     = (uint32_t)l0 | ((uint32_t)l1 << 16);
            *reinterpret_cast<uint32_t*>(&Alo[base + 2]) = (uint32_t)l2 | ((uint32_t)l3 << 16);
        }
#pragma unroll
        for (int it = 0; it < 2; it++) {
            int v = tid + it * 256;
            int kk = v >> 4;
            int n4 = (v & 15) * 4;
            int gk = k0 + kk;
            int gn = bn + n4;
            float4 x = make_float4(0.f, 0.f, 0.f, 0.f);
            if (gk < K && gn < N)
                x = *reinterpret_cast<const float4*>(W + (size_t)gk * N + gn);
            uint16_t h, l;
            split_bf16(x.x,h,l); Bhi[(n4+0)*SB+kk]=h; Blo[(n4+0)*SB+kk]=l;
            split_bf16(x.y,h,l); Bhi[(n4+1)*SB+kk]=h; Blo[(n4+1)*SB+kk]=l;
            split_bf16(x.z,h,l); Bhi[(n4+2)*SB+kk]=h; Blo[(n4+2)*SB+kk]=l;
            split_bf16(x.w,h,l); Bhi[(n4+3)*SB+kk]=h; Blo[(n4+3)*SB+kk]=l;
        }
        __syncthreads();

#pragma unroll
        for (int kc = 0; kc < BK; kc += 16) {
            uint32_t ah[2][4], al[2][4], bh[4][2], bl[4][2];
#pragma unroll
            for (int i = 0; i < 2; i++) {
                int rm = m0 + i * 16;
                ah[i][0] = *reinterpret_cast<const uint32_t*>(&Ahi[(rm+g)    *SA + kc+t2]);
                ah[i][1] = *reinterpret_cast<const uint32_t*>(&Ahi[(rm+g+8)  *SA + kc+t2]);
                ah[i][2] = *reinterpret_cast<const uint32_t*>(&Ahi[(rm+g)    *SA + kc+t2+8]);
                ah[i][3] = *reinterpret_cast<const uint32_t*>(&Ahi[(rm+g+8)  *SA + kc+t2+8]);
                al[i][0] = *reinterpret_cast<const uint32_t*>(&Alo[(rm+g)    *SA + kc+t2]);
                al[i][1] = *reinterpret_cast<const uint32_t*>(&Alo[(rm+g+8)  *SA + kc+t2]);
                al[i][2] = *reinterpret_cast<const uint32_t*>(&Alo[(rm+g)    *SA + kc+t2+8]);
                al[i][3] = *reinterpret_cast<const uint32_t*>(&Alo[(rm+g+8)  *SA + kc+t2+8]);
            }
#pragma unroll
            for (int j = 0; j < 4; j++) {
                int rn = n0 + j * 8;
                bh[j][0] = *reinterpret_cast<const uint32_t*>(&Bhi[(rn+g)*SB + kc+t2]);
                bh[j][1] = *reinterpret_cast<const uint32_t*>(&Bhi[(rn+g)*SB + kc+t2+8]);
                bl[j][0] = *reinterpret_cast<const uint32_t*>(&Blo[(rn+g)*SB + kc+t2]);
                bl[j][1] = *reinterpret_cast<const uint32_t*>(&Blo[(rn+g)*SB + kc+t2+8]);
            }
#pragma unroll
            for (int i = 0; i < 2; i++)
#pragma unroll
                for (int j = 0; j < 4; j++) {
                    mma16816(acc[i][j], ah[i], bh[j]);
                    mma16816(acc[i][j], ah[i], bl[j]);
                    mma16816(acc[i][j], al[i], bh[j]);
                }
        }
        __syncthreads();
    }

#pragma unroll
    for (int i = 0; i < 2; i++) {
#pragma unroll
        for (int j = 0; j < 4; j++) {
            int gn = bn + n0 + j * 8 + t2;
            if (gn >= N) continue;
#pragma unroll
            for (int half = 0; half < 2; half++) {
                int gr = bm + m0 + i * 16 + g + half * 8;
                if (gr >= M) continue;
                float2 o;
                o.x = acc[i][j][half * 2 + 0];
                o.y = acc[i][j][half * 2 + 1];
                if (bias) { o.x += bias[gn]; o.y += bias[gn + 1]; }
                if (act) {
                    o.x = 1.0f / (1.0f + __expf(-o.x));
                    o.y = 1.0f / (1.0f + __expf(-o.y));
                }
                *reinterpret_cast<float2*>(C + (size_t)gr * N + gn) = o;
            }
        }
    }
}

// ================= graph preprocessing =================
__global__ void zero_int_kernel(int* p, int n) {
    int i = blockIdx.x * blockDim.x + threadIdx.x;
    if (i < n) p[i] = 0;
}

__global__ void count_kernel(const int* __restrict__ erow) {
    int e = blockIdx.x * blockDim.x + threadIdx.x;
    if (e < NE) atomicAdd(&g_cnt[erow[e]], 1);
}

__global__ void dinv_kernel() {
    int i = blockIdx.x * blockDim.x + threadIdx.x;
    if (i < NV) {
        int d = g_cnt[i];
        g_dinv[i] = (d > 0) ? rsqrtf((float)d) : 0.0f;
    }
}

__global__ void vals_kernel(const int* __restrict__ erow, const int* __restrict__ ecol) {
    int e = blockIdx.x * blockDim.x + threadIdx.x;
    if (e < NE) g_vals[e] = g_dinv[erow[e]] * g_dinv[ecol[e]];
}

__global__ void scanA_kernel() {
    __shared__ int s[1024];
    int i = blockIdx.x * 1024 + threadIdx.x;
    int v = (i < NV) ? g_cnt[i] : 0;
    s[threadIdx.x] = v;
    __syncthreads();
    for (int o = 1; o < 1024; o <<= 1) {
        int t = 0;
        if (threadIdx.x >= o) t = s[threadIdx.x - o];
        __syncthreads();
        if (threadIdx.x >= o) s[threadIdx.x] += t;
        __syncthreads();
    }
    if (i < NV) g_rowstart[i] = s[threadIdx.x] - v;
    if (threadIdx.x == 1023) g_tot[blockIdx.x] = s[1023];
}

__global__ void scanB_kernel() {
    __shared__ int s[128];
    int v = (threadIdx.x < NBLK_SCAN) ? g_tot[threadIdx.x] : 0;
    s[threadIdx.x] = v;
    __syncthreads();
    for (int o = 1; o < 128; o <<= 1) {
        int t = 0;
        if (threadIdx.x >= o) t = s[threadIdx.x - o];
        __syncthreads();
        if (threadIdx.x >= o) s[threadIdx.x] += t;
        __syncthreads();
    }
    if (threadIdx.x < NBLK_SCAN) g_tot[threadIdx.x] = s[threadIdx.x] - v;
}

__global__ void scanC_kernel() {
    int i = blockIdx.x * blockDim.x + threadIdx.x;
    if (i < NV) g_rowstart[i] += g_tot[i >> 10];
    if (i == 0) g_rowstart[NV] = NE;
}

__global__ void scatter_kernel(const int* __restrict__ erow, const int* __restrict__ ecol) {
    int e = blockIdx.x * blockDim.x + threadIdx.x;
    if (e >= NE) return;
    int r = erow[e];
    int pos = g_rowstart[r] + atomicAdd(&g_cursor[r], 1);
    g_scol[pos] = ecol[e];
    g_sval[pos] = g_vals[e];
}

// ================= pull SpMM + fused sigmoid =================
// core: computes sigmoid(sum val*X[col]) for one warp-row into a0,a1,a2
__device__ __forceinline__ void spmm_row(const float* __restrict__ X, int row, int lane,
                                         float4& a0, float4& a1, float4& a2) {
    int s = g_rowstart[row];
    int e = g_rowstart[row + 1];
    a0 = make_float4(0.f,0.f,0.f,0.f);
    a1 = make_float4(0.f,0.f,0.f,0.f);
    a2 = make_float4(0.f,0.f,0.f,0.f);
    for (int j = s; j < e; j++) {
        int c = g_scol[j];
        float v = g_sval[j];
        const float4* x4 = reinterpret_cast<const float4*>(X + (size_t)c * EMB);
        float4 t0 = x4[lane];
        a0.x += v*t0.x; a0.y += v*t0.y; a0.z += v*t0.z; a0.w += v*t0.w;
        float4 t1 = x4[lane + 32];
        a1.x += v*t1.x; a1.y += v*t1.y; a1.z += v*t1.z; a1.w += v*t1.w;
        if (lane < 11) {
            float4 t2 = x4[lane + 64];
            a2.x += v*t2.x; a2.y += v*t2.y; a2.z += v*t2.z; a2.w += v*t2.w;
        }
    }
    a0.x = 1.0f/(1.0f+__expf(-a0.x)); a0.y = 1.0f/(1.0f+__expf(-a0.y));
    a0.z = 1.0f/(1.0f+__expf(-a0.z)); a0.w = 1.0f/(1.0f+__expf(-a0.w));
    a1.x = 1.0f/(1.0f+__expf(-a1.x)); a1.y = 1.0f/(1.0f+__expf(-a1.y));
    a1.z = 1.0f/(1.0f+__expf(-a1.z)); a1.w = 1.0f/(1.0f+__expf(-a1.w));
    a2.x = 1.0f/(1.0f+__expf(-a2.x)); a2.y = 1.0f/(1.0f+__expf(-a2.y));
    a2.z = 1.0f/(1.0f+__expf(-a2.z)); a2.w = 1.0f/(1.0f+__expf(-a2.w));
}

__device__ __forceinline__ uint2 pack_split4(float4 v, uint2& lo_out) {
    uint16_t h0,l0,h1,l1,h2,l2,h3,l3;
    split_bf16(v.x,h0,l0); split_bf16(v.y,h1,l1);
    split_bf16(v.z,h2,l2); split_bf16(v.w,h3,l3);
    lo_out = make_uint2((uint32_t)l0 | ((uint32_t)l1 << 16),
                        (uint32_t)l2 | ((uint32_t)l3 << 16));
    return make_uint2((uint32_t)h0 | ((uint32_t)h1 << 16),
                      (uint32_t)h2 | ((uint32_t)h3 << 16));
}

// writes bf16 hi/lo into g_ahi/g_alo (stride AP) — feeds next big GEMM
__global__ void spmm_to_bf16_kernel(const float* __restrict__ X) {
    int warp = (blockIdx.x * blockDim.x + threadIdx.x) >> 5;
    int lane = threadIdx.x & 31;
    if (warp >= NV) return;
    float4 a0, a1, a2;
    spmm_row(X, warp, lane, a0, a1, a2);
    size_t base = (size_t)warp * AP;
    uint2 lo, hi;
    hi = pack_split4(a0, lo);
    *reinterpret_cast<uint2*>(&g_ahi[base + lane*4]) = hi;
    *reinterpret_cast<uint2*>(&g_alo[base + lane*4]) = lo;
    hi = pack_split4(a1, lo);
    *reinterpret_cast<uint2*>(&g_ahi[base + 128 + lane*4]) = hi;
    *reinterpret_cast<uint2*>(&g_alo[base + 128 + lane*4]) = lo;
    if (lane < 11) {
        hi = pack_split4(a2, lo);
        *reinterpret_cast<uint2*>(&g_ahi[base + 256 + lane*4]) = hi;
        *reinterpret_cast<uint2*>(&g_alo[base + 256 + lane*4]) = lo;
    }
}

// writes fp32 (stride EMB) — feeds fc_build
__global__ void spmm_to_f32_kernel(const float* __restrict__ X, float* __restrict__ out) {
    int warp = (blockIdx.x * blockDim.x + threadIdx.x) >> 5;
    int lane = threadIdx.x & 31;
    if (warp >= NV) return;
    float4 a0, a1, a2;
    spmm_row(X, warp, lane, a0, a1, a2);
    float4* o4 = reinterpret_cast<float4*>(out + (size_t)warp * EMB);
    o4[lane] = a0;
    o4[lane + 32] = a1;
    if (lane < 11) o4[lane + 64] = a2;
}

// build fc = concat(H2[node], input)
__global__ void fc_build_kernel(const float* __restrict__ H2,
                                const int* __restrict__ node,
                                const float* __restrict__ input) {
    int idx = blockIdx.x * blockDim.x + threadIdx.x;
    if (idx >= BATCH * FCK) return;
    int b = idx / FCK;
    int j = idx - b * FCK;
    float v;
    if (j < EMB) {
        size_t n = (size_t)node[b];
        v = H2[n * EMB + j];
    } else {
        v = input[(size_t)b * IN_DIM + (j - EMB)];
    }
    g_fc[idx] = v;
}

// final layer
__global__ void final_kernel(const float* __restrict__ h,
                             const float* __restrict__ Wc,
                             const float* __restrict__ bc,
                             float* __restrict__ out) {
    int warp = (blockIdx.x * blockDim.x + threadIdx.x) >> 5;
    int lane = threadIdx.x & 31;
    if (warp >= BATCH) return;
    const float* hr = h + (size_t)warp * HID;
    float a0 = 0.f, a1 = 0.f;
    for (int k = lane; k < HID; k += 32) {
        float hv = hr[k];
        a0 += hv * Wc[k * 2 + 0];
        a1 += hv * Wc[k * 2 + 1];
    }
#pragma unroll
    for (int o = 16; o > 0; o >>= 1) {
        a0 += __shfl_down_sync(0xFFFFFFFFu, a0, o);
        a1 += __shfl_down_sync(0xFFFFFFFFu, a1, o);
    }
    if (lane == 0) {
        out[warp * 2 + 0] = a0 + bc[0];
        out[warp * 2 + 1] = a1 + bc[1];
    }
}

// ================= host launch =================
extern "C" void kernel_launch(void* const* d_in, const int* in_sizes, int n_in,
                              void* d_out, int out_size) {
    const float* input = (const float*)d_in[0];
    const int*   node  = (const int*)d_in[1];
    const int*   erow  = (const int*)d_in[2];
    const int*   ecol  = (const int*)d_in[3];
    const float* H0    = (const float*)d_in[4];
    const float* W1    = (const float*)d_in[5];
    const float* W2    = (const float*)d_in[6];
    const float* Wa    = (const float*)d_in[7];
    const float* ba    = (const float*)d_in[8];
    const float* Wb    = (const float*)d_in[9];
    const float* bb    = (const float*)d_in[10];
    const float* Wc    = (const float*)d_in[11];
    const float* bc    = (const float*)d_in[12];
    float*       out   = (float*)d_out;

    void *p_cnt, *p_cursor, *p_bufA, *p_bufB, *p_fc, *p_h1, *p_h2;
    void *p_ahi, *p_alo, *p_w1thi, *p_w1tlo, *p_w2thi, *p_w2tlo;
    cudaGetSymbolAddress(&p_cnt,    g_cnt);
    cudaGetSymbolAddress(&p_cursor, g_cursor);
    cudaGetSymbolAddress(&p_bufA,   g_bufA);
    cudaGetSymbolAddress(&p_bufB,   g_bufB);
    cudaGetSymbolAddress(&p_fc,     g_fc);
    cudaGetSymbolAddress(&p_h1,     g_h1);
    cudaGetSymbolAddress(&p_h2,     g_h2);
    cudaGetSymbolAddress(&p_ahi,    g_ahi);
    cudaGetSymbolAddress(&p_alo,    g_alo);
    cudaGetSymbolAddress(&p_w1thi,  g_w1thi);
    cudaGetSymbolAddress(&p_w1tlo,  g_w1tlo);
    cudaGetSymbolAddress(&p_w2thi,  g_w2thi);
    cudaGetSymbolAddress(&p_w2tlo,  g_w2tlo);

    float* bufA = (float*)p_bufA;
    float* bufB = (float*)p_bufB;
    float* fc   = (float*)p_fc;
    float* h1   = (float*)p_h1;
    float* h2   = (float*)p_h2;

    cudaFuncSetAttribute(gemm_big_kernel,
                         cudaFuncAttributeMaxDynamicSharedMemorySize, GB_SM_TOTAL);

    const int TPB = 256;

    // ---- CSR build + normalization ----
    zero_int_kernel<<<(NV + TPB - 1) / TPB, TPB>>>((int*)p_cnt, NV);
    count_kernel<<<(NE + TPB - 1) / TPB, TPB>>>(erow);
    dinv_kernel<<<(NV + TPB - 1) / TPB, TPB>>>();
    vals_kernel<<<(NE + TPB - 1) / TPB, TPB>>>(erow, ecol);
    scanA_kernel<<<NBLK_SCAN, 1024>>>();
    scanB_kernel<<<1, 128>>>();
    scanC_kernel<<<(NV + TPB - 1) / TPB, TPB>>>();
    zero_int_kernel<<<(NV + TPB - 1) / TPB, TPB>>>((int*)p_cursor, NV);
    scatter_kernel<<<(NE + TPB - 1) / TPB, TPB>>>(erow, ecol);

    // ---- presplit ----
    presplit_act_kernel<<<(NV * 75 + TPB - 1) / TPB, TPB>>>(H0);
    presplit_w_kernel<<<(EMB * EMB + TPB - 1) / TPB, TPB>>>(W1, (uint16_t*)p_w1thi, (uint16_t*)p_w1tlo);
    presplit_w_kernel<<<(EMB * EMB + TPB - 1) / TPB, TPB>>>(W2, (uint16_t*)p_w2thi, (uint16_t*)p_w2tlo);

    // ---- GCN layer 1 ----
    dim3 gbig(2, (NV + 127) / 128);
    gemm_big_kernel<<<gbig, 512, GB_SM_TOTAL>>>((uint16_t*)p_ahi, (uint16_t*)p_alo,
                                                (uint16_t*)p_w1thi, (uint16_t*)p_w1tlo,
                                                bufA, NV);
    spmm_to_bf16_kernel<<<(NV * 32 + TPB - 1) / TPB, TPB>>>(bufA);   // H1 -> g_ahi/g_alo

    // ---- GCN layer 2 ----
    gemm_big_kernel<<<gbig, 512, GB_SM_TOTAL>>>((uint16_t*)p_ahi, (uint16_t*)p_alo,
                                                (uint16_t*)p_w2thi, (uint16_t*)p_w2tlo,
                                                bufA, NV);
    spmm_to_f32_kernel<<<(NV * 32 + TPB - 1) / TPB, TPB>>>(bufA, bufB);  // H2 fp32

    // ---- MLP head ----
    fc_build_kernel<<<(BATCH * FCK + TPB - 1) / TPB, TPB>>>(bufB, node, input);

    dim3 gemmA((HID + BN - 1) / BN, (BATCH + BM - 1) / BM);
    gemm_mma_kernel<<<gemmA, 256>>>(fc, Wa, ba, h1, BATCH, HID, FCK, 1);
    gemm_mma_kernel<<<gemmA, 256>>>(h1, Wb, bb, h2, BATCH, HID, HID, 1);

    final_kernel<<<(BATCH * 32 + TPB - 1) / TPB, TPB>>>(h2, Wc, bc, out);
}

// round 6
// speedup vs baseline: 2.2538x; 1.0043x over previous
#include <cuda_runtime.h>
#include <cuda_bf16.h>
#include <math.h>
#include <cstdint>

#define NV 117000
#define NE 468000
#define EMB 300
#define IN_DIM 768
#define BATCH 4096
#define HID 500
#define FCK (EMB + IN_DIM)   // 1068
#define NBLK_SCAN ((NV + 1023) / 1024)   // 115
#define AP 320               // padded bf16 stride for GCN activations / weights
#define FCP 1088             // padded fc width
#define HP 512               // padded hidden width
#define BROWS 640            // padded rows for transposed weight buffers

// ---------------- device scratch (allocation-free, zero-initialized) -------
__device__ float g_vals[NE];
__device__ int   g_cnt[NV];
__device__ int   g_rowstart[NV + 1];
__device__ int   g_tot[256];
__device__ int   g_cursor[NV];
__device__ int   g_scol[NE];
__device__ float g_sval[NE];
__device__ float g_bufA[(size_t)NV * EMB];
__device__ float g_bufB[(size_t)NV * EMB];
__device__ float g_h2[BATCH * HID];
// presplit bf16 buffers (pads stay statically zero — never written)
__device__ uint16_t g_ahi[(size_t)NV * AP];
__device__ uint16_t g_alo[(size_t)NV * AP];
__device__ uint16_t g_w1thi[AP * AP];
__device__ uint16_t g_w1tlo[AP * AP];
__device__ uint16_t g_w2thi[AP * AP];
__device__ uint16_t g_w2tlo[AP * AP];
__device__ uint16_t g_fchi[(size_t)BATCH * FCP];
__device__ uint16_t g_fclo[(size_t)BATCH * FCP];
__device__ uint16_t g_wathi[(size_t)BROWS * FCP];
__device__ uint16_t g_watlo[(size_t)BROWS * FCP];
__device__ uint16_t g_wbthi[(size_t)BROWS * HP];
__device__ uint16_t g_wbtlo[(size_t)BROWS * HP];
__device__ uint16_t g_h1hi[(size_t)BATCH * HP];
__device__ uint16_t g_h1lo[(size_t)BATCH * HP];

// ================= helpers =================
__device__ __forceinline__ void split_bf16(float x, uint16_t& hi, uint16_t& lo) {
    __nv_bfloat16 h = __float2bfloat16_rn(x);
    float r = x - __bfloat162float(h);
    __nv_bfloat16 l = __float2bfloat16_rn(r);
    hi = *reinterpret_cast<uint16_t*>(&h);
    lo = *reinterpret_cast<uint16_t*>(&l);
}

__device__ __forceinline__ void mma16816(float* c, const uint32_t* a, const uint32_t* b) {
    asm volatile(
        "mma.sync.aligned.m16n8k16.row.col.f32.bf16.bf16.f32 "
        "{%0,%1,%2,%3}, {%4,%5,%6,%7}, {%8,%9}, {%0,%1,%2,%3};"
        : "+f"(c[0]), "+f"(c[1]), "+f"(c[2]), "+f"(c[3])
        : "r"(a[0]), "r"(a[1]), "r"(a[2]), "r"(a[3]),
          "r"(b[0]), "r"(b[1]));
}

__device__ __forceinline__ uint32_t cvta_shared_u32(const void* p) {
    uint32_t a;
    asm("{ .reg .u64 t; cvta.to.shared.u64 t, %1; cvt.u32.u64 %0, t; }"
        : "=r"(a) : "l"(p));
    return a;
}

__device__ __forceinline__ void cp_async16(uint32_t dst, const void* src) {
    asm volatile("cp.async.ca.shared.global [%0], [%1], 16;" :: "r"(dst), "l"(src));
}
__device__ __forceinline__ void cp_commit() {
    asm volatile("cp.async.commit_group;");
}
__device__ __forceinline__ void cp_wait0() {
    asm volatile("cp.async.wait_group 0;");
}

// ================= presplit kernels =================
// H0 fp32 [NV,300] -> g_ahi/g_alo bf16 [NV,320]
__global__ void presplit_act_kernel(const float* __restrict__ X) {
    int idx = blockIdx.x * blockDim.x + threadIdx.x;
    if (idx >= NV * 75) return;
    int r = idx / 75;
    int q = idx - r * 75;
    float4 v = reinterpret_cast<const float4*>(X)[(size_t)r * 75 + q];
    uint16_t h0,l0,h1,l1,h2,l2,h3,l3;
    split_bf16(v.x,h0,l0); split_bf16(v.y,h1,l1);
    split_bf16(v.z,h2,l2); split_bf16(v.w,h3,l3);
    size_t o = (size_t)r * AP + q * 4;
    *reinterpret_cast<uint2*>(&g_ahi[o]) =
        make_uint2((uint32_t)h0 | ((uint32_t)h1 << 16), (uint32_t)h2 | ((uint32_t)h3 << 16));
    *reinterpret_cast<uint2*>(&g_alo[o]) =
        make_uint2((uint32_t)l0 | ((uint32_t)l1 << 16), (uint32_t)l2 | ((uint32_t)l3 << 16));
}

// W row-major [K][N] -> transposed bf16 [n*ldo + k]
__global__ void presplit_wT_kernel(const float* __restrict__ W, int K, int N, int ldo,
                                   uint16_t* __restrict__ thi, uint16_t* __restrict__ tlo) {
    int idx = blockIdx.x * blockDim.x + threadIdx.x;
    if (idx >= K * N) return;
    int k = idx / N;
    int n = idx - k * N;
    uint16_t h, l;
    split_bf16(W[idx], h, l);
    thi[(size_t)n * ldo + k] = h;
    tlo[(size_t)n * ldo + k] = l;
}

// ================= generalized pipelined tensor-core GEMM ===================
// C[M,N] = A[M,K] @ B[K,N] from presplit bf16 (A: lda-stride hi/lo; B
// transposed [n][k], ldb-stride hi/lo). BM=128, BN=160, BK=32, 512 threads.
// mode 0: fp32 store to C (ldc)      mode 1: bias+sigmoid fp32 store
// mode 2: bias+sigmoid -> bf16 split store to (ohi, olo) stride ldo
#define GB_SM_ABUF 20480
#define GB_SM_BBUF 25600
#define GB_SM_BOFF (2 * GB_SM_ABUF)
#define GB_SM_TOTAL (GB_SM_BOFF + 2 * GB_SM_BBUF)   // 92160

__global__ void __launch_bounds__(512, 1)
gemm_ps_kernel(const uint16_t* __restrict__ ahi, const uint16_t* __restrict__ alo, int lda,
               const uint16_t* __restrict__ bthi, const uint16_t* __restrict__ btlo, int ldb,
               float* __restrict__ C, int ldc,
               uint16_t* __restrict__ ohi, uint16_t* __restrict__ olo, int ldo,
               const float* __restrict__ bias,
               int M, int N, int K, int mode) {
    extern __shared__ __align__(16) char sm[];
    int tid = threadIdx.x;
    int w = tid >> 5;
    int lane = tid & 31;
    int g = lane >> 2;
    int t2 = (lane & 3) * 2;

    int bm = blockIdx.y * 128;
    int bn = blockIdx.x * 160;
    int m0 = (w & 3) * 32;
    int n0 = (w >> 2) * 40;
    int nch = K >> 5;

    float acc[2][5][4];
#pragma unroll
    for (int i = 0; i < 2; i++)
#pragma unroll
        for (int j = 0; j < 5; j++)
#pragma unroll
            for (int q = 0; q < 4; q++) acc[i][j][q] = 0.0f;

    auto prefetch = [&](int ch, int buf) {
        int k0 = ch * 32;
        {
            int r = tid >> 2;
            int c = tid & 3;
            int gr = bm + r;
            if (gr > M - 1) gr = M - 1;
            size_t so = (size_t)gr * lda + k0 + c * 8;
            uint32_t d = cvta_shared_u32(sm + buf * GB_SM_ABUF + (r * 40 + c * 8) * 2);
            cp_async16(d, ahi + so);
            cp_async16(d + 10240, alo + so);
        }
#pragma unroll
        for (int it = 0; it < 2; it++) {
            int idx = tid + it * 512;
            if (idx < 640) {
                int r = idx >> 2;
                int c = idx & 3;
                size_t so = (size_t)(bn + r) * ldb + k0 + c * 8;
                uint32_t d = cvta_shared_u32(sm + GB_SM_BOFF + buf * GB_SM_BBUF +
                                             (r * 40 + c * 8) * 2);
                cp_async16(d, bthi + so);
                cp_async16(d + 12800, btlo + so);
            }
        }
    };

    prefetch(0, 0);
    cp_commit();

    for (int ch = 0; ch < nch; ch++) {
        int buf = ch & 1;
        cp_wait0();
        __syncthreads();
        if (ch < nch - 1) {
            prefetch(ch + 1, buf ^ 1);
            cp_commit();
        }
        const uint16_t* Ah = reinterpret_cast<const uint16_t*>(sm + buf * GB_SM_ABUF);
        const uint16_t* Al = Ah + 5120;
        const uint16_t* Bh = reinterpret_cast<const uint16_t*>(sm + GB_SM_BOFF + buf * GB_SM_BBUF);
        const uint16_t* Bl = Bh + 6400;

#pragma unroll
        for (int kc = 0; kc < 32; kc += 16) {
            uint32_t ah[2][4], al[2][4];
#pragma unroll
            for (int i = 0; i < 2; i++) {
                int rm = m0 + i * 16;
                ah[i][0] = *reinterpret_cast<const uint32_t*>(&Ah[(rm + g)     * 40 + kc + t2]);
                ah[i][1] = *reinterpret_cast<const uint32_t*>(&Ah[(rm + g + 8) * 40 + kc + t2]);
                ah[i][2] = *reinterpret_cast<const uint32_t*>(&Ah[(rm + g)     * 40 + kc + t2 + 8]);
                ah[i][3] = *reinterpret_cast<const uint32_t*>(&Ah[(rm + g + 8) * 40 + kc + t2 + 8]);
                al[i][0] = *reinterpret_cast<const uint32_t*>(&Al[(rm + g)     * 40 + kc + t2]);
                al[i][1] = *reinterpret_cast<const uint32_t*>(&Al[(rm + g + 8) * 40 + kc + t2]);
                al[i][2] = *reinterpret_cast<const uint32_t*>(&Al[(rm + g)     * 40 + kc + t2 + 8]);
                al[i][3] = *reinterpret_cast<const uint32_t*>(&Al[(rm + g + 8) * 40 + kc + t2 + 8]);
            }
#pragma unroll
            for (int j = 0; j < 5; j++) {
                int rn = n0 + j * 8;
                uint32_t bh[2], bl[2];
                bh[0] = *reinterpret_cast<const uint32_t*>(&Bh[(rn + g) * 40 + kc + t2]);
                bh[1] = *reinterpret_cast<const uint32_t*>(&Bh[(rn + g) * 40 + kc + t2 + 8]);
                bl[0] = *reinterpret_cast<const uint32_t*>(&Bl[(rn + g) * 40 + kc + t2]);
                bl[1] = *reinterpret_cast<const uint32_t*>(&Bl[(rn + g) * 40 + kc + t2 + 8]);
#pragma unroll
                for (int i = 0; i < 2; i++) {
                    mma16816(acc[i][j], ah[i], bh);
                    mma16816(acc[i][j], ah[i], bl);
                    mma16816(acc[i][j], al[i], bh);
                }
            }
        }
        __syncthreads();
    }

    // ---- epilogue ----
#pragma unroll
    for (int i = 0; i < 2; i++) {
#pragma unroll
        for (int j = 0; j < 5; j++) {
            int gn = bn + n0 + j * 8 + t2;
            if (gn >= N) continue;      // N even, gn even -> gn+1 safe
#pragma unroll
            for (int half = 0; half < 2; half++) {
                int gr = bm + m0 + i * 16 + g + half * 8;
                if (gr >= M) continue;
                float2 o;
                o.x = acc[i][j][half * 2 + 0];
                o.y = acc[i][j][half * 2 + 1];
                if (mode != 0) {
                    o.x += bias[gn];
                    o.y += bias[gn + 1];
                    o.x = 1.0f / (1.0f + __expf(-o.x));
                    o.y = 1.0f / (1.0f + __expf(-o.y));
                }
                if (mode == 2) {
                    uint16_t h0, l0, h1, l1;
                    split_bf16(o.x, h0, l0);
                    split_bf16(o.y, h1, l1);
                    *reinterpret_cast<uint32_t*>(&ohi[(size_t)gr * ldo + gn]) =
                        (uint32_t)h0 | ((uint32_t)h1 << 16);
                    *reinterpret_cast<uint32_t*>(&olo[(size_t)gr * ldo + gn]) =
                        (uint32_t)l0 | ((uint32_t)l1 << 16);
                } else {
                    *reinterpret_cast<float2*>(C + (size_t)gr * ldc + gn) = o;
                }
            }
        }
    }
}

// ================= graph preprocessing =================
__global__ void zero_int_kernel(int* p, int n) {
    int i = blockIdx.x * blockDim.x + threadIdx.x;
    if (i < n) p[i] = 0;
}

__global__ void count_kernel(const int* __restrict__ erow) {
    int e = blockIdx.x * blockDim.x + threadIdx.x;
    if (e < NE) atomicAdd(&g_cnt[erow[e]], 1);
}

// fused: vals[e] = dinv[row]*dinv[col] computed from counts directly
__global__ void vals_kernel(const int* __restrict__ erow, const int* __restrict__ ecol) {
    int e = blockIdx.x * blockDim.x + threadIdx.x;
    if (e >= NE) return;
    int dr = g_cnt[erow[e]];
    int dc = g_cnt[ecol[e]];
    float a = (dr > 0) ? rsqrtf((float)dr) : 0.0f;
    float b = (dc > 0) ? rsqrtf((float)dc) : 0.0f;
    g_vals[e] = a * b;
}

__global__ void scanA_kernel() {
    __shared__ int s[1024];
    int i = blockIdx.x * 1024 + threadIdx.x;
    int v = (i < NV) ? g_cnt[i] : 0;
    s[threadIdx.x] = v;
    __syncthreads();
    for (int o = 1; o < 1024; o <<= 1) {
        int t = 0;
        if (threadIdx.x >= o) t = s[threadIdx.x - o];
        __syncthreads();
        if (threadIdx.x >= o) s[threadIdx.x] += t;
        __syncthreads();
    }
    if (i < NV) g_rowstart[i] = s[threadIdx.x] - v;
    if (threadIdx.x == 1023) g_tot[blockIdx.x] = s[1023];
}

__global__ void scanB_kernel() {
    __shared__ int s[128];
    int v = (threadIdx.x < NBLK_SCAN) ? g_tot[threadIdx.x] : 0;
    s[threadIdx.x] = v;
    __syncthreads();
    for (int o = 1; o < 128; o <<= 1) {
        int t = 0;
        if (threadIdx.x >= o) t = s[threadIdx.x - o];
        __syncthreads();
        if (threadIdx.x >= o) s[threadIdx.x] += t;
        __syncthreads();
    }
    if (threadIdx.x < NBLK_SCAN) g_tot[threadIdx.x] = s[threadIdx.x] - v;
}

__global__ void scanC_kernel() {
    int i = blockIdx.x * blockDim.x + threadIdx.x;
    if (i < NV) g_rowstart[i] += g_tot[i >> 10];
    if (i == 0) g_rowstart[NV] = NE;
}

__global__ void scatter_kernel(const int* __restrict__ erow, const int* __restrict__ ecol) {
    int e = blockIdx.x * blockDim.x + threadIdx.x;
    if (e >= NE) return;
    int r = erow[e];
    int pos = g_rowstart[r] + atomicAdd(&g_cursor[r], 1);
    g_scol[pos] = ecol[e];
    g_sval[pos] = g_vals[e];
}

// ================= pull SpMM + fused sigmoid =================
__device__ __forceinline__ void spmm_row(const float* __restrict__ X, int row, int lane,
                                         float4& a0, float4& a1, float4& a2) {
    int s = g_rowstart[row];
    int e = g_rowstart[row + 1];
    a0 = make_float4(0.f,0.f,0.f,0.f);
    a1 = make_float4(0.f,0.f,0.f,0.f);
    a2 = make_float4(0.f,0.f,0.f,0.f);
    float4 b0 = a0, b1 = a1, b2 = a2;
    int j = s;
    for (; j + 1 < e; j += 2) {
        int c0 = g_scol[j];
        float v0 = g_sval[j];
        int c1 = g_scol[j + 1];
        float v1 = g_sval[j + 1];
        const float4* x0 = reinterpret_cast<const float4*>(X + (size_t)c0 * EMB);
        const float4* x1 = reinterpret_cast<const float4*>(X + (size_t)c1 * EMB);
        float4 t0 = x0[lane], u0 = x1[lane];
        a0.x += v0*t0.x; a0.y += v0*t0.y; a0.z += v0*t0.z; a0.w += v0*t0.w;
        b0.x += v1*u0.x; b0.y += v1*u0.y; b0.z += v1*u0.z; b0.w += v1*u0.w;
        float4 t1 = x0[lane + 32], u1 = x1[lane + 32];
        a1.x += v0*t1.x; a1.y += v0*t1.y; a1.z += v0*t1.z; a1.w += v0*t1.w;
        b1.x += v1*u1.x; b1.y += v1*u1.y; b1.z += v1*u1.z; b1.w += v1*u1.w;
        if (lane < 11) {
            float4 t2 = x0[lane + 64], u2 = x1[lane + 64];
            a2.x += v0*t2.x; a2.y += v0*t2.y; a2.z += v0*t2.z; a2.w += v0*t2.w;
            b2.x += v1*u2.x; b2.y += v1*u2.y; b2.z += v1*u2.z; b2.w += v1*u2.w;
        }
    }
    if (j < e) {
        int c = g_scol[j];
        float v = g_sval[j];
        const float4* x4 = reinterpret_cast<const float4*>(X + (size_t)c * EMB);
        float4 t0 = x4[lane];
        a0.x += v*t0.x; a0.y += v*t0.y; a0.z += v*t0.z; a0.w += v*t0.w;
        float4 t1 = x4[lane + 32];
        a1.x += v*t1.x; a1.y += v*t1.y; a1.z += v*t1.z; a1.w += v*t1.w;
        if (lane < 11) {
            float4 t2 = x4[lane + 64];
            a2.x += v*t2.x; a2.y += v*t2.y; a2.z += v*t2.z; a2.w += v*t2.w;
        }
    }
    a0.x += b0.x; a0.y += b0.y; a0.z += b0.z; a0.w += b0.w;
    a1.x += b1.x; a1.y += b1.y; a1.z += b1.z; a1.w += b1.w;
    a2.x += b2.x; a2.y += b2.y; a2.z += b2.z; a2.w += b2.w;
    a0.x = 1.0f/(1.0f+__expf(-a0.x)); a0.y = 1.0f/(1.0f+__expf(-a0.y));
    a0.z = 1.0f/(1.0f+__expf(-a0.z)); a0.w = 1.0f/(1.0f+__expf(-a0.w));
    a1.x = 1.0f/(1.0f+__expf(-a1.x)); a1.y = 1.0f/(1.0f+__expf(-a1.y));
    a1.z = 1.0f/(1.0f+__expf(-a1.z)); a1.w = 1.0f/(1.0f+__expf(-a1.w));
    a2.x = 1.0f/(1.0f+__expf(-a2.x)); a2.y = 1.0f/(1.0f+__expf(-a2.y));
    a2.z = 1.0f/(1.0f+__expf(-a2.z)); a2.w = 1.0f/(1.0f+__expf(-a2.w));
}

__device__ __forceinline__ uint2 pack_split4(float4 v, uint2& lo_out) {
    uint16_t h0,l0,h1,l1,h2,l2,h3,l3;
    split_bf16(v.x,h0,l0); split_bf16(v.y,h1,l1);
    split_bf16(v.z,h2,l2); split_bf16(v.w,h3,l3);
    lo_out = make_uint2((uint32_t)l0 | ((uint32_t)l1 << 16),
                        (uint32_t)l2 | ((uint32_t)l3 << 16));
    return make_uint2((uint32_t)h0 | ((uint32_t)h1 << 16),
                      (uint32_t)h2 | ((uint32_t)h3 << 16));
}

__global__ void spmm_to_bf16_kernel(const float* __restrict__ X) {
    int warp = (blockIdx.x * blockDim.x + threadIdx.x) >> 5;
    int lane = threadIdx.x & 31;
    if (warp >= NV) return;
    float4 a0, a1, a2;
    spmm_row(X, warp, lane, a0, a1, a2);
    size_t base = (size_t)warp * AP;
    uint2 lo, hi;
    hi = pack_split4(a0, lo);
    *reinterpret_cast<uint2*>(&g_ahi[base + lane*4]) = hi;
    *reinterpret_cast<uint2*>(&g_alo[base + lane*4]) = lo;
    hi = pack_split4(a1, lo);
    *reinterpret_cast<uint2*>(&g_ahi[base + 128 + lane*4]) = hi;
    *reinterpret_cast<uint2*>(&g_alo[base + 128 + lane*4]) = lo;
    if (lane < 11) {
        hi = pack_split4(a2, lo);
        *reinterpret_cast<uint2*>(&g_ahi[base + 256 + lane*4]) = hi;
        *reinterpret_cast<uint2*>(&g_alo[base + 256 + lane*4]) = lo;
    }
}

__global__ void spmm_to_f32_kernel(const float* __restrict__ X, float* __restrict__ out) {
    int warp = (blockIdx.x * blockDim.x + threadIdx.x) >> 5;
    int lane = threadIdx.x & 31;
    if (warp >= NV) return;
    float4 a0, a1, a2;
    spmm_row(X, warp, lane, a0, a1, a2);
    float4* o4 = reinterpret_cast<float4*>(out + (size_t)warp * EMB);
    o4[lane] = a0;
    o4[lane + 32] = a1;
    if (lane < 11) o4[lane + 64] = a2;
}

// build fc = concat(H2[node], input) pre-split to bf16 [BATCH, FCP]
__global__ void fc_build_bf16_kernel(const float* __restrict__ H2,
                                     const int* __restrict__ node,
                                     const float* __restrict__ input) {
    int idx = blockIdx.x * blockDim.x + threadIdx.x;
    if (idx >= BATCH * FCK) return;
    int b = idx / FCK;
    int j = idx - b * FCK;
    float v;
    if (j < EMB) {
        size_t n = (size_t)node[b];
        v = H2[n * EMB + j];
    } else {
        v = input[(size_t)b * IN_DIM + (j - EMB)];
    }
    uint16_t h, l;
    split_bf16(v, h, l);
    g_fchi[(size_t)b * FCP + j] = h;
    g_fclo[(size_t)b * FCP + j] = l;
}

// final layer
__global__ void final_kernel(const float* __restrict__ h,
                             const float* __restrict__ Wc,
                             const float* __restrict__ bc,
                             float* __restrict__ out) {
    int warp = (blockIdx.x * blockDim.x + threadIdx.x) >> 5;
    int lane = threadIdx.x & 31;
    if (warp >= BATCH) return;
    const float* hr = h + (size_t)warp * HID;
    float a0 = 0.f, a1 = 0.f;
    for (int k = lane; k < HID; k += 32) {
        float hv = hr[k];
        a0 += hv * Wc[k * 2 + 0];
        a1 += hv * Wc[k * 2 + 1];
    }
#pragma unroll
    for (int o = 16; o > 0; o >>= 1) {
        a0 += __shfl_down_sync(0xFFFFFFFFu, a0, o);
        a1 += __shfl_down_sync(0xFFFFFFFFu, a1, o);
    }
    if (lane == 0) {
        out[warp * 2 + 0] = a0 + bc[0];
        out[warp * 2 + 1] = a1 + bc[1];
    }
}

// ================= host launch =================
extern "C" void kernel_launch(void* const* d_in, const int* in_sizes, int n_in,
                              void* d_out, int out_size) {
    const float* input = (const float*)d_in[0];
    const int*   node  = (const int*)d_in[1];
    const int*   erow  = (const int*)d_in[2];
    const int*   ecol  = (const int*)d_in[3];
    const float* H0    = (const float*)d_in[4];
    const float* W1    = (const float*)d_in[5];
    const float* W2    = (const float*)d_in[6];
    const float* Wa    = (const float*)d_in[7];
    const float* ba    = (const float*)d_in[8];
    const float* Wb    = (const float*)d_in[9];
    const float* bb    = (const float*)d_in[10];
    const float* Wc    = (const float*)d_in[11];
    const float* bc    = (const float*)d_in[12];
    float*       out   = (float*)d_out;

    void *p_cnt, *p_cursor, *p_bufA, *p_bufB, *p_h2;
    void *p_ahi, *p_alo, *p_w1thi, *p_w1tlo, *p_w2thi, *p_w2tlo;
    void *p_fchi, *p_fclo, *p_wathi, *p_watlo, *p_wbthi, *p_wbtlo, *p_h1hi, *p_h1lo;
    cudaGetSymbolAddress(&p_cnt,    g_cnt);
    cudaGetSymbolAddress(&p_cursor, g_cursor);
    cudaGetSymbolAddress(&p_bufA,   g_bufA);
    cudaGetSymbolAddress(&p_bufB,   g_bufB);
    cudaGetSymbolAddress(&p_h2,     g_h2);
    cudaGetSymbolAddress(&p_ahi,    g_ahi);
    cudaGetSymbolAddress(&p_alo,    g_alo);
    cudaGetSymbolAddress(&p_w1thi,  g_w1thi);
    cudaGetSymbolAddress(&p_w1tlo,  g_w1tlo);
    cudaGetSymbolAddress(&p_w2thi,  g_w2thi);
    cudaGetSymbolAddress(&p_w2tlo,  g_w2tlo);
    cudaGetSymbolAddress(&p_fchi,   g_fchi);
    cudaGetSymbolAddress(&p_fclo,   g_fclo);
    cudaGetSymbolAddress(&p_wathi,  g_wathi);
    cudaGetSymbolAddress(&p_watlo,  g_watlo);
    cudaGetSymbolAddress(&p_wbthi,  g_wbthi);
    cudaGetSymbolAddress(&p_wbtlo,  g_wbtlo);
    cudaGetSymbolAddress(&p_h1hi,   g_h1hi);
    cudaGetSymbolAddress(&p_h1lo,   g_h1lo);

    float* bufA = (float*)p_bufA;
    float* bufB = (float*)p_bufB;
    float* h2   = (float*)p_h2;

    cudaFuncSetAttribute(gemm_ps_kernel,
                         cudaFuncAttributeMaxDynamicSharedMemorySize, GB_SM_TOTAL);

    // stream/event handles created once, reused (no device memory involved)
    static cudaStream_t s2 = nullptr;
    static cudaEvent_t evF = nullptr, evJ = nullptr;
    if (!s2) {
        cudaStreamCreateWithFlags(&s2, cudaStreamNonBlocking);
        cudaEventCreateWithFlags(&evF, cudaEventDisableTiming);
        cudaEventCreateWithFlags(&evJ, cudaEventDisableTiming);
    }

    const int TPB = 256;

    // ---- fork: CSR build chain on s2 ----
    cudaEventRecord(evF, 0);
    cudaStreamWaitEvent(s2, evF, 0);
    zero_int_kernel<<<(NV + TPB - 1) / TPB, TPB, 0, s2>>>((int*)p_cnt, NV);
    zero_int_kernel<<<(NV + TPB - 1) / TPB, TPB, 0, s2>>>((int*)p_cursor, NV);
    count_kernel<<<(NE + TPB - 1) / TPB, TPB, 0, s2>>>(erow);
    vals_kernel<<<(NE + TPB - 1) / TPB, TPB, 0, s2>>>(erow, ecol);
    scanA_kernel<<<NBLK_SCAN, 1024, 0, s2>>>();
    scanB_kernel<<<1, 128, 0, s2>>>();
    scanC_kernel<<<(NV + TPB - 1) / TPB, TPB, 0, s2>>>();
    scatter_kernel<<<(NE + TPB - 1) / TPB, TPB, 0, s2>>>(erow, ecol);
    cudaEventRecord(evJ, s2);

    // ---- main stream: presplits ----
    presplit_act_kernel<<<(NV * 75 + TPB - 1) / TPB, TPB>>>(H0);
    presplit_wT_kernel<<<(EMB * EMB + TPB - 1) / TPB, TPB>>>(W1, EMB, EMB, AP,
        (uint16_t*)p_w1thi, (uint16_t*)p_w1tlo);
    presplit_wT_kernel<<<(EMB * EMB + TPB - 1) / TPB, TPB>>>(W2, EMB, EMB, AP,
        (uint16_t*)p_w2thi, (uint16_t*)p_w2tlo);
    presplit_wT_kernel<<<(FCK * HID + TPB - 1) / TPB, TPB>>>(Wa, FCK, HID, FCP,
        (uint16_t*)p_wathi, (uint16_t*)p_watlo);
    presplit_wT_kernel<<<(HID * HID + TPB - 1) / TPB, TPB>>>(Wb, HID, HID, HP,
        (uint16_t*)p_wbthi, (uint16_t*)p_wbtlo);

    // ---- GCN layer 1 GEMM ----
    dim3 gbig(2, (NV + 127) / 128);
    gemm_ps_kernel<<<gbig, 512, GB_SM_TOTAL>>>(
        (uint16_t*)p_ahi, (uint16_t*)p_alo, AP,
        (uint16_t*)p_w1thi, (uint16_t*)p_w1tlo, AP,
        bufA, EMB, nullptr, nullptr, 0, nullptr, NV, EMB, AP, 0);

    // ---- join CSR chain, then SpMM 1 ----
    cudaStreamWaitEvent(0, evJ, 0);
    spmm_to_bf16_kernel<<<(NV * 32 + TPB - 1) / TPB, TPB>>>(bufA);

    // ---- GCN layer 2 ----
    gemm_ps_kernel<<<gbig, 512, GB_SM_TOTAL>>>(
        (uint16_t*)p_ahi, (uint16_t*)p_alo, AP,
        (uint16_t*)p_w2thi, (uint16_t*)p_w2tlo, AP,
        bufA, EMB, nullptr, nullptr, 0, nullptr, NV, EMB, AP, 0);
    spmm_to_f32_kernel<<<(NV * 32 + TPB - 1) / TPB, TPB>>>(bufA, bufB);

    // ---- MLP head ----
    fc_build_bf16_kernel<<<(BATCH * FCK + TPB - 1) / TPB, TPB>>>(bufB, node, input);

    dim3 gmlp(4, BATCH / 128);   // N=500 -> 4 col blocks of 160
    // h1 = sigmoid(fc @ Wa + ba) -> bf16 split
    gemm_ps_kernel<<<gmlp, 512, GB_SM_TOTAL>>>(
        (uint16_t*)p_fchi, (uint16_t*)p_fclo, FCP,
        (uint16_t*)p_wathi, (uint16_t*)p_watlo, FCP,
        nullptr, 0, (uint16_t*)p_h1hi, (uint16_t*)p_h1lo, HP, ba,
        BATCH, HID, FCP, 2);
    // h2 = sigmoid(h1 @ Wb + bb) -> fp32
    gemm_ps_kernel<<<gmlp, 512, GB_SM_TOTAL>>>(
        (uint16_t*)p_h1hi, (uint16_t*)p_h1lo, HP,
        (uint16_t*)p_wbthi, (uint16_t*)p_wbtlo, HP,
        h2, HID, nullptr, nullptr, 0, bb,
        BATCH, HID, HP, 1);

    final_kernel<<<(BATCH * 32 + TPB - 1) / TPB, TPB>>>(h2, Wc, bc, out);
}

// round 7
// speedup vs baseline: 2.4365x; 1.0811x over previous
#include <cuda_runtime.h>
#include <cuda_fp16.h>
#include <math.h>
#include <cstdint>

#define NV 117000
#define NE 468000
#define EMB 300
#define IN_DIM 768
#define BATCH 4096
#define HID 500
#define FCK (EMB + IN_DIM)   // 1068
#define NBLK_SCAN ((NV + 1023) / 1024)   // 115
#define AP 320               // padded fp16 stride for GCN activations / weights
#define FCP 1088             // padded fc width
#define HP 512               // padded hidden width
#define BNROWS 640           // padded N-rows for transposed MLP weights

// ---------------- device scratch (allocation-free, zero-initialized) -------
__device__ float g_vals[NE];
__device__ int   g_cnt[NV];
__device__ int   g_rowstart[NV + 1];
__device__ int   g_tot[256];
__device__ int   g_cursor[NV];
__device__ int   g_scol[NE];
__device__ float g_sval[NE];
__device__ float g_bufA[(size_t)NV * EMB];
__device__ float g_bufB[(size_t)NV * EMB];
__device__ float g_h2[BATCH * HID];
// fp16 operand buffers (pads stay statically zero — never written)
__device__ __half g_af16[(size_t)NV * AP];          // activations, single fp16
__device__ __half g_w1th[AP * AP];                  // W1^T hi
__device__ __half g_w1tl[AP * AP];                  // W1^T lo
__device__ __half g_w2th[AP * AP];
__device__ __half g_w2tl[AP * AP];
__device__ __half g_fcf16[(size_t)BATCH * FCP];
__device__ __half g_wath[(size_t)BNROWS * FCP];
__device__ __half g_watl[(size_t)BNROWS * FCP];
__device__ __half g_wbth[(size_t)BNROWS * HP];
__device__ __half g_wbtl[(size_t)BNROWS * HP];
__device__ __half g_h1f16[(size_t)BATCH * HP];

// ================= helpers =================
__device__ __forceinline__ void split_f16(float x, __half& hi, __half& lo) {
    hi = __float2half_rn(x);
    lo = __float2half_rn(x - __half2float(hi));
}

// mma.sync m16n8k16 row.col f32 += f16*f16
__device__ __forceinline__ void mma16816(float* c, const uint32_t* a, const uint32_t* b) {
    asm volatile(
        "mma.sync.aligned.m16n8k16.row.col.f32.f16.f16.f32 "
        "{%0,%1,%2,%3}, {%4,%5,%6,%7}, {%8,%9}, {%0,%1,%2,%3};"
        : "+f"(c[0]), "+f"(c[1]), "+f"(c[2]), "+f"(c[3])
        : "r"(a[0]), "r"(a[1]), "r"(a[2]), "r"(a[3]),
          "r"(b[0]), "r"(b[1]));
}

__device__ __forceinline__ uint32_t cvta_shared_u32(const void* p) {
    uint32_t a;
    asm("{ .reg .u64 t; cvta.to.shared.u64 t, %1; cvt.u32.u64 %0, t; }"
        : "=r"(a) : "l"(p));
    return a;
}

__device__ __forceinline__ void cp_async16(uint32_t dst, const void* src) {
    asm volatile("cp.async.ca.shared.global [%0], [%1], 16;" :: "r"(dst), "l"(src));
}
__device__ __forceinline__ void cp_commit() {
    asm volatile("cp.async.commit_group;");
}
__device__ __forceinline__ void cp_wait0() {
    asm volatile("cp.async.wait_group 0;");
}

// ================= presplit kernels =================
// H0 fp32 [NV,300] -> g_af16 fp16 [NV,320]
__global__ void pre_act_f16_kernel(const float* __restrict__ X) {
    int idx = blockIdx.x * blockDim.x + threadIdx.x;
    if (idx >= NV * 75) return;
    int r = idx / 75;
    int q = idx - r * 75;
    float4 v = reinterpret_cast<const float4*>(X)[(size_t)r * 75 + q];
    __half2 p0 = __floats2half2_rn(v.x, v.y);
    __half2 p1 = __floats2half2_rn(v.z, v.w);
    uint2 pk = make_uint2(*reinterpret_cast<uint32_t*>(&p0),
                          *reinterpret_cast<uint32_t*>(&p1));
    *reinterpret_cast<uint2*>(&g_af16[(size_t)r * AP + q * 4]) = pk;
}

// W row-major [K][N] -> transposed fp16 hi/lo at [n*ldo + k]
__global__ void pre_wT_kernel(const float* __restrict__ W, int K, int N, int ldo,
                              __half* __restrict__ th, __half* __restrict__ tl) {
    int idx = blockIdx.x * blockDim.x + threadIdx.x;
    if (idx >= K * N) return;
    int k = idx / N;
    int n = idx - k * N;
    __half h, l;
    split_f16(W[idx], h, l);
    th[(size_t)n * ldo + k] = h;
    tl[(size_t)n * ldo + k] = l;
}

// ================= pipelined tensor-core GEMM (fp16, 2-term) ================
// C[M,N] = A[M,K] @ B[K,N]; A single fp16 (lda), B transposed [n][k] hi/lo (ldb)
// BM=128, BN=160, BK=32, 512 threads. modes: 0 fp32 / 1 bias+sig fp32 /
// 2 bias+sig -> fp16 (ohi stride ldo)
#define GB_SM_ABUF 10240
#define GB_SM_BBUF 25600
#define GB_SM_BOFF (2 * GB_SM_ABUF)                 // 20480
#define GB_SM_TOTAL (GB_SM_BOFF + 2 * GB_SM_BBUF)   // 71680

__global__ void __launch_bounds__(512)
gemm_f16_kernel(const __half* __restrict__ a16, int lda,
                const __half* __restrict__ bth, const __half* __restrict__ btl, int ldb,
                float* __restrict__ C, int ldc,
                __half* __restrict__ o16, int ldo,
                const float* __restrict__ bias,
                int M, int N, int K, int mode) {
    extern __shared__ __align__(16) char sm[];
    int tid = threadIdx.x;
    int w = tid >> 5;
    int lane = tid & 31;
    int g = lane >> 2;
    int t2 = (lane & 3) * 2;

    int bm = blockIdx.y * 128;
    int bn = blockIdx.x * 160;
    int m0 = (w & 3) * 32;
    int n0 = (w >> 2) * 40;
    int nch = K >> 5;

    float acc[2][5][4];
#pragma unroll
    for (int i = 0; i < 2; i++)
#pragma unroll
        for (int j = 0; j < 5; j++)
#pragma unroll
            for (int q = 0; q < 4; q++) acc[i][j][q] = 0.0f;

    auto prefetch = [&](int ch, int buf) {
        int k0 = ch * 32;
        {   // A: 128 rows x 32 fp16 = 8192B = 512 x 16B, exactly 1/thread
            int r = tid >> 2;
            int c = tid & 3;
            int gr = bm + r;
            if (gr > M - 1) gr = M - 1;
            size_t so = (size_t)gr * lda + k0 + c * 8;
            uint32_t d = cvta_shared_u32(sm + buf * GB_SM_ABUF + (r * 40 + c * 8) * 2);
            cp_async16(d, a16 + so);
        }
#pragma unroll
        for (int it = 0; it < 2; it++) {  // B: 160 rows x 32 fp16, hi+lo
            int idx = tid + it * 512;
            if (idx < 640) {
                int r = idx >> 2;
                int c = idx & 3;
                size_t so = (size_t)(bn + r) * ldb + k0 + c * 8;
                uint32_t d = cvta_shared_u32(sm + GB_SM_BOFF + buf * GB_SM_BBUF +
                                             (r * 40 + c * 8) * 2);
                cp_async16(d, bth + so);
                cp_async16(d + 12800, btl + so);
            }
        }
    };

    prefetch(0, 0);
    cp_commit();

    for (int ch = 0; ch < nch; ch++) {
        int buf = ch & 1;
        cp_wait0();
        __syncthreads();
        if (ch < nch - 1) {
            prefetch(ch + 1, buf ^ 1);
            cp_commit();
        }
        const __half* Af = reinterpret_cast<const __half*>(sm + buf * GB_SM_ABUF);
        const __half* Bh = reinterpret_cast<const __half*>(sm + GB_SM_BOFF + buf * GB_SM_BBUF);
        const __half* Bl = Bh + 6400;

#pragma unroll
        for (int kc = 0; kc < 32; kc += 16) {
            uint32_t af[2][4];
#pragma unroll
            for (int i = 0; i < 2; i++) {
                int rm = m0 + i * 16;
                af[i][0] = *reinterpret_cast<const uint32_t*>(&Af[(rm + g)     * 40 + kc + t2]);
                af[i][1] = *reinterpret_cast<const uint32_t*>(&Af[(rm + g + 8) * 40 + kc + t2]);
                af[i][2] = *reinterpret_cast<const uint32_t*>(&Af[(rm + g)     * 40 + kc + t2 + 8]);
                af[i][3] = *reinterpret_cast<const uint32_t*>(&Af[(rm + g + 8) * 40 + kc + t2 + 8]);
            }
#pragma unroll
            for (int j = 0; j < 5; j++) {
                int rn = n0 + j * 8;
                uint32_t bh[2], bl[2];
                bh[0] = *reinterpret_cast<const uint32_t*>(&Bh[(rn + g) * 40 + kc + t2]);
                bh[1] = *reinterpret_cast<const uint32_t*>(&Bh[(rn + g) * 40 + kc + t2 + 8]);
                bl[0] = *reinterpret_cast<const uint32_t*>(&Bl[(rn + g) * 40 + kc + t2]);
                bl[1] = *reinterpret_cast<const uint32_t*>(&Bl[(rn + g) * 40 + kc + t2 + 8]);
#pragma unroll
                for (int i = 0; i < 2; i++) {
                    mma16816(acc[i][j], af[i], bh);
                    mma16816(acc[i][j], af[i], bl);
                }
            }
        }
        __syncthreads();
    }

    // ---- epilogue ----
#pragma unroll
    for (int i = 0; i < 2; i++) {
#pragma unroll
        for (int j = 0; j < 5; j++) {
            int gn = bn + n0 + j * 8 + t2;
            if (gn >= N) continue;      // N even, gn even -> gn+1 safe
#pragma unroll
            for (int half = 0; half < 2; half++) {
                int gr = bm + m0 + i * 16 + g + half * 8;
                if (gr >= M) continue;
                float2 o;
                o.x = acc[i][j][half * 2 + 0];
                o.y = acc[i][j][half * 2 + 1];
                if (mode != 0) {
                    o.x += bias[gn];
                    o.y += bias[gn + 1];
                    o.x = 1.0f / (1.0f + __expf(-o.x));
                    o.y = 1.0f / (1.0f + __expf(-o.y));
                }
                if (mode == 2) {
                    __half2 hv = __floats2half2_rn(o.x, o.y);
                    *reinterpret_cast<uint32_t*>(&o16[(size_t)gr * ldo + gn]) =
                        *reinterpret_cast<uint32_t*>(&hv);
                } else {
                    *reinterpret_cast<float2*>(C + (size_t)gr * ldc + gn) = o;
                }
            }
        }
    }
}

// ================= graph preprocessing =================
__global__ void zero_int_kernel(int* p, int n) {
    int i = blockIdx.x * blockDim.x + threadIdx.x;
    if (i < n) p[i] = 0;
}

__global__ void count_kernel(const int* __restrict__ erow) {
    int e = blockIdx.x * blockDim.x + threadIdx.x;
    if (e < NE) atomicAdd(&g_cnt[erow[e]], 1);
}

__global__ void vals_kernel(const int* __restrict__ erow, const int* __restrict__ ecol) {
    int e = blockIdx.x * blockDim.x + threadIdx.x;
    if (e >= NE) return;
    int dr = g_cnt[erow[e]];
    int dc = g_cnt[ecol[e]];
    float a = (dr > 0) ? rsqrtf((float)dr) : 0.0f;
    float b = (dc > 0) ? rsqrtf((float)dc) : 0.0f;
    g_vals[e] = a * b;
}

__global__ void scanA_kernel() {
    __shared__ int s[1024];
    int i = blockIdx.x * 1024 + threadIdx.x;
    int v = (i < NV) ? g_cnt[i] : 0;
    s[threadIdx.x] = v;
    __syncthreads();
    for (int o = 1; o < 1024; o <<= 1) {
        int t = 0;
        if (threadIdx.x >= o) t = s[threadIdx.x - o];
        __syncthreads();
        if (threadIdx.x >= o) s[threadIdx.x] += t;
        __syncthreads();
    }
    if (i < NV) g_rowstart[i] = s[threadIdx.x] - v;
    if (threadIdx.x == 1023) g_tot[blockIdx.x] = s[1023];
}

__global__ void scanB_kernel() {
    __shared__ int s[128];
    int v = (threadIdx.x < NBLK_SCAN) ? g_tot[threadIdx.x] : 0;
    s[threadIdx.x] = v;
    __syncthreads();
    for (int o = 1; o < 128; o <<= 1) {
        int t = 0;
        if (threadIdx.x >= o) t = s[threadIdx.x - o];
        __syncthreads();
        if (threadIdx.x >= o) s[threadIdx.x] += t;
        __syncthreads();
    }
    if (threadIdx.x < NBLK_SCAN) g_tot[threadIdx.x] = s[threadIdx.x] - v;
}

__global__ void scanC_kernel() {
    int i = blockIdx.x * blockDim.x + threadIdx.x;
    if (i < NV) g_rowstart[i] += g_tot[i >> 10];
    if (i == 0) g_rowstart[NV] = NE;
}

__global__ void scatter_kernel(const int* __restrict__ erow, const int* __restrict__ ecol) {
    int e = blockIdx.x * blockDim.x + threadIdx.x;
    if (e >= NE) return;
    int r = erow[e];
    int pos = g_rowstart[r] + atomicAdd(&g_cursor[r], 1);
    g_scol[pos] = ecol[e];
    g_sval[pos] = g_vals[e];
}

// ================= feature-tiled pull SpMM + fused sigmoid ==================
// Processes feature f4-range [f0, f0+nf4). One warp per row. Working set of X
// per pass fits in L2 (<=75MB), so each X element hits DRAM once per pass.
__device__ __forceinline__ void spmm_row_range(const float* __restrict__ X,
                                               int row, int lane, int f0, int nf4,
                                               float4& a0, float4& a1, bool has2) {
    int s = g_rowstart[row];
    int e = g_rowstart[row + 1];
    a0 = make_float4(0.f,0.f,0.f,0.f);
    a1 = make_float4(0.f,0.f,0.f,0.f);
    float4 b0 = a0, b1 = a1;
    int j = s;
    for (; j + 1 < e; j += 2) {
        int c0 = g_scol[j];
        float v0 = g_sval[j];
        int c1 = g_scol[j + 1];
        float v1 = g_sval[j + 1];
        const float4* x0 = reinterpret_cast<const float4*>(X + (size_t)c0 * EMB) + f0;
        const float4* x1 = reinterpret_cast<const float4*>(X + (size_t)c1 * EMB) + f0;
        float4 t0 = x0[lane], u0 = x1[lane];
        a0.x += v0*t0.x; a0.y += v0*t0.y; a0.z += v0*t0.z; a0.w += v0*t0.w;
        b0.x += v1*u0.x; b0.y += v1*u0.y; b0.z += v1*u0.z; b0.w += v1*u0.w;
        if (has2) {
            float4 t1 = x0[lane + 32], u1 = x1[lane + 32];
            a1.x += v0*t1.x; a1.y += v0*t1.y; a1.z += v0*t1.z; a1.w += v0*t1.w;
            b1.x += v1*u1.x; b1.y += v1*u1.y; b1.z += v1*u1.z; b1.w += v1*u1.w;
        }
    }
    if (j < e) {
        int c = g_scol[j];
        float v = g_sval[j];
        const float4* x4 = reinterpret_cast<const float4*>(X + (size_t)c * EMB) + f0;
        float4 t0 = x4[lane];
        a0.x += v*t0.x; a0.y += v*t0.y; a0.z += v*t0.z; a0.w += v*t0.w;
        if (has2) {
            float4 t1 = x4[lane + 32];
            a1.x += v*t1.x; a1.y += v*t1.y; a1.z += v*t1.z; a1.w += v*t1.w;
        }
    }
    a0.x += b0.x; a0.y += b0.y; a0.z += b0.z; a0.w += b0.w;
    a1.x += b1.x; a1.y += b1.y; a1.z += b1.z; a1.w += b1.w;
    a0.x = 1.0f/(1.0f+__expf(-a0.x)); a0.y = 1.0f/(1.0f+__expf(-a0.y));
    a0.z = 1.0f/(1.0f+__expf(-a0.z)); a0.w = 1.0f/(1.0f+__expf(-a0.w));
    a1.x = 1.0f/(1.0f+__expf(-a1.x)); a1.y = 1.0f/(1.0f+__expf(-a1.y));
    a1.z = 1.0f/(1.0f+__expf(-a1.z)); a1.w = 1.0f/(1.0f+__expf(-a1.w));
}

// output -> fp16 activations g_af16 (stride AP), streaming stores
__global__ void spmm_f16_kernel(const float* __restrict__ X, int f0, int nf4) {
    int warp = (blockIdx.x * blockDim.x + threadIdx.x) >> 5;
    int lane = threadIdx.x & 31;
    if (warp >= NV) return;
    bool has2 = (lane + 32) < nf4;
    float4 a0, a1;
    spmm_row_range(X, warp, lane, f0, nf4, a0, a1, has2);
    size_t base = (size_t)warp * AP + f0 * 4;
    __half2 p0 = __floats2half2_rn(a0.x, a0.y);
    __half2 p1 = __floats2half2_rn(a0.z, a0.w);
    float2 pk;
    *reinterpret_cast<uint32_t*>(&pk.x) = *reinterpret_cast<uint32_t*>(&p0);
    *reinterpret_cast<uint32_t*>(&pk.y) = *reinterpret_cast<uint32_t*>(&p1);
    __stcs(reinterpret_cast<float2*>(&g_af16[base + lane * 4]), pk);
    if (has2) {
        p0 = __floats2half2_rn(a1.x, a1.y);
        p1 = __floats2half2_rn(a1.z, a1.w);
        *reinterpret_cast<uint32_t*>(&pk.x) = *reinterpret_cast<uint32_t*>(&p0);
        *reinterpret_cast<uint32_t*>(&pk.y) = *reinterpret_cast<uint32_t*>(&p1);
        __stcs(reinterpret_cast<float2*>(&g_af16[base + (lane + 32) * 4]), pk);
    }
}

// output -> fp32 (stride EMB), streaming stores
__global__ void spmm_f32_kernel(const float* __restrict__ X, float* __restrict__ out,
                                int f0, int nf4) {
    int warp = (blockIdx.x * blockDim.x + threadIdx.x) >> 5;
    int lane = threadIdx.x & 31;
    if (warp >= NV) return;
    bool has2 = (lane + 32) < nf4;
    float4 a0, a1;
    spmm_row_range(X, warp, lane, f0, nf4, a0, a1, has2);
    float4* o4 = reinterpret_cast<float4*>(out + (size_t)warp * EMB) + f0;
    __stcs(&o4[lane], a0);
    if (has2) __stcs(&o4[lane + 32], a1);
}

// build fc = concat(H2[node], input) -> fp16 [BATCH, FCP]
__global__ void fc_build_f16_kernel(const float* __restrict__ H2,
                                    const int* __restrict__ node,
                                    const float* __restrict__ input) {
    int idx = blockIdx.x * blockDim.x + threadIdx.x;
    if (idx >= BATCH * FCK) return;
    int b = idx / FCK;
    int j = idx - b * FCK;
    float v;
    if (j < EMB) {
        size_t n = (size_t)node[b];
        v = H2[n * EMB + j];
    } else {
        v = input[(size_t)b * IN_DIM + (j - EMB)];
    }
    g_fcf16[(size_t)b * FCP + j] = __float2half_rn(v);
}

// final layer
__global__ void final_kernel(const float* __restrict__ h,
                             const float* __restrict__ Wc,
                             const float* __restrict__ bc,
                             float* __restrict__ out) {
    int warp = (blockIdx.x * blockDim.x + threadIdx.x) >> 5;
    int lane = threadIdx.x & 31;
    if (warp >= BATCH) return;
    const float* hr = h + (size_t)warp * HID;
    float a0 = 0.f, a1 = 0.f;
    for (int k = lane; k < HID; k += 32) {
        float hv = hr[k];
        a0 += hv * Wc[k * 2 + 0];
        a1 += hv * Wc[k * 2 + 1];
    }
#pragma unroll
    for (int o = 16; o > 0; o >>= 1) {
        a0 += __shfl_down_sync(0xFFFFFFFFu, a0, o);
        a1 += __shfl_down_sync(0xFFFFFFFFu, a1, o);
    }
    if (lane == 0) {
        out[warp * 2 + 0] = a0 + bc[0];
        out[warp * 2 + 1] = a1 + bc[1];
    }
}

// ================= host launch =================
extern "C" void kernel_launch(void* const* d_in, const int* in_sizes, int n_in,
                              void* d_out, int out_size) {
    const float* input = (const float*)d_in[0];
    const int*   node  = (const int*)d_in[1];
    const int*   erow  = (const int*)d_in[2];
    const int*   ecol  = (const int*)d_in[3];
    const float* H0    = (const float*)d_in[4];
    const float* W1    = (const float*)d_in[5];
    const float* W2    = (const float*)d_in[6];
    const float* Wa    = (const float*)d_in[7];
    const float* ba    = (const float*)d_in[8];
    const float* Wb    = (const float*)d_in[9];
    const float* bb    = (const float*)d_in[10];
    const float* Wc    = (const float*)d_in[11];
    const float* bc    = (const float*)d_in[12];
    float*       out   = (float*)d_out;

    void *p_cnt, *p_cursor, *p_bufA, *p_bufB, *p_h2;
    void *p_af16, *p_w1th, *p_w1tl, *p_w2th, *p_w2tl;
    void *p_fcf16, *p_wath, *p_watl, *p_wbth, *p_wbtl, *p_h1f16;
    cudaGetSymbolAddress(&p_cnt,    g_cnt);
    cudaGetSymbolAddress(&p_cursor, g_cursor);
    cudaGetSymbolAddress(&p_bufA,   g_bufA);
    cudaGetSymbolAddress(&p_bufB,   g_bufB);
    cudaGetSymbolAddress(&p_h2,     g_h2);
    cudaGetSymbolAddress(&p_af16,   g_af16);
    cudaGetSymbolAddress(&p_w1th,   g_w1th);
    cudaGetSymbolAddress(&p_w1tl,   g_w1tl);
    cudaGetSymbolAddress(&p_w2th,   g_w2th);
    cudaGetSymbolAddress(&p_w2tl,   g_w2tl);
    cudaGetSymbolAddress(&p_fcf16,  g_fcf16);
    cudaGetSymbolAddress(&p_wath,   g_wath);
    cudaGetSymbolAddress(&p_watl,   g_watl);
    cudaGetSymbolAddress(&p_wbth,   g_wbth);
    cudaGetSymbolAddress(&p_wbtl,   g_wbtl);
    cudaGetSymbolAddress(&p_h1f16,  g_h1f16);

    float* bufA = (float*)p_bufA;
    float* bufB = (float*)p_bufB;
    float* h2   = (float*)p_h2;

    cudaFuncSetAttribute(gemm_f16_kernel,
                         cudaFuncAttributeMaxDynamicSharedMemorySize, GB_SM_TOTAL);

    static cudaStream_t s2 = nullptr;
    static cudaEvent_t evF = nullptr, evJ = nullptr;
    if (!s2) {
        cudaStreamCreateWithFlags(&s2, cudaStreamNonBlocking);
        cudaEventCreateWithFlags(&evF, cudaEventDisableTiming);
        cudaEventCreateWithFlags(&evJ, cudaEventDisableTiming);
    }

    const int TPB = 256;

    // ---- fork: CSR build chain on s2 ----
    cudaEventRecord(evF, 0);
    cudaStreamWaitEvent(s2, evF, 0);
    zero_int_kernel<<<(NV + TPB - 1) / TPB, TPB, 0, s2>>>((int*)p_cnt, NV);
    zero_int_kernel<<<(NV + TPB - 1) / TPB, TPB, 0, s2>>>((int*)p_cursor, NV);
    count_kernel<<<(NE + TPB - 1) / TPB, TPB, 0, s2>>>(erow);
    vals_kernel<<<(NE + TPB - 1) / TPB, TPB, 0, s2>>>(erow, ecol);
    scanA_kernel<<<NBLK_SCAN, 1024, 0, s2>>>();
    scanB_kernel<<<1, 128, 0, s2>>>();
    scanC_kernel<<<(NV + TPB - 1) / TPB, TPB, 0, s2>>>();
    scatter_kernel<<<(NE + TPB - 1) / TPB, TPB, 0, s2>>>(erow, ecol);
    cudaEventRecord(evJ, s2);

    // ---- main stream: prepare fp16 operands ----
    pre_act_f16_kernel<<<(NV * 75 + TPB - 1) / TPB, TPB>>>(H0);
    pre_wT_kernel<<<(EMB * EMB + TPB - 1) / TPB, TPB>>>(W1, EMB, EMB, AP,
        (__half*)p_w1th, (__half*)p_w1tl);
    pre_wT_kernel<<<(EMB * EMB + TPB - 1) / TPB, TPB>>>(W2, EMB, EMB, AP,
        (__half*)p_w2th, (__half*)p_w2tl);
    pre_wT_kernel<<<(FCK * HID + TPB - 1) / TPB, TPB>>>(Wa, FCK, HID, FCP,
        (__half*)p_wath, (__half*)p_watl);
    pre_wT_kernel<<<(HID * HID + TPB - 1) / TPB, TPB>>>(Wb, HID, HID, HP,
        (__half*)p_wbth, (__half*)p_wbtl);

    // ---- GCN layer 1 GEMM ----
    dim3 gbig(2, (NV + 127) / 128);
    gemm_f16_kernel<<<gbig, 512, GB_SM_TOTAL>>>(
        (__half*)p_af16, AP, (__half*)p_w1th, (__half*)p_w1tl, AP,
        bufA, EMB, nullptr, 0, nullptr, NV, EMB, AP, 0);

    // ---- join CSR chain, then SpMM 1 (2 feature-tiled passes) ----
    cudaStreamWaitEvent(0, evJ, 0);
    int spmmBlocks = (NV * 32 + TPB - 1) / TPB;
    spmm_f16_kernel<<<spmmBlocks, TPB>>>(bufA, 0, 40);
    spmm_f16_kernel<<<spmmBlocks, TPB>>>(bufA, 40, 35);

    // ---- GCN layer 2 ----
    gemm_f16_kernel<<<gbig, 512, GB_SM_TOTAL>>>(
        (__half*)p_af16, AP, (__half*)p_w2th, (__half*)p_w2tl, AP,
        bufA, EMB, nullptr, 0, nullptr, NV, EMB, AP, 0);
    spmm_f32_kernel<<<spmmBlocks, TPB>>>(bufA, bufB, 0, 40);
    spmm_f32_kernel<<<spmmBlocks, TPB>>>(bufA, bufB, 40, 35);

    // ---- MLP head ----
    fc_build_f16_kernel<<<(BATCH * FCK + TPB - 1) / TPB, TPB>>>(bufB, node, input);

    dim3 gmlp(4, BATCH / 128);   // N=500 -> 4 col blocks of 160
    gemm_f16_kernel<<<gmlp, 512, GB_SM_TOTAL>>>(
        (__half*)p_fcf16, FCP, (__half*)p_wath, (__half*)p_watl, FCP,
        nullptr, 0, (__half*)p_h1f16, HP, ba, BATCH, HID, FCP, 2);
    gemm_f16_kernel<<<gmlp, 512, GB_SM_TOTAL>>>(
        (__half*)p_h1f16, HP, (__half*)p_wbth, (__half*)p_wbtl, HP,
        h2, HID, nullptr, 0, bb, BATCH, HID, HP, 1);

    final_kernel<<<(BATCH * 32 + TPB - 1) / TPB, TPB>>>(h2, Wc, bc, out);
}

// round 8
// speedup vs baseline: 3.7369x; 1.5337x over previous
#include <cuda_runtime.h>
#include <cuda_fp16.h>
#include <math.h>
#include <cstdint>

#define NV 117000
#define NE 468000
#define EMB 300
#define IN_DIM 768
#define BATCH 4096
#define HID 500
#define FCK (EMB + IN_DIM)   // 1068
#define NBLK_SCAN ((NV + 1023) / 1024)   // 115
#define AP 320               // padded fp16 stride for GCN activations/weights
#define FCP 1088             // padded fc width
#define HP 512               // padded hidden width
#define BNROWS 640           // padded N-rows for transposed MLP weights

// ---------------- device scratch (allocation-free, zero-initialized) -------
__device__ float g_vals[NE];
__device__ int   g_cnt[NV];
__device__ int   g_rowstart[NV + 1];
__device__ int   g_tot[256];
__device__ int   g_cursor[NV];
__device__ int   g_scol[NE];
__device__ float g_sval[NE];
__device__ float g_h2[BATCH * HID];
// fp16 buffers (pads stay statically zero — never written)
__device__ __half g_act[(size_t)NV * AP];           // activations ping
__device__ __half g_x16[(size_t)NV * AP];           // GEMM output pong
__device__ __half g_w1t[AP * AP];
__device__ __half g_w2t[AP * AP];
__device__ __half g_fcf16[(size_t)BATCH * FCP];
__device__ __half g_wat[(size_t)BNROWS * FCP];
__device__ __half g_wbt[(size_t)BNROWS * HP];
__device__ __half g_h1f16[(size_t)BATCH * HP];

// ================= helpers =================
__device__ __forceinline__ void mma16816(float* c, const uint32_t* a, const uint32_t* b) {
    asm volatile(
        "mma.sync.aligned.m16n8k16.row.col.f32.f16.f16.f32 "
        "{%0,%1,%2,%3}, {%4,%5,%6,%7}, {%8,%9}, {%0,%1,%2,%3};"
        : "+f"(c[0]), "+f"(c[1]), "+f"(c[2]), "+f"(c[3])
        : "r"(a[0]), "r"(a[1]), "r"(a[2]), "r"(a[3]),
          "r"(b[0]), "r"(b[1]));
}

__device__ __forceinline__ uint32_t cvta_shared_u32(const void* p) {
    uint32_t a;
    asm("{ .reg .u64 t; cvta.to.shared.u64 t, %1; cvt.u32.u64 %0, t; }"
        : "=r"(a) : "l"(p));
    return a;
}

__device__ __forceinline__ void cp_async16(uint32_t dst, const void* src) {
    asm volatile("cp.async.ca.shared.global [%0], [%1], 16;" :: "r"(dst), "l"(src));
}
__device__ __forceinline__ void cp_commit() {
    asm volatile("cp.async.commit_group;");
}
__device__ __forceinline__ void cp_wait0() {
    asm volatile("cp.async.wait_group 0;");
}

// ================= prep kernels =================
// H0 fp32 [NV,300] -> g_act fp16 [NV,320]
__global__ void pre_act_f16_kernel(const float* __restrict__ X) {
    int idx = blockIdx.x * blockDim.x + threadIdx.x;
    if (idx >= NV * 75) return;
    int r = idx / 75;
    int q = idx - r * 75;
    float4 v = reinterpret_cast<const float4*>(X)[(size_t)r * 75 + q];
    __half2 p0 = __floats2half2_rn(v.x, v.y);
    __half2 p1 = __floats2half2_rn(v.z, v.w);
    uint2 pk = make_uint2(*reinterpret_cast<uint32_t*>(&p0),
                          *reinterpret_cast<uint32_t*>(&p1));
    *reinterpret_cast<uint2*>(&g_act[(size_t)r * AP + q * 4]) = pk;
}

// W row-major [K][N] -> transposed fp16 at [n*ldo + k]
__global__ void pre_wT_kernel(const float* __restrict__ W, int K, int N, int ldo,
                              __half* __restrict__ t16) {
    int idx = blockIdx.x * blockDim.x + threadIdx.x;
    if (idx >= K * N) return;
    int k = idx / N;
    int n = idx - k * N;
    t16[(size_t)n * ldo + k] = __float2half_rn(W[idx]);
}

// ================= pipelined fp16 tensor-core GEMM ==========================
// C[M,N] = A[M,K] @ B[K,N]; A fp16 (lda), B transposed [n][k] fp16 (ldb).
// BM=128, BN=160, BK=32, 512 threads.
// mode 0: fp32 store  1: bias+sig fp32  2: bias+sig fp16  3: plain fp16
#define GS_ABUF 10240
#define GS_BBUF 12800
#define GS_BOFF (2 * GS_ABUF)                  // 20480
#define GS_TOTAL (GS_BOFF + 2 * GS_BBUF)       // 46080

__global__ void __launch_bounds__(512)
gemm_f16_kernel(const __half* __restrict__ a16, int lda,
                const __half* __restrict__ bt, int ldb,
                float* __restrict__ C, int ldc,
                __half* __restrict__ o16, int ldo,
                const float* __restrict__ bias,
                int M, int N, int K, int mode) {
    extern __shared__ __align__(16) char sm[];
    int tid = threadIdx.x;
    int w = tid >> 5;
    int lane = tid & 31;
    int g = lane >> 2;
    int t2 = (lane & 3) * 2;

    int bm = blockIdx.y * 128;
    int bn = blockIdx.x * 160;
    int m0 = (w & 3) * 32;
    int n0 = (w >> 2) * 40;
    int nch = K >> 5;

    float acc[2][5][4];
#pragma unroll
    for (int i = 0; i < 2; i++)
#pragma unroll
        for (int j = 0; j < 5; j++)
#pragma unroll
            for (int q = 0; q < 4; q++) acc[i][j][q] = 0.0f;

    auto prefetch = [&](int ch, int buf) {
        int k0 = ch * 32;
        {   // A: 128 rows x 32 fp16 = 512 x 16B, 1/thread
            int r = tid >> 2;
            int c = tid & 3;
            int gr = bm + r;
            if (gr > M - 1) gr = M - 1;
            size_t so = (size_t)gr * lda + k0 + c * 8;
            uint32_t d = cvta_shared_u32(sm + buf * GS_ABUF + (r * 40 + c * 8) * 2);
            cp_async16(d, a16 + so);
        }
#pragma unroll
        for (int it = 0; it < 2; it++) {  // B: 160 rows x 32 fp16 = 640 x 16B
            int idx = tid + it * 512;
            if (idx < 640) {
                int r = idx >> 2;
                int c = idx & 3;
                size_t so = (size_t)(bn + r) * ldb + k0 + c * 8;
                uint32_t d = cvta_shared_u32(sm + GS_BOFF + buf * GS_BBUF +
                                             (r * 40 + c * 8) * 2);
                cp_async16(d, bt + so);
            }
        }
    };

    prefetch(0, 0);
    cp_commit();

    for (int ch = 0; ch < nch; ch++) {
        int buf = ch & 1;
        cp_wait0();
        __syncthreads();
        if (ch < nch - 1) {
            prefetch(ch + 1, buf ^ 1);
            cp_commit();
        }
        const __half* Af = reinterpret_cast<const __half*>(sm + buf * GS_ABUF);
        const __half* Bf = reinterpret_cast<const __half*>(sm + GS_BOFF + buf * GS_BBUF);

#pragma unroll
        for (int kc = 0; kc < 32; kc += 16) {
            uint32_t af[2][4];
#pragma unroll
            for (int i = 0; i < 2; i++) {
                int rm = m0 + i * 16;
                af[i][0] = *reinterpret_cast<const uint32_t*>(&Af[(rm + g)     * 40 + kc + t2]);
                af[i][1] = *reinterpret_cast<const uint32_t*>(&Af[(rm + g + 8) * 40 + kc + t2]);
                af[i][2] = *reinterpret_cast<const uint32_t*>(&Af[(rm + g)     * 40 + kc + t2 + 8]);
                af[i][3] = *reinterpret_cast<const uint32_t*>(&Af[(rm + g + 8) * 40 + kc + t2 + 8]);
            }
#pragma unroll
            for (int j = 0; j < 5; j++) {
                int rn = n0 + j * 8;
                uint32_t bf[2];
                bf[0] = *reinterpret_cast<const uint32_t*>(&Bf[(rn + g) * 40 + kc + t2]);
                bf[1] = *reinterpret_cast<const uint32_t*>(&Bf[(rn + g) * 40 + kc + t2 + 8]);
#pragma unroll
                for (int i = 0; i < 2; i++)
                    mma16816(acc[i][j], af[i], bf);
            }
        }
        __syncthreads();
    }

    // ---- epilogue ----
#pragma unroll
    for (int i = 0; i < 2; i++) {
#pragma unroll
        for (int j = 0; j < 5; j++) {
            int gn = bn + n0 + j * 8 + t2;
            if (gn >= N) continue;      // N even, gn even -> gn+1 safe
#pragma unroll
            for (int half = 0; half < 2; half++) {
                int gr = bm + m0 + i * 16 + g + half * 8;
                if (gr >= M) continue;
                float2 o;
                o.x = acc[i][j][half * 2 + 0];
                o.y = acc[i][j][half * 2 + 1];
                if (mode == 1 || mode == 2) {
                    o.x += bias[gn];
                    o.y += bias[gn + 1];
                    o.x = 1.0f / (1.0f + __expf(-o.x));
                    o.y = 1.0f / (1.0f + __expf(-o.y));
                }
                if (mode >= 2) {
                    __half2 hv = __floats2half2_rn(o.x, o.y);
                    *reinterpret_cast<uint32_t*>(&o16[(size_t)gr * ldo + gn]) =
                        *reinterpret_cast<uint32_t*>(&hv);
                } else {
                    *reinterpret_cast<float2*>(C + (size_t)gr * ldc + gn) = o;
                }
            }
        }
    }
}

// ================= graph preprocessing =================
__global__ void zero_int_kernel(int* p, int n) {
    int i = blockIdx.x * blockDim.x + threadIdx.x;
    if (i < n) p[i] = 0;
}

__global__ void count_kernel(const int* __restrict__ erow) {
    int e = blockIdx.x * blockDim.x + threadIdx.x;
    if (e < NE) atomicAdd(&g_cnt[erow[e]], 1);
}

__global__ void vals_kernel(const int* __restrict__ erow, const int* __restrict__ ecol) {
    int e = blockIdx.x * blockDim.x + threadIdx.x;
    if (e >= NE) return;
    int dr = g_cnt[erow[e]];
    int dc = g_cnt[ecol[e]];
    float a = (dr > 0) ? rsqrtf((float)dr) : 0.0f;
    float b = (dc > 0) ? rsqrtf((float)dc) : 0.0f;
    g_vals[e] = a * b;
}

__global__ void scanA_kernel() {
    __shared__ int s[1024];
    int i = blockIdx.x * 1024 + threadIdx.x;
    int v = (i < NV) ? g_cnt[i] : 0;
    s[threadIdx.x] = v;
    __syncthreads();
    for (int o = 1; o < 1024; o <<= 1) {
        int t = 0;
        if (threadIdx.x >= o) t = s[threadIdx.x - o];
        __syncthreads();
        if (threadIdx.x >= o) s[threadIdx.x] += t;
        __syncthreads();
    }
    if (i < NV) g_rowstart[i] = s[threadIdx.x] - v;
    if (threadIdx.x == 1023) g_tot[blockIdx.x] = s[1023];
}

__global__ void scanB_kernel() {
    __shared__ int s[128];
    int v = (threadIdx.x < NBLK_SCAN) ? g_tot[threadIdx.x] : 0;
    s[threadIdx.x] = v;
    __syncthreads();
    for (int o = 1; o < 128; o <<= 1) {
        int t = 0;
        if (threadIdx.x >= o) t = s[threadIdx.x - o];
        __syncthreads();
        if (threadIdx.x >= o) s[threadIdx.x] += t;
        __syncthreads();
    }
    if (threadIdx.x < NBLK_SCAN) g_tot[threadIdx.x] = s[threadIdx.x] - v;
}

__global__ void scanC_kernel() {
    int i = blockIdx.x * blockDim.x + threadIdx.x;
    if (i < NV) g_rowstart[i] += g_tot[i >> 10];
    if (i == 0) g_rowstart[NV] = NE;
}

__global__ void scatter_kernel(const int* __restrict__ erow, const int* __restrict__ ecol) {
    int e = blockIdx.x * blockDim.x + threadIdx.x;
    if (e >= NE) return;
    int r = erow[e];
    int pos = g_rowstart[r] + atomicAdd(&g_cursor[r], 1);
    g_scol[pos] = ecol[e];
    g_sval[pos] = g_vals[e];
}

// ================= fp16 pull SpMM + fused sigmoid ===========================
// X: fp16 [NV, AP] (75 MB — L2 resident). One warp per row. Each lane owns
// uint4 slot `lane` (features 8*lane..8*lane+7); lanes 0..7 also own slot
// 32+lane (features 256..319, pad-masked at 300). Output fp16 [NV, AP].
__device__ __forceinline__ void fma8(float* acc, uint4 t, float v) {
    __half2 p;
    float2 f;
    *reinterpret_cast<uint32_t*>(&p) = t.x; f = __half22float2(p);
    acc[0] += v * f.x; acc[1] += v * f.y;
    *reinterpret_cast<uint32_t*>(&p) = t.y; f = __half22float2(p);
    acc[2] += v * f.x; acc[3] += v * f.y;
    *reinterpret_cast<uint32_t*>(&p) = t.z; f = __half22float2(p);
    acc[4] += v * f.x; acc[5] += v * f.y;
    *reinterpret_cast<uint32_t*>(&p) = t.w; f = __half22float2(p);
    acc[6] += v * f.x; acc[7] += v * f.y;
}

__global__ void spmm_f16_kernel(const __half* __restrict__ X, __half* __restrict__ O) {
    int warp = (blockIdx.x * blockDim.x + threadIdx.x) >> 5;
    int lane = threadIdx.x & 31;
    if (warp >= NV) return;
    int s = g_rowstart[warp];
    int e = g_rowstart[warp + 1];
    bool lo8 = lane < 8;
    float a[8] = {0,0,0,0,0,0,0,0};
    float b[8] = {0,0,0,0,0,0,0,0};
    int j = s;
    for (; j + 1 < e; j += 2) {
        int c0 = g_scol[j];
        float v0 = g_sval[j];
        int c1 = g_scol[j + 1];
        float v1 = g_sval[j + 1];
        const uint4* x0 = reinterpret_cast<const uint4*>(X + (size_t)c0 * AP);
        const uint4* x1 = reinterpret_cast<const uint4*>(X + (size_t)c1 * AP);
        uint4 t0 = x0[lane];
        uint4 t1 = x1[lane];
        fma8(a, t0, v0);
        fma8(a, t1, v1);
        if (lo8) {
            uint4 s0 = x0[32 + lane];
            uint4 s1 = x1[32 + lane];
            fma8(b, s0, v0);
            fma8(b, s1, v1);
        }
    }
    if (j < e) {
        int c = g_scol[j];
        float v = g_sval[j];
        const uint4* x4 = reinterpret_cast<const uint4*>(X + (size_t)c * AP);
        fma8(a, x4[lane], v);
        if (lo8) fma8(b, x4[32 + lane], v);
    }
    // sigmoid + pack; group1 features all < 256 < 300
    __half2 h0 = __floats2half2_rn(1.0f/(1.0f+__expf(-a[0])), 1.0f/(1.0f+__expf(-a[1])));
    __half2 h1 = __floats2half2_rn(1.0f/(1.0f+__expf(-a[2])), 1.0f/(1.0f+__expf(-a[3])));
    __half2 h2 = __floats2half2_rn(1.0f/(1.0f+__expf(-a[4])), 1.0f/(1.0f+__expf(-a[5])));
    __half2 h3 = __floats2half2_rn(1.0f/(1.0f+__expf(-a[6])), 1.0f/(1.0f+__expf(-a[7])));
    uint4 pk;
    pk.x = *reinterpret_cast<uint32_t*>(&h0);
    pk.y = *reinterpret_cast<uint32_t*>(&h1);
    pk.z = *reinterpret_cast<uint32_t*>(&h2);
    pk.w = *reinterpret_cast<uint32_t*>(&h3);
    __stcs(reinterpret_cast<uint4*>(O + (size_t)warp * AP) + lane, pk);
    if (lo8) {
        int fb = 256 + lane * 8;
        float o[8];
#pragma unroll
        for (int t = 0; t < 8; t++)
            o[t] = (fb + t < EMB) ? 1.0f/(1.0f+__expf(-b[t])) : 0.0f;
        h0 = __floats2half2_rn(o[0], o[1]);
        h1 = __floats2half2_rn(o[2], o[3]);
        h2 = __floats2half2_rn(o[4], o[5]);
        h3 = __floats2half2_rn(o[6], o[7]);
        pk.x = *reinterpret_cast<uint32_t*>(&h0);
        pk.y = *reinterpret_cast<uint32_t*>(&h1);
        pk.z = *reinterpret_cast<uint32_t*>(&h2);
        pk.w = *reinterpret_cast<uint32_t*>(&h3);
        __stcs(reinterpret_cast<uint4*>(O + (size_t)warp * AP) + 32 + lane, pk);
    }
}

// build fc = concat(H2[node], input) -> fp16 [BATCH, FCP]
__global__ void fc_build_f16_kernel(const __half* __restrict__ H2,
                                    const int* __restrict__ node,
                                    const float* __restrict__ input) {
    int idx = blockIdx.x * blockDim.x + threadIdx.x;
    if (idx >= BATCH * FCK) return;
    int b = idx / FCK;
    int j = idx - b * FCK;
    __half v;
    if (j < EMB) {
        size_t n = (size_t)node[b];
        v = H2[n * AP + j];
    } else {
        v = __float2half_rn(input[(size_t)b * IN_DIM + (j - EMB)]);
    }
    g_fcf16[(size_t)b * FCP + j] = v;
}

// final layer
__global__ void final_kernel(const float* __restrict__ h,
                             const float* __restrict__ Wc,
                             const float* __restrict__ bc,
                             float* __restrict__ out) {
    int warp = (blockIdx.x * blockDim.x + threadIdx.x) >> 5;
    int lane = threadIdx.x & 31;
    if (warp >= BATCH) return;
    const float* hr = h + (size_t)warp * HID;
    float a0 = 0.f, a1 = 0.f;
    for (int k = lane; k < HID; k += 32) {
        float hv = hr[k];
        a0 += hv * Wc[k * 2 + 0];
        a1 += hv * Wc[k * 2 + 1];
    }
#pragma unroll
    for (int o = 16; o > 0; o >>= 1) {
        a0 += __shfl_down_sync(0xFFFFFFFFu, a0, o);
        a1 += __shfl_down_sync(0xFFFFFFFFu, a1, o);
    }
    if (lane == 0) {
        out[warp * 2 + 0] = a0 + bc[0];
        out[warp * 2 + 1] = a1 + bc[1];
    }
}

// ================= host launch =================
extern "C" void kernel_launch(void* const* d_in, const int* in_sizes, int n_in,
                              void* d_out, int out_size) {
    const float* input = (const float*)d_in[0];
    const int*   node  = (const int*)d_in[1];
    const int*   erow  = (const int*)d_in[2];
    const int*   ecol  = (const int*)d_in[3];
    const float* H0    = (const float*)d_in[4];
    const float* W1    = (const float*)d_in[5];
    const float* W2    = (const float*)d_in[6];
    const float* Wa    = (const float*)d_in[7];
    const float* ba    = (const float*)d_in[8];
    const float* Wb    = (const float*)d_in[9];
    const float* bb    = (const float*)d_in[10];
    const float* Wc    = (const float*)d_in[11];
    const float* bc    = (const float*)d_in[12];
    float*       out   = (float*)d_out;

    void *p_cnt, *p_cursor, *p_h2;
    void *p_act, *p_x16, *p_w1t, *p_w2t, *p_fcf16, *p_wat, *p_wbt, *p_h1f16;
    cudaGetSymbolAddress(&p_cnt,    g_cnt);
    cudaGetSymbolAddress(&p_cursor, g_cursor);
    cudaGetSymbolAddress(&p_h2,     g_h2);
    cudaGetSymbolAddress(&p_act,    g_act);
    cudaGetSymbolAddress(&p_x16,    g_x16);
    cudaGetSymbolAddress(&p_w1t,    g_w1t);
    cudaGetSymbolAddress(&p_w2t,    g_w2t);
    cudaGetSymbolAddress(&p_fcf16,  g_fcf16);
    cudaGetSymbolAddress(&p_wat,    g_wat);
    cudaGetSymbolAddress(&p_wbt,    g_wbt);
    cudaGetSymbolAddress(&p_h1f16,  g_h1f16);

    float* h2 = (float*)p_h2;

    cudaFuncSetAttribute(gemm_f16_kernel,
                         cudaFuncAttributeMaxDynamicSharedMemorySize, GS_TOTAL);

    static cudaStream_t s2 = nullptr;
    static cudaEvent_t evF = nullptr, evJ = nullptr;
    if (!s2) {
        cudaStreamCreateWithFlags(&s2, cudaStreamNonBlocking);
        cudaEventCreateWithFlags(&evF, cudaEventDisableTiming);
        cudaEventCreateWithFlags(&evJ, cudaEventDisableTiming);
    }

    const int TPB = 256;

    // ---- fork: CSR build chain on s2 ----
    cudaEventRecord(evF, 0);
    cudaStreamWaitEvent(s2, evF, 0);
    zero_int_kernel<<<(NV + TPB - 1) / TPB, TPB, 0, s2>>>((int*)p_cnt, NV);
    zero_int_kernel<<<(NV + TPB - 1) / TPB, TPB, 0, s2>>>((int*)p_cursor, NV);
    count_kernel<<<(NE + TPB - 1) / TPB, TPB, 0, s2>>>(erow);
    vals_kernel<<<(NE + TPB - 1) / TPB, TPB, 0, s2>>>(erow, ecol);
    scanA_kernel<<<NBLK_SCAN, 1024, 0, s2>>>();
    scanB_kernel<<<1, 128, 0, s2>>>();
    scanC_kernel<<<(NV + TPB - 1) / TPB, TPB, 0, s2>>>();
    scatter_kernel<<<(NE + TPB - 1) / TPB, TPB, 0, s2>>>(erow, ecol);
    cudaEventRecord(evJ, s2);

    // ---- main stream: prepare fp16 operands ----
    pre_act_f16_kernel<<<(NV * 75 + TPB - 1) / TPB, TPB>>>(H0);
    pre_wT_kernel<<<(EMB * EMB + TPB - 1) / TPB, TPB>>>(W1, EMB, EMB, AP, (__half*)p_w1t);
    pre_wT_kernel<<<(EMB * EMB + TPB - 1) / TPB, TPB>>>(W2, EMB, EMB, AP, (__half*)p_w2t);
    pre_wT_kernel<<<(FCK * HID + TPB - 1) / TPB, TPB>>>(Wa, FCK, HID, FCP, (__half*)p_wat);
    pre_wT_kernel<<<(HID * HID + TPB - 1) / TPB, TPB>>>(Wb, HID, HID, HP, (__half*)p_wbt);

    // ---- GCN layer 1 ----
    dim3 gbig(2, (NV + 127) / 128);
    gemm_f16_kernel<<<gbig, 512, GS_TOTAL>>>(
        (__half*)p_act, AP, (__half*)p_w1t, AP,
        nullptr, 0, (__half*)p_x16, AP, nullptr, NV, EMB, AP, 3);

    cudaStreamWaitEvent(0, evJ, 0);
    int spmmBlocks = (NV * 32 + TPB - 1) / TPB;
    spmm_f16_kernel<<<spmmBlocks, TPB>>>((__half*)p_x16, (__half*)p_act);

    // ---- GCN layer 2 ----
    gemm_f16_kernel<<<gbig, 512, GS_TOTAL>>>(
        (__half*)p_act, AP, (__half*)p_w2t, AP,
        nullptr, 0, (__half*)p_x16, AP, nullptr, NV, EMB, AP, 3);
    spmm_f16_kernel<<<spmmBlocks, TPB>>>((__half*)p_x16, (__half*)p_act);

    // ---- MLP head ----
    fc_build_f16_kernel<<<(BATCH * FCK + TPB - 1) / TPB, TPB>>>(
        (__half*)p_act, node, input);

    dim3 gmlp(4, BATCH / 128);   // N=500 -> 4 col blocks of 160
    gemm_f16_kernel<<<gmlp, 512, GS_TOTAL>>>(
        (__half*)p_fcf16, FCP, (__half*)p_wat, FCP,
        nullptr, 0, (__half*)p_h1f16, HP, ba, BATCH, HID, FCP, 2);
    gemm_f16_kernel<<<gmlp, 512, GS_TOTAL>>>(
        (__half*)p_h1f16, HP, (__half*)p_wbt, HP,
        h2, HID, nullptr, 0, bb, BATCH, HID, HP, 1);

    final_kernel<<<(BATCH * 32 + TPB - 1) / TPB, TPB>>>(h2, Wc, bc, out);
}

// round 9
// speedup vs baseline: 6.2204x; 1.6646x over previous
#include <cuda_runtime.h>
#include <cuda_fp16.h>
#include <math.h>
#include <cstdint>

#define NV 117000
#define NE 468000
#define EMB 300
#define IN_DIM 768
#define BATCH 4096
#define HID 500
#define FCK (EMB + IN_DIM)   // 1068
#define NBLK_SCAN ((NV + 1023) / 1024)   // 115
#define AP 320               // padded fp16 stride for GCN activations/weights
#define FCP 1088             // padded fc width
#define HP 512               // padded hidden width
#define BNROWS 640           // padded N-rows for transposed MLP weights

// ---------------- device scratch (allocation-free, zero-initialized) -------
__device__ float g_vals[NE];
__device__ int   g_cnt[NV];
__device__ int   g_rowstart[NV + 1];
__device__ int   g_tot[256];
__device__ int   g_cursor[NV];
__device__ int   g_scol[NE];
__device__ float g_sval[NE];
__device__ float g_h2[BATCH * HID];
// frontier machinery
__device__ int   g_fnode[NV];    // flags: rows in nodeset
__device__ int   g_f1[NV];       // flags: 1-hop rows (S1)
__device__ int   g_list1[NV];    // compacted S1
__device__ int   g_list2[NV];    // compacted nodeset
__device__ int   g_n1;
__device__ int   g_n2;
// fp16 buffers (pads stay statically zero — never written)
__device__ __half g_act[(size_t)NV * AP];           // activations ping
__device__ __half g_x16[(size_t)NV * AP];           // GEMM output pong
__device__ __half g_w1t[AP * AP];
__device__ __half g_w2t[AP * AP];
__device__ __half g_fcf16[(size_t)BATCH * FCP];
__device__ __half g_wat[(size_t)BNROWS * FCP];
__device__ __half g_wbt[(size_t)BNROWS * HP];
__device__ __half g_h1f16[(size_t)BATCH * HP];

// ================= helpers =================
__device__ __forceinline__ void mma16816(float* c, const uint32_t* a, const uint32_t* b) {
    asm volatile(
        "mma.sync.aligned.m16n8k16.row.col.f32.f16.f16.f32 "
        "{%0,%1,%2,%3}, {%4,%5,%6,%7}, {%8,%9}, {%0,%1,%2,%3};"
        : "+f"(c[0]), "+f"(c[1]), "+f"(c[2]), "+f"(c[3])
        : "r"(a[0]), "r"(a[1]), "r"(a[2]), "r"(a[3]),
          "r"(b[0]), "r"(b[1]));
}

__device__ __forceinline__ uint32_t cvta_shared_u32(const void* p) {
    uint32_t a;
    asm("{ .reg .u64 t; cvta.to.shared.u64 t, %1; cvt.u32.u64 %0, t; }"
        : "=r"(a) : "l"(p));
    return a;
}

__device__ __forceinline__ void cp_async16(uint32_t dst, const void* src) {
    asm volatile("cp.async.ca.shared.global [%0], [%1], 16;" :: "r"(dst), "l"(src));
}
__device__ __forceinline__ void cp_commit() {
    asm volatile("cp.async.commit_group;");
}
__device__ __forceinline__ void cp_wait0() {
    asm volatile("cp.async.wait_group 0;");
}

// ================= prep kernels =================
__global__ void pre_act_f16_kernel(const float* __restrict__ X) {
    int idx = blockIdx.x * blockDim.x + threadIdx.x;
    if (idx >= NV * 75) return;
    int r = idx / 75;
    int q = idx - r * 75;
    float4 v = reinterpret_cast<const float4*>(X)[(size_t)r * 75 + q];
    __half2 p0 = __floats2half2_rn(v.x, v.y);
    __half2 p1 = __floats2half2_rn(v.z, v.w);
    uint2 pk = make_uint2(*reinterpret_cast<uint32_t*>(&p0),
                          *reinterpret_cast<uint32_t*>(&p1));
    *reinterpret_cast<uint2*>(&g_act[(size_t)r * AP + q * 4]) = pk;
}

__global__ void pre_wT_kernel(const float* __restrict__ W, int K, int N, int ldo,
                              __half* __restrict__ t16) {
    int idx = blockIdx.x * blockDim.x + threadIdx.x;
    if (idx >= K * N) return;
    int k = idx / N;
    int n = idx - k * N;
    t16[(size_t)n * ldo + k] = __float2half_rn(W[idx]);
}

// ================= frontier kernels =================
__global__ void zero_int_kernel(int* p, int n) {
    int i = blockIdx.x * blockDim.x + threadIdx.x;
    if (i < n) p[i] = 0;
}

__global__ void zero_ctr_kernel() { g_n1 = 0; g_n2 = 0; }

__global__ void mark_node_kernel(const int* __restrict__ node) {
    int i = blockIdx.x * blockDim.x + threadIdx.x;
    if (i < BATCH) g_fnode[node[i]] = 1;
}

__global__ void mark_1hop_kernel(const int* __restrict__ erow,
                                 const int* __restrict__ ecol) {
    int e = blockIdx.x * blockDim.x + threadIdx.x;
    if (e >= NE) return;
    if (g_fnode[erow[e]]) g_f1[ecol[e]] = 1;
}

__global__ void compact_kernel(const int* __restrict__ flags,
                               int* __restrict__ list, int* __restrict__ ctr) {
    int i = blockIdx.x * blockDim.x + threadIdx.x;
    if (i < NV && flags[i]) {
        int p = atomicAdd(ctr, 1);
        list[p] = i;
    }
}

// ================= pipelined fp16 tensor-core GEMM ==========================
// C[M,N] = A[rows, K] @ B[K,N]; optional rowlist/pcount select A rows (output
// scattered to the same original indices). BM=128, BN=160, BK=32, 512 thr.
// mode 0: fp32 store  1: bias+sig fp32  2: bias+sig fp16  3: plain fp16
#define GS_ABUF 10240
#define GS_BBUF 12800
#define GS_BOFF (2 * GS_ABUF)                  // 20480
#define GS_TOTAL (GS_BOFF + 2 * GS_BBUF)       // 46080 dynamic

__global__ void __launch_bounds__(512)
gemm_f16_kernel(const __half* __restrict__ a16, int lda,
                const __half* __restrict__ bt, int ldb,
                float* __restrict__ C, int ldc,
                __half* __restrict__ o16, int ldo,
                const float* __restrict__ bias,
                const int* __restrict__ rowlist, const int* __restrict__ pcount,
                int M, int N, int K, int mode) {
    extern __shared__ __align__(16) char sm[];
    __shared__ int rows_sm[128];

    int cnt = pcount ? *pcount : M;
    int bm = blockIdx.y * 128;
    if (bm >= cnt) return;

    int tid = threadIdx.x;
    if (tid < 128) {
        int gi = bm + tid;
        if (gi > cnt - 1) gi = cnt - 1;
        rows_sm[tid] = rowlist ? rowlist[gi] : gi;
    }
    __syncthreads();

    int w = tid >> 5;
    int lane = tid & 31;
    int g = lane >> 2;
    int t2 = (lane & 3) * 2;

    int bn = blockIdx.x * 160;
    int m0 = (w & 3) * 32;
    int n0 = (w >> 2) * 40;
    int nch = K >> 5;

    float acc[2][5][4];
#pragma unroll
    for (int i = 0; i < 2; i++)
#pragma unroll
        for (int j = 0; j < 5; j++)
#pragma unroll
            for (int q = 0; q < 4; q++) acc[i][j][q] = 0.0f;

    auto prefetch = [&](int ch, int buf) {
        int k0 = ch * 32;
        {   // A: 128 rows x 32 fp16 = 512 x 16B, 1/thread
            int r = tid >> 2;
            int c = tid & 3;
            size_t so = (size_t)rows_sm[r] * lda + k0 + c * 8;
            uint32_t d = cvta_shared_u32(sm + buf * GS_ABUF + (r * 40 + c * 8) * 2);
            cp_async16(d, a16 + so);
        }
#pragma unroll
        for (int it = 0; it < 2; it++) {  // B: 160 rows x 32 fp16 = 640 x 16B
            int idx = tid + it * 512;
            if (idx < 640) {
                int r = idx >> 2;
                int c = idx & 3;
                size_t so = (size_t)(bn + r) * ldb + k0 + c * 8;
                uint32_t d = cvta_shared_u32(sm + GS_BOFF + buf * GS_BBUF +
                                             (r * 40 + c * 8) * 2);
                cp_async16(d, bt + so);
            }
        }
    };

    prefetch(0, 0);
    cp_commit();

    for (int ch = 0; ch < nch; ch++) {
        int buf = ch & 1;
        cp_wait0();
        __syncthreads();
        if (ch < nch - 1) {
            prefetch(ch + 1, buf ^ 1);
            cp_commit();
        }
        const __half* Af = reinterpret_cast<const __half*>(sm + buf * GS_ABUF);
        const __half* Bf = reinterpret_cast<const __half*>(sm + GS_BOFF + buf * GS_BBUF);

#pragma unroll
        for (int kc = 0; kc < 32; kc += 16) {
            uint32_t af[2][4];
#pragma unroll
            for (int i = 0; i < 2; i++) {
                int rm = m0 + i * 16;
                af[i][0] = *reinterpret_cast<const uint32_t*>(&Af[(rm + g)     * 40 + kc + t2]);
                af[i][1] = *reinterpret_cast<const uint32_t*>(&Af[(rm + g + 8) * 40 + kc + t2]);
                af[i][2] = *reinterpret_cast<const uint32_t*>(&Af[(rm + g)     * 40 + kc + t2 + 8]);
                af[i][3] = *reinterpret_cast<const uint32_t*>(&Af[(rm + g + 8) * 40 + kc + t2 + 8]);
            }
#pragma unroll
            for (int j = 0; j < 5; j++) {
                int rn = n0 + j * 8;
                uint32_t bf[2];
                bf[0] = *reinterpret_cast<const uint32_t*>(&Bf[(rn + g) * 40 + kc + t2]);
                bf[1] = *reinterpret_cast<const uint32_t*>(&Bf[(rn + g) * 40 + kc + t2 + 8]);
#pragma unroll
                for (int i = 0; i < 2; i++)
                    mma16816(acc[i][j], af[i], bf);
            }
        }
        __syncthreads();
    }

    // ---- epilogue ----
#pragma unroll
    for (int i = 0; i < 2; i++) {
#pragma unroll
        for (int j = 0; j < 5; j++) {
            int gn = bn + n0 + j * 8 + t2;
            if (gn >= N) continue;      // N even, gn even -> gn+1 safe
#pragma unroll
            for (int half = 0; half < 2; half++) {
                int gm = bm + m0 + i * 16 + g + half * 8;
                if (gm >= cnt) continue;
                int gr = rows_sm[gm - bm];
                float2 o;
                o.x = acc[i][j][half * 2 + 0];
                o.y = acc[i][j][half * 2 + 1];
                if (mode == 1 || mode == 2) {
                    o.x += bias[gn];
                    o.y += bias[gn + 1];
                    o.x = 1.0f / (1.0f + __expf(-o.x));
                    o.y = 1.0f / (1.0f + __expf(-o.y));
                }
                if (mode >= 2) {
                    __half2 hv = __floats2half2_rn(o.x, o.y);
                    *reinterpret_cast<uint32_t*>(&o16[(size_t)gr * ldo + gn]) =
                        *reinterpret_cast<uint32_t*>(&hv);
                } else {
                    *reinterpret_cast<float2*>(C + (size_t)gr * ldc + gn) = o;
                }
            }
        }
    }
}

// ================= graph preprocessing =================
__global__ void count_kernel(const int* __restrict__ erow) {
    int e = blockIdx.x * blockDim.x + threadIdx.x;
    if (e < NE) atomicAdd(&g_cnt[erow[e]], 1);
}

__global__ void vals_kernel(const int* __restrict__ erow, const int* __restrict__ ecol) {
    int e = blockIdx.x * blockDim.x + threadIdx.x;
    if (e >= NE) return;
    int dr = g_cnt[erow[e]];
    int dc = g_cnt[ecol[e]];
    float a = (dr > 0) ? rsqrtf((float)dr) : 0.0f;
    float b = (dc > 0) ? rsqrtf((float)dc) : 0.0f;
    g_vals[e] = a * b;
}

__global__ void scanA_kernel() {
    __shared__ int s[1024];
    int i = blockIdx.x * 1024 + threadIdx.x;
    int v = (i < NV) ? g_cnt[i] : 0;
    s[threadIdx.x] = v;
    __syncthreads();
    for (int o = 1; o < 1024; o <<= 1) {
        int t = 0;
        if (threadIdx.x >= o) t = s[threadIdx.x - o];
        __syncthreads();
        if (threadIdx.x >= o) s[threadIdx.x] += t;
        __syncthreads();
    }
    if (i < NV) g_rowstart[i] = s[threadIdx.x] - v;
    if (threadIdx.x == 1023) g_tot[blockIdx.x] = s[1023];
}

__global__ void scanB_kernel() {
    __shared__ int s[128];
    int v = (threadIdx.x < NBLK_SCAN) ? g_tot[threadIdx.x] : 0;
    s[threadIdx.x] = v;
    __syncthreads();
    for (int o = 1; o < 128; o <<= 1) {
        int t = 0;
        if (threadIdx.x >= o) t = s[threadIdx.x - o];
        __syncthreads();
        if (threadIdx.x >= o) s[threadIdx.x] += t;
        __syncthreads();
    }
    if (threadIdx.x < NBLK_SCAN) g_tot[threadIdx.x] = s[threadIdx.x] - v;
}

__global__ void scanC_kernel() {
    int i = blockIdx.x * blockDim.x + threadIdx.x;
    if (i < NV) g_rowstart[i] += g_tot[i >> 10];
    if (i == 0) g_rowstart[NV] = NE;
}

__global__ void scatter_kernel(const int* __restrict__ erow, const int* __restrict__ ecol) {
    int e = blockIdx.x * blockDim.x + threadIdx.x;
    if (e >= NE) return;
    int r = erow[e];
    int pos = g_rowstart[r] + atomicAdd(&g_cursor[r], 1);
    g_scol[pos] = ecol[e];
    g_sval[pos] = g_vals[e];
}

// ================= fp16 pull SpMM + fused sigmoid (row-list) ================
__device__ __forceinline__ void fma8(float* acc, uint4 t, float v) {
    __half2 p;
    float2 f;
    *reinterpret_cast<uint32_t*>(&p) = t.x; f = __half22float2(p);
    acc[0] += v * f.x; acc[1] += v * f.y;
    *reinterpret_cast<uint32_t*>(&p) = t.y; f = __half22float2(p);
    acc[2] += v * f.x; acc[3] += v * f.y;
    *reinterpret_cast<uint32_t*>(&p) = t.z; f = __half22float2(p);
    acc[4] += v * f.x; acc[5] += v * f.y;
    *reinterpret_cast<uint32_t*>(&p) = t.w; f = __half22float2(p);
    acc[6] += v * f.x; acc[7] += v * f.y;
}

__global__ void spmm_f16_kernel(const __half* __restrict__ X, __half* __restrict__ O,
                                const int* __restrict__ rowlist,
                                const int* __restrict__ pcount) {
    int widx = (blockIdx.x * blockDim.x + threadIdx.x) >> 5;
    int lane = threadIdx.x & 31;
    int cnt = *pcount;
    if (widx >= cnt) return;
    int row = rowlist[widx];
    int s = g_rowstart[row];
    int e = g_rowstart[row + 1];
    bool lo8 = lane < 8;
    float a[8] = {0,0,0,0,0,0,0,0};
    float b[8] = {0,0,0,0,0,0,0,0};
    int j = s;
    for (; j + 1 < e; j += 2) {
        int c0 = g_scol[j];
        float v0 = g_sval[j];
        int c1 = g_scol[j + 1];
        float v1 = g_sval[j + 1];
        const uint4* x0 = reinterpret_cast<const uint4*>(X + (size_t)c0 * AP);
        const uint4* x1 = reinterpret_cast<const uint4*>(X + (size_t)c1 * AP);
        uint4 t0 = x0[lane];
        uint4 t1 = x1[lane];
        fma8(a, t0, v0);
        fma8(a, t1, v1);
        if (lo8) {
            uint4 s0 = x0[32 + lane];
            uint4 s1 = x1[32 + lane];
            fma8(b, s0, v0);
            fma8(b, s1, v1);
        }
    }
    if (j < e) {
        int c = g_scol[j];
        float v = g_sval[j];
        const uint4* x4 = reinterpret_cast<const uint4*>(X + (size_t)c * AP);
        fma8(a, x4[lane], v);
        if (lo8) fma8(b, x4[32 + lane], v);
    }
    __half2 h0 = __floats2half2_rn(1.0f/(1.0f+__expf(-a[0])), 1.0f/(1.0f+__expf(-a[1])));
    __half2 h1 = __floats2half2_rn(1.0f/(1.0f+__expf(-a[2])), 1.0f/(1.0f+__expf(-a[3])));
    __half2 h2 = __floats2half2_rn(1.0f/(1.0f+__expf(-a[4])), 1.0f/(1.0f+__expf(-a[5])));
    __half2 h3 = __floats2half2_rn(1.0f/(1.0f+__expf(-a[6])), 1.0f/(1.0f+__expf(-a[7])));
    uint4 pk;
    pk.x = *reinterpret_cast<uint32_t*>(&h0);
    pk.y = *reinterpret_cast<uint32_t*>(&h1);
    pk.z = *reinterpret_cast<uint32_t*>(&h2);
    pk.w = *reinterpret_cast<uint32_t*>(&h3);
    __stcs(reinterpret_cast<uint4*>(O + (size_t)row * AP) + lane, pk);
    if (lo8) {
        int fb = 256 + lane * 8;
        float o[8];
#pragma unroll
        for (int t = 0; t < 8; t++)
            o[t] = (fb + t < EMB) ? 1.0f/(1.0f+__expf(-b[t])) : 0.0f;
        h0 = __floats2half2_rn(o[0], o[1]);
        h1 = __floats2half2_rn(o[2], o[3]);
        h2 = __floats2half2_rn(o[4], o[5]);
        h3 = __floats2half2_rn(o[6], o[7]);
        pk.x = *reinterpret_cast<uint32_t*>(&h0);
        pk.y = *reinterpret_cast<uint32_t*>(&h1);
        pk.z = *reinterpret_cast<uint32_t*>(&h2);
        pk.w = *reinterpret_cast<uint32_t*>(&h3);
        __stcs(reinterpret_cast<uint4*>(O + (size_t)row * AP) + 32 + lane, pk);
    }
}

// build fc = concat(H2[node], input) -> fp16 [BATCH, FCP]
__global__ void fc_build_f16_kernel(const __half* __restrict__ H2,
                                    const int* __restrict__ node,
                                    const float* __restrict__ input) {
    int idx = blockIdx.x * blockDim.x + threadIdx.x;
    if (idx >= BATCH * FCK) return;
    int b = idx / FCK;
    int j = idx - b * FCK;
    __half v;
    if (j < EMB) {
        size_t n = (size_t)node[b];
        v = H2[n * AP + j];
    } else {
        v = __float2half_rn(input[(size_t)b * IN_DIM + (j - EMB)]);
    }
    g_fcf16[(size_t)b * FCP + j] = v;
}

// final layer
__global__ void final_kernel(const float* __restrict__ h,
                             const float* __restrict__ Wc,
                             const float* __restrict__ bc,
                             float* __restrict__ out) {
    int warp = (blockIdx.x * blockDim.x + threadIdx.x) >> 5;
    int lane = threadIdx.x & 31;
    if (warp >= BATCH) return;
    const float* hr = h + (size_t)warp * HID;
    float a0 = 0.f, a1 = 0.f;
    for (int k = lane; k < HID; k += 32) {
        float hv = hr[k];
        a0 += hv * Wc[k * 2 + 0];
        a1 += hv * Wc[k * 2 + 1];
    }
#pragma unroll
    for (int o = 16; o > 0; o >>= 1) {
        a0 += __shfl_down_sync(0xFFFFFFFFu, a0, o);
        a1 += __shfl_down_sync(0xFFFFFFFFu, a1, o);
    }
    if (lane == 0) {
        out[warp * 2 + 0] = a0 + bc[0];
        out[warp * 2 + 1] = a1 + bc[1];
    }
}

// ================= host launch =================
extern "C" void kernel_launch(void* const* d_in, const int* in_sizes, int n_in,
                              void* d_out, int out_size) {
    const float* input = (const float*)d_in[0];
    const int*   node  = (const int*)d_in[1];
    const int*   erow  = (const int*)d_in[2];
    const int*   ecol  = (const int*)d_in[3];
    const float* H0    = (const float*)d_in[4];
    const float* W1    = (const float*)d_in[5];
    const float* W2    = (const float*)d_in[6];
    const float* Wa    = (const float*)d_in[7];
    const float* ba    = (const float*)d_in[8];
    const float* Wb    = (const float*)d_in[9];
    const float* bb    = (const float*)d_in[10];
    const float* Wc    = (const float*)d_in[11];
    const float* bc    = (const float*)d_in[12];
    float*       out   = (float*)d_out;

    void *p_cnt, *p_cursor, *p_h2;
    void *p_act, *p_x16, *p_w1t, *p_w2t, *p_fcf16, *p_wat, *p_wbt, *p_h1f16;
    void *p_fnode, *p_f1, *p_list1, *p_list2, *p_n1, *p_n2;
    cudaGetSymbolAddress(&p_cnt,    g_cnt);
    cudaGetSymbolAddress(&p_cursor, g_cursor);
    cudaGetSymbolAddress(&p_h2,     g_h2);
    cudaGetSymbolAddress(&p_act,    g_act);
    cudaGetSymbolAddress(&p_x16,    g_x16);
    cudaGetSymbolAddress(&p_w1t,    g_w1t);
    cudaGetSymbolAddress(&p_w2t,    g_w2t);
    cudaGetSymbolAddress(&p_fcf16,  g_fcf16);
    cudaGetSymbolAddress(&p_wat,    g_wat);
    cudaGetSymbolAddress(&p_wbt,    g_wbt);
    cudaGetSymbolAddress(&p_h1f16,  g_h1f16);
    cudaGetSymbolAddress(&p_fnode,  g_fnode);
    cudaGetSymbolAddress(&p_f1,     g_f1);
    cudaGetSymbolAddress(&p_list1,  g_list1);
    cudaGetSymbolAddress(&p_list2,  g_list2);
    cudaGetSymbolAddress(&p_n1,     g_n1);
    cudaGetSymbolAddress(&p_n2,     g_n2);

    float* h2 = (float*)p_h2;

    cudaFuncSetAttribute(gemm_f16_kernel,
                         cudaFuncAttributeMaxDynamicSharedMemorySize, GS_TOTAL);

    static cudaStream_t s2 = nullptr;
    static cudaEvent_t evF = nullptr, evJ = nullptr;
    if (!s2) {
        cudaStreamCreateWithFlags(&s2, cudaStreamNonBlocking);
        cudaEventCreateWithFlags(&evF, cudaEventDisableTiming);
        cudaEventCreateWithFlags(&evJ, cudaEventDisableTiming);
    }

    const int TPB = 256;
    const int nvBlocks = (NV + TPB - 1) / TPB;
    const int neBlocks = (NE + TPB - 1) / TPB;

    // ---- fork: CSR build + frontier construction on s2 ----
    cudaEventRecord(evF, 0);
    cudaStreamWaitEvent(s2, evF, 0);
    zero_int_kernel<<<nvBlocks, TPB, 0, s2>>>((int*)p_cnt, NV);
    zero_int_kernel<<<nvBlocks, TPB, 0, s2>>>((int*)p_cursor, NV);
    zero_int_kernel<<<nvBlocks, TPB, 0, s2>>>((int*)p_fnode, NV);
    zero_int_kernel<<<nvBlocks, TPB, 0, s2>>>((int*)p_f1, NV);
    zero_ctr_kernel<<<1, 1, 0, s2>>>();
    mark_node_kernel<<<(BATCH + TPB - 1) / TPB, TPB, 0, s2>>>(node);
    mark_1hop_kernel<<<neBlocks, TPB, 0, s2>>>(erow, ecol);
    compact_kernel<<<nvBlocks, TPB, 0, s2>>>((int*)p_f1, (int*)p_list1, (int*)p_n1);
    compact_kernel<<<nvBlocks, TPB, 0, s2>>>((int*)p_fnode, (int*)p_list2, (int*)p_n2);
    count_kernel<<<neBlocks, TPB, 0, s2>>>(erow);
    vals_kernel<<<neBlocks, TPB, 0, s2>>>(erow, ecol);
    scanA_kernel<<<NBLK_SCAN, 1024, 0, s2>>>();
    scanB_kernel<<<1, 128, 0, s2>>>();
    scanC_kernel<<<nvBlocks, TPB, 0, s2>>>();
    scatter_kernel<<<neBlocks, TPB, 0, s2>>>(erow, ecol);
    cudaEventRecord(evJ, s2);

    // ---- main stream: prepare fp16 operands ----
    pre_act_f16_kernel<<<(NV * 75 + TPB - 1) / TPB, TPB>>>(H0);
    pre_wT_kernel<<<(EMB * EMB + TPB - 1) / TPB, TPB>>>(W1, EMB, EMB, AP, (__half*)p_w1t);
    pre_wT_kernel<<<(EMB * EMB + TPB - 1) / TPB, TPB>>>(W2, EMB, EMB, AP, (__half*)p_w2t);
    pre_wT_kernel<<<(FCK * HID + TPB - 1) / TPB, TPB>>>(Wa, FCK, HID, FCP, (__half*)p_wat);
    pre_wT_kernel<<<(HID * HID + TPB - 1) / TPB, TPB>>>(Wb, HID, HID, HP, (__half*)p_wbt);

    // ---- GCN layer 1 GEMM (all rows) ----
    dim3 gbig(2, (NV + 127) / 128);
    gemm_f16_kernel<<<gbig, 512, GS_TOTAL>>>(
        (__half*)p_act, AP, (__half*)p_w1t, AP,
        nullptr, 0, (__half*)p_x16, AP, nullptr,
        nullptr, nullptr, NV, EMB, AP, 3);

    // ---- join CSR+frontier, then SpMM 1 on S1 rows only ----
    cudaStreamWaitEvent(0, evJ, 0);
    int spmmBlocks = (NV * 32 + TPB - 1) / TPB;
    spmm_f16_kernel<<<spmmBlocks, TPB>>>((__half*)p_x16, (__half*)p_act,
                                         (int*)p_list1, (int*)p_n1);

    // ---- GCN layer 2 GEMM on S1 rows only ----
    gemm_f16_kernel<<<gbig, 512, GS_TOTAL>>>(
        (__half*)p_act, AP, (__half*)p_w2t, AP,
        nullptr, 0, (__half*)p_x16, AP, nullptr,
        (int*)p_list1, (int*)p_n1, NV, EMB, AP, 3);

    // ---- SpMM 2 on nodeset rows only ----
    int spmm2Blocks = (BATCH * 32 + TPB - 1) / TPB;
    spmm_f16_kernel<<<spmm2Blocks, TPB>>>((__half*)p_x16, (__half*)p_act,
                                          (int*)p_list2, (int*)p_n2);

    // ---- MLP head ----
    fc_build_f16_kernel<<<(BATCH * FCK + TPB - 1) / TPB, TPB>>>(
        (__half*)p_act, node, input);

    dim3 gmlp(4, BATCH / 128);
    gemm_f16_kernel<<<gmlp, 512, GS_TOTAL>>>(
        (__half*)p_fcf16, FCP, (__half*)p_wat, FCP,
        nullptr, 0, (__half*)p_h1f16, HP, ba,
        nullptr, nullptr, BATCH, HID, FCP, 2);
    gemm_f16_kernel<<<gmlp, 512, GS_TOTAL>>>(
        (__half*)p_h1f16, HP, (__half*)p_wbt, HP,
        h2, HID, nullptr, 0, bb,
        nullptr, nullptr, BATCH, HID, HP, 1);

    final_kernel<<<(BATCH * 32 + TPB - 1) / TPB, TPB>>>(h2, Wc, bc, out);
}

// round 10
// speedup vs baseline: 8.2757x; 1.3304x over previous
#include <cuda_runtime.h>
#include <cuda_fp16.h>
#include <math.h>
#include <cstdint>

#define NV 117000
#define NE 468000
#define EMB 300
#define IN_DIM 768
#define BATCH 4096
#define HID 500
#define FCK (EMB + IN_DIM)   // 1068
#define NBLK_SCAN ((NV + 1023) / 1024)   // 115
#define AP 320               // padded fp16 stride for GCN activations/weights
#define FCP 1088             // padded fc width
#define HP 512               // padded hidden width
#define BNROWS 640           // padded N-rows for transposed MLP weights

// ---------------- device scratch (allocation-free, zero-initialized) -------
__device__ float g_vals[NE];
__device__ int   g_cnt[NV];
__device__ int   g_rowstart[NV + 1];
__device__ int   g_tot[256];
__device__ int   g_cursor[NV];
__device__ int   g_scol[NE];
__device__ float g_sval[NE];
__device__ float g_h2[BATCH * HID];
// frontier machinery
__device__ int   g_fnode[NV];    // flags: nodeset
__device__ int   g_f1[NV];       // flags: S1 (1-hop)
__device__ int   g_f2[NV];       // flags: S2 (2-hop)
__device__ int   g_list1[NV];    // compacted S1
__device__ int   g_list2[NV];    // compacted nodeset
__device__ int   g_list3[NV];    // compacted S2
__device__ int   g_n1;
__device__ int   g_n2;
__device__ int   g_n3;
// fp16 buffers (pads stay statically zero — never written)
__device__ __half g_act[(size_t)NV * AP];           // activations ping
__device__ __half g_x16[(size_t)NV * AP];           // GEMM output pong
__device__ __half g_w1t[AP * AP];
__device__ __half g_w2t[AP * AP];
__device__ __half g_fcf16[(size_t)BATCH * FCP];
__device__ __half g_wat[(size_t)BNROWS * FCP];
__device__ __half g_wbt[(size_t)BNROWS * HP];
__device__ __half g_h1f16[(size_t)BATCH * HP];

// ================= helpers =================
__device__ __forceinline__ void mma16816(float* c, const uint32_t* a, const uint32_t* b) {
    asm volatile(
        "mma.sync.aligned.m16n8k16.row.col.f32.f16.f16.f32 "
        "{%0,%1,%2,%3}, {%4,%5,%6,%7}, {%8,%9}, {%0,%1,%2,%3};"
        : "+f"(c[0]), "+f"(c[1]), "+f"(c[2]), "+f"(c[3])
        : "r"(a[0]), "r"(a[1]), "r"(a[2]), "r"(a[3]),
          "r"(b[0]), "r"(b[1]));
}

__device__ __forceinline__ uint32_t cvta_shared_u32(const void* p) {
    uint32_t a;
    asm("{ .reg .u64 t; cvta.to.shared.u64 t, %1; cvt.u32.u64 %0, t; }"
        : "=r"(a) : "l"(p));
    return a;
}

__device__ __forceinline__ void cp_async16(uint32_t dst, const void* src) {
    asm volatile("cp.async.ca.shared.global [%0], [%1], 16;" :: "r"(dst), "l"(src));
}
__device__ __forceinline__ void cp_commit() {
    asm volatile("cp.async.commit_group;");
}
__device__ __forceinline__ void cp_wait0() {
    asm volatile("cp.async.wait_group 0;");
}

// ================= prep kernels =================
// H0 fp32 -> fp16, only rows in rowlist (count in *pcount)
__global__ void pre_act_list_kernel(const float* __restrict__ X,
                                    const int* __restrict__ rowlist,
                                    const int* __restrict__ pcount) {
    int idx = blockIdx.x * blockDim.x + threadIdx.x;
    int cnt = *pcount;
    int i = idx / 75;
    if (i >= cnt) return;
    int q = idx - i * 75;
    int r = rowlist[i];
    float4 v = reinterpret_cast<const float4*>(X)[(size_t)r * 75 + q];
    __half2 p0 = __floats2half2_rn(v.x, v.y);
    __half2 p1 = __floats2half2_rn(v.z, v.w);
    uint2 pk = make_uint2(*reinterpret_cast<uint32_t*>(&p0),
                          *reinterpret_cast<uint32_t*>(&p1));
    *reinterpret_cast<uint2*>(&g_act[(size_t)r * AP + q * 4]) = pk;
}

__global__ void pre_wT_kernel(const float* __restrict__ W, int K, int N, int ldo,
                              __half* __restrict__ t16) {
    int idx = blockIdx.x * blockDim.x + threadIdx.x;
    if (idx >= K * N) return;
    int k = idx / N;
    int n = idx - k * N;
    t16[(size_t)n * ldo + k] = __float2half_rn(W[idx]);
}

// ================= frontier kernels =================
__global__ void zero_int_kernel(int* p, int n) {
    int i = blockIdx.x * blockDim.x + threadIdx.x;
    if (i < n) p[i] = 0;
}

__global__ void zero_flags_kernel() {
    int i = blockIdx.x * blockDim.x + threadIdx.x;
    if (i < NV) { g_fnode[i] = 0; g_f1[i] = 0; g_f2[i] = 0; }
    if (i == 0) { g_n1 = 0; g_n2 = 0; g_n3 = 0; }
}

__global__ void mark_node_kernel(const int* __restrict__ node) {
    int i = blockIdx.x * blockDim.x + threadIdx.x;
    if (i < BATCH) g_fnode[node[i]] = 1;
}

__global__ void mark_1hop_kernel(const int* __restrict__ erow,
                                 const int* __restrict__ ecol) {
    int e = blockIdx.x * blockDim.x + threadIdx.x;
    if (e >= NE) return;
    if (g_fnode[erow[e]]) g_f1[ecol[e]] = 1;
}

__global__ void mark_2hop_kernel(const int* __restrict__ erow,
                                 const int* __restrict__ ecol) {
    int e = blockIdx.x * blockDim.x + threadIdx.x;
    if (e >= NE) return;
    if (g_f1[erow[e]]) g_f2[ecol[e]] = 1;
}

__global__ void compact_kernel(const int* __restrict__ flags,
                               int* __restrict__ list, int* __restrict__ ctr) {
    int i = blockIdx.x * blockDim.x + threadIdx.x;
    if (i < NV && flags[i]) {
        int p = atomicAdd(ctr, 1);
        list[p] = i;
    }
}

// ================= pipelined fp16 tensor-core GEMM ==========================
// C[M,N] = A[rows, K] @ B[K,N]; optional rowlist/pcount select A rows (output
// scattered to the same original indices). BM=128, BN=160, BK=32, 512 thr.
// mode 0: fp32 store  1: bias+sig fp32  2: bias+sig fp16  3: plain fp16
#define GS_ABUF 10240
#define GS_BBUF 12800
#define GS_BOFF (2 * GS_ABUF)                  // 20480
#define GS_TOTAL (GS_BOFF + 2 * GS_BBUF)       // 46080 dynamic

__global__ void __launch_bounds__(512)
gemm_f16_kernel(const __half* __restrict__ a16, int lda,
                const __half* __restrict__ bt, int ldb,
                float* __restrict__ C, int ldc,
                __half* __restrict__ o16, int ldo,
                const float* __restrict__ bias,
                const int* __restrict__ rowlist, const int* __restrict__ pcount,
                int M, int N, int K, int mode) {
    extern __shared__ __align__(16) char sm[];
    __shared__ int rows_sm[128];

    int cnt = pcount ? *pcount : M;
    int bm = blockIdx.y * 128;
    if (bm >= cnt) return;

    int tid = threadIdx.x;
    if (tid < 128) {
        int gi = bm + tid;
        if (gi > cnt - 1) gi = cnt - 1;
        rows_sm[tid] = rowlist ? rowlist[gi] : gi;
    }
    __syncthreads();

    int w = tid >> 5;
    int lane = tid & 31;
    int g = lane >> 2;
    int t2 = (lane & 3) * 2;

    int bn = blockIdx.x * 160;
    int m0 = (w & 3) * 32;
    int n0 = (w >> 2) * 40;
    int nch = K >> 5;

    float acc[2][5][4];
#pragma unroll
    for (int i = 0; i < 2; i++)
#pragma unroll
        for (int j = 0; j < 5; j++)
#pragma unroll
            for (int q = 0; q < 4; q++) acc[i][j][q] = 0.0f;

    auto prefetch = [&](int ch, int buf) {
        int k0 = ch * 32;
        {
            int r = tid >> 2;
            int c = tid & 3;
            size_t so = (size_t)rows_sm[r] * lda + k0 + c * 8;
            uint32_t d = cvta_shared_u32(sm + buf * GS_ABUF + (r * 40 + c * 8) * 2);
            cp_async16(d, a16 + so);
        }
#pragma unroll
        for (int it = 0; it < 2; it++) {
            int idx = tid + it * 512;
            if (idx < 640) {
                int r = idx >> 2;
                int c = idx & 3;
                size_t so = (size_t)(bn + r) * ldb + k0 + c * 8;
                uint32_t d = cvta_shared_u32(sm + GS_BOFF + buf * GS_BBUF +
                                             (r * 40 + c * 8) * 2);
                cp_async16(d, bt + so);
            }
        }
    };

    prefetch(0, 0);
    cp_commit();

    for (int ch = 0; ch < nch; ch++) {
        int buf = ch & 1;
        cp_wait0();
        __syncthreads();
        if (ch < nch - 1) {
            prefetch(ch + 1, buf ^ 1);
            cp_commit();
        }
        const __half* Af = reinterpret_cast<const __half*>(sm + buf * GS_ABUF);
        const __half* Bf = reinterpret_cast<const __half*>(sm + GS_BOFF + buf * GS_BBUF);

#pragma unroll
        for (int kc = 0; kc < 32; kc += 16) {
            uint32_t af[2][4];
#pragma unroll
            for (int i = 0; i < 2; i++) {
                int rm = m0 + i * 16;
                af[i][0] = *reinterpret_cast<const uint32_t*>(&Af[(rm + g)     * 40 + kc + t2]);
                af[i][1] = *reinterpret_cast<const uint32_t*>(&Af[(rm + g + 8) * 40 + kc + t2]);
                af[i][2] = *reinterpret_cast<const uint32_t*>(&Af[(rm + g)     * 40 + kc + t2 + 8]);
                af[i][3] = *reinterpret_cast<const uint32_t*>(&Af[(rm + g + 8) * 40 + kc + t2 + 8]);
            }
#pragma unroll
            for (int j = 0; j < 5; j++) {
                int rn = n0 + j * 8;
                uint32_t bf[2];
                bf[0] = *reinterpret_cast<const uint32_t*>(&Bf[(rn + g) * 40 + kc + t2]);
                bf[1] = *reinterpret_cast<const uint32_t*>(&Bf[(rn + g) * 40 + kc + t2 + 8]);
#pragma unroll
                for (int i = 0; i < 2; i++)
                    mma16816(acc[i][j], af[i], bf);
            }
        }
        __syncthreads();
    }

    // ---- epilogue ----
#pragma unroll
    for (int i = 0; i < 2; i++) {
#pragma unroll
        for (int j = 0; j < 5; j++) {
            int gn = bn + n0 + j * 8 + t2;
            if (gn >= N) continue;
#pragma unroll
            for (int half = 0; half < 2; half++) {
                int gm = bm + m0 + i * 16 + g + half * 8;
                if (gm >= cnt) continue;
                int gr = rows_sm[gm - bm];
                float2 o;
                o.x = acc[i][j][half * 2 + 0];
                o.y = acc[i][j][half * 2 + 1];
                if (mode == 1 || mode == 2) {
                    o.x += bias[gn];
                    o.y += bias[gn + 1];
                    o.x = 1.0f / (1.0f + __expf(-o.x));
                    o.y = 1.0f / (1.0f + __expf(-o.y));
                }
                if (mode >= 2) {
                    __half2 hv = __floats2half2_rn(o.x, o.y);
                    *reinterpret_cast<uint32_t*>(&o16[(size_t)gr * ldo + gn]) =
                        *reinterpret_cast<uint32_t*>(&hv);
                } else {
                    *reinterpret_cast<float2*>(C + (size_t)gr * ldc + gn) = o;
                }
            }
        }
    }
}

// ================= graph preprocessing =================
__global__ void count_kernel(const int* __restrict__ erow) {
    int e = blockIdx.x * blockDim.x + threadIdx.x;
    if (e < NE) atomicAdd(&g_cnt[erow[e]], 1);
}

__global__ void vals_kernel(const int* __restrict__ erow, const int* __restrict__ ecol) {
    int e = blockIdx.x * blockDim.x + threadIdx.x;
    if (e >= NE) return;
    int dr = g_cnt[erow[e]];
    int dc = g_cnt[ecol[e]];
    float a = (dr > 0) ? rsqrtf((float)dr) : 0.0f;
    float b = (dc > 0) ? rsqrtf((float)dc) : 0.0f;
    g_vals[e] = a * b;
}

__global__ void scanA_kernel() {
    __shared__ int s[1024];
    int i = blockIdx.x * 1024 + threadIdx.x;
    int v = (i < NV) ? g_cnt[i] : 0;
    s[threadIdx.x] = v;
    __syncthreads();
    for (int o = 1; o < 1024; o <<= 1) {
        int t = 0;
        if (threadIdx.x >= o) t = s[threadIdx.x - o];
        __syncthreads();
        if (threadIdx.x >= o) s[threadIdx.x] += t;
        __syncthreads();
    }
    if (i < NV) g_rowstart[i] = s[threadIdx.x] - v;
    if (threadIdx.x == 1023) g_tot[blockIdx.x] = s[1023];
}

__global__ void scanB_kernel() {
    __shared__ int s[128];
    int v = (threadIdx.x < NBLK_SCAN) ? g_tot[threadIdx.x] : 0;
    s[threadIdx.x] = v;
    __syncthreads();
    for (int o = 1; o < 128; o <<= 1) {
        int t = 0;
        if (threadIdx.x >= o) t = s[threadIdx.x - o];
        __syncthreads();
        if (threadIdx.x >= o) s[threadIdx.x] += t;
        __syncthreads();
    }
    if (threadIdx.x < NBLK_SCAN) g_tot[threadIdx.x] = s[threadIdx.x] - v;
}

__global__ void scanC_kernel() {
    int i = blockIdx.x * blockDim.x + threadIdx.x;
    if (i < NV) g_rowstart[i] += g_tot[i >> 10];
    if (i == 0) g_rowstart[NV] = NE;
}

__global__ void scatter_kernel(const int* __restrict__ erow, const int* __restrict__ ecol) {
    int e = blockIdx.x * blockDim.x + threadIdx.x;
    if (e >= NE) return;
    int r = erow[e];
    int pos = g_rowstart[r] + atomicAdd(&g_cursor[r], 1);
    g_scol[pos] = ecol[e];
    g_sval[pos] = g_vals[e];
}

// ================= fp16 pull SpMM + fused sigmoid (row-list) ================
__device__ __forceinline__ void fma8(float* acc, uint4 t, float v) {
    __half2 p;
    float2 f;
    *reinterpret_cast<uint32_t*>(&p) = t.x; f = __half22float2(p);
    acc[0] += v * f.x; acc[1] += v * f.y;
    *reinterpret_cast<uint32_t*>(&p) = t.y; f = __half22float2(p);
    acc[2] += v * f.x; acc[3] += v * f.y;
    *reinterpret_cast<uint32_t*>(&p) = t.z; f = __half22float2(p);
    acc[4] += v * f.x; acc[5] += v * f.y;
    *reinterpret_cast<uint32_t*>(&p) = t.w; f = __half22float2(p);
    acc[6] += v * f.x; acc[7] += v * f.y;
}

__global__ void spmm_f16_kernel(const __half* __restrict__ X, __half* __restrict__ O,
                                const int* __restrict__ rowlist,
                                const int* __restrict__ pcount) {
    int widx = (blockIdx.x * blockDim.x + threadIdx.x) >> 5;
    int lane = threadIdx.x & 31;
    int cnt = *pcount;
    if (widx >= cnt) return;
    int row = rowlist[widx];
    int s = g_rowstart[row];
    int e = g_rowstart[row + 1];
    bool lo8 = lane < 8;
    float a[8] = {0,0,0,0,0,0,0,0};
    float b[8] = {0,0,0,0,0,0,0,0};
    int j = s;
    for (; j + 1 < e; j += 2) {
        int c0 = g_scol[j];
        float v0 = g_sval[j];
        int c1 = g_scol[j + 1];
        float v1 = g_sval[j + 1];
        const uint4* x0 = reinterpret_cast<const uint4*>(X + (size_t)c0 * AP);
        const uint4* x1 = reinterpret_cast<const uint4*>(X + (size_t)c1 * AP);
        uint4 t0 = x0[lane];
        uint4 t1 = x1[lane];
        fma8(a, t0, v0);
        fma8(a, t1, v1);
        if (lo8) {
            uint4 s0 = x0[32 + lane];
            uint4 s1 = x1[32 + lane];
            fma8(b, s0, v0);
            fma8(b, s1, v1);
        }
    }
    if (j < e) {
        int c = g_scol[j];
        float v = g_sval[j];
        const uint4* x4 = reinterpret_cast<const uint4*>(X + (size_t)c * AP);
        fma8(a, x4[lane], v);
        if (lo8) fma8(b, x4[32 + lane], v);
    }
    __half2 h0 = __floats2half2_rn(1.0f/(1.0f+__expf(-a[0])), 1.0f/(1.0f+__expf(-a[1])));
    __half2 h1 = __floats2half2_rn(1.0f/(1.0f+__expf(-a[2])), 1.0f/(1.0f+__expf(-a[3])));
    __half2 h2 = __floats2half2_rn(1.0f/(1.0f+__expf(-a[4])), 1.0f/(1.0f+__expf(-a[5])));
    __half2 h3 = __floats2half2_rn(1.0f/(1.0f+__expf(-a[6])), 1.0f/(1.0f+__expf(-a[7])));
    uint4 pk;
    pk.x = *reinterpret_cast<uint32_t*>(&h0);
    pk.y = *reinterpret_cast<uint32_t*>(&h1);
    pk.z = *reinterpret_cast<uint32_t*>(&h2);
    pk.w = *reinterpret_cast<uint32_t*>(&h3);
    __stcs(reinterpret_cast<uint4*>(O + (size_t)row * AP) + lane, pk);
    if (lo8) {
        int fb = 256 + lane * 8;
        float o[8];
#pragma unroll
        for (int t = 0; t < 8; t++)
            o[t] = (fb + t < EMB) ? 1.0f/(1.0f+__expf(-b[t])) : 0.0f;
        h0 = __floats2half2_rn(o[0], o[1]);
        h1 = __floats2half2_rn(o[2], o[3]);
        h2 = __floats2half2_rn(o[4], o[5]);
        h3 = __floats2half2_rn(o[6], o[7]);
        pk.x = *reinterpret_cast<uint32_t*>(&h0);
        pk.y = *reinterpret_cast<uint32_t*>(&h1);
        pk.z = *reinterpret_cast<uint32_t*>(&h2);
        pk.w = *reinterpret_cast<uint32_t*>(&h3);
        __stcs(reinterpret_cast<uint4*>(O + (size_t)row * AP) + 32 + lane, pk);
    }
}

// build fc = concat(H2[node], input) -> fp16 [BATCH, FCP]
__global__ void fc_build_f16_kernel(const __half* __restrict__ H2,
                                    const int* __restrict__ node,
                                    const float* __restrict__ input) {
    int idx = blockIdx.x * blockDim.x + threadIdx.x;
    if (idx >= BATCH * FCK) return;
    int b = idx / FCK;
    int j = idx - b * FCK;
    __half v;
    if (j < EMB) {
        size_t n = (size_t)node[b];
        v = H2[n * AP + j];
    } else {
        v = __float2half_rn(input[(size_t)b * IN_DIM + (j - EMB)]);
    }
    g_fcf16[(size_t)b * FCP + j] = v;
}

// final layer
__global__ void final_kernel(const float* __restrict__ h,
                             const float* __restrict__ Wc,
                             const float* __restrict__ bc,
                             float* __restrict__ out) {
    int warp = (blockIdx.x * blockDim.x + threadIdx.x) >> 5;
    int lane = threadIdx.x & 31;
    if (warp >= BATCH) return;
    const float* hr = h + (size_t)warp * HID;
    float a0 = 0.f, a1 = 0.f;
    for (int k = lane; k < HID; k += 32) {
        float hv = hr[k];
        a0 += hv * Wc[k * 2 + 0];
        a1 += hv * Wc[k * 2 + 1];
    }
#pragma unroll
    for (int o = 16; o > 0; o >>= 1) {
        a0 += __shfl_down_sync(0xFFFFFFFFu, a0, o);
        a1 += __shfl_down_sync(0xFFFFFFFFu, a1, o);
    }
    if (lane == 0) {
        out[warp * 2 + 0] = a0 + bc[0];
        out[warp * 2 + 1] = a1 + bc[1];
    }
}

// ================= host launch =================
extern "C" void kernel_launch(void* const* d_in, const int* in_sizes, int n_in,
                              void* d_out, int out_size) {
    const float* input = (const float*)d_in[0];
    const int*   node  = (const int*)d_in[1];
    const int*   erow  = (const int*)d_in[2];
    const int*   ecol  = (const int*)d_in[3];
    const float* H0    = (const float*)d_in[4];
    const float* W1    = (const float*)d_in[5];
    const float* W2    = (const float*)d_in[6];
    const float* Wa    = (const float*)d_in[7];
    const float* ba    = (const float*)d_in[8];
    const float* Wb    = (const float*)d_in[9];
    const float* bb    = (const float*)d_in[10];
    const float* Wc    = (const float*)d_in[11];
    const float* bc    = (const float*)d_in[12];
    float*       out   = (float*)d_out;

    void *p_cnt, *p_cursor, *p_h2;
    void *p_act, *p_x16, *p_w1t, *p_w2t, *p_fcf16, *p_wat, *p_wbt, *p_h1f16;
    void *p_fnode, *p_f1, *p_f2, *p_list1, *p_list2, *p_list3, *p_n1, *p_n2, *p_n3;
    cudaGetSymbolAddress(&p_cnt,    g_cnt);
    cudaGetSymbolAddress(&p_cursor, g_cursor);
    cudaGetSymbolAddress(&p_h2,     g_h2);
    cudaGetSymbolAddress(&p_act,    g_act);
    cudaGetSymbolAddress(&p_x16,    g_x16);
    cudaGetSymbolAddress(&p_w1t,    g_w1t);
    cudaGetSymbolAddress(&p_w2t,    g_w2t);
    cudaGetSymbolAddress(&p_fcf16,  g_fcf16);
    cudaGetSymbolAddress(&p_wat,    g_wat);
    cudaGetSymbolAddress(&p_wbt,    g_wbt);
    cudaGetSymbolAddress(&p_h1f16,  g_h1f16);
    cudaGetSymbolAddress(&p_fnode,  g_fnode);
    cudaGetSymbolAddress(&p_f1,     g_f1);
    cudaGetSymbolAddress(&p_f2,     g_f2);
    cudaGetSymbolAddress(&p_list1,  g_list1);
    cudaGetSymbolAddress(&p_list2,  g_list2);
    cudaGetSymbolAddress(&p_list3,  g_list3);
    cudaGetSymbolAddress(&p_n1,     g_n1);
    cudaGetSymbolAddress(&p_n2,     g_n2);
    cudaGetSymbolAddress(&p_n3,     g_n3);

    float* h2 = (float*)p_h2;

    cudaFuncSetAttribute(gemm_f16_kernel,
                         cudaFuncAttributeMaxDynamicSharedMemorySize, GS_TOTAL);

    static cudaStream_t s2 = nullptr, s3 = nullptr;
    static cudaEvent_t evF = nullptr, evFront = nullptr, evCsr = nullptr;
    if (!s2) {
        cudaStreamCreateWithFlags(&s2, cudaStreamNonBlocking);
        cudaStreamCreateWithFlags(&s3, cudaStreamNonBlocking);
        cudaEventCreateWithFlags(&evF, cudaEventDisableTiming);
        cudaEventCreateWithFlags(&evFront, cudaEventDisableTiming);
        cudaEventCreateWithFlags(&evCsr, cudaEventDisableTiming);
    }

    const int TPB = 256;
    const int nvBlocks = (NV + TPB - 1) / TPB;
    const int neBlocks = (NE + TPB - 1) / TPB;

    cudaEventRecord(evF, 0);

    // ---- s2: frontier construction (no CSR needed) ----
    cudaStreamWaitEvent(s2, evF, 0);
    zero_flags_kernel<<<nvBlocks, TPB, 0, s2>>>();
    mark_node_kernel<<<(BATCH + TPB - 1) / TPB, TPB, 0, s2>>>(node);
    mark_1hop_kernel<<<neBlocks, TPB, 0, s2>>>(erow, ecol);
    mark_2hop_kernel<<<neBlocks, TPB, 0, s2>>>(erow, ecol);
    compact_kernel<<<nvBlocks, TPB, 0, s2>>>((int*)p_f1, (int*)p_list1, (int*)p_n1);
    compact_kernel<<<nvBlocks, TPB, 0, s2>>>((int*)p_fnode, (int*)p_list2, (int*)p_n2);
    compact_kernel<<<nvBlocks, TPB, 0, s2>>>((int*)p_f2, (int*)p_list3, (int*)p_n3);
    cudaEventRecord(evFront, s2);

    // ---- s3: CSR build ----
    cudaStreamWaitEvent(s3, evF, 0);
    zero_int_kernel<<<nvBlocks, TPB, 0, s3>>>((int*)p_cnt, NV);
    zero_int_kernel<<<nvBlocks, TPB, 0, s3>>>((int*)p_cursor, NV);
    count_kernel<<<neBlocks, TPB, 0, s3>>>(erow);
    vals_kernel<<<neBlocks, TPB, 0, s3>>>(erow, ecol);
    scanA_kernel<<<NBLK_SCAN, 1024, 0, s3>>>();
    scanB_kernel<<<1, 128, 0, s3>>>();
    scanC_kernel<<<nvBlocks, TPB, 0, s3>>>();
    scatter_kernel<<<neBlocks, TPB, 0, s3>>>(erow, ecol);
    cudaEventRecord(evCsr, s3);

    // ---- main stream: weight conversions (independent of frontier) ----
    pre_wT_kernel<<<(EMB * EMB + TPB - 1) / TPB, TPB>>>(W1, EMB, EMB, AP, (__half*)p_w1t);
    pre_wT_kernel<<<(EMB * EMB + TPB - 1) / TPB, TPB>>>(W2, EMB, EMB, AP, (__half*)p_w2t);
    pre_wT_kernel<<<(FCK * HID + TPB - 1) / TPB, TPB>>>(Wa, FCK, HID, FCP, (__half*)p_wat);
    pre_wT_kernel<<<(HID * HID + TPB - 1) / TPB, TPB>>>(Wb, HID, HID, HP, (__half*)p_wbt);

    // ---- join frontier, then pre_act + GEMM1 on S2 rows only ----
    cudaStreamWaitEvent(0, evFront, 0);
    pre_act_list_kernel<<<(NV * 75 + TPB - 1) / TPB, TPB>>>(H0, (int*)p_list3, (int*)p_n3);

    dim3 gbig(2, (NV + 127) / 128);
    gemm_f16_kernel<<<gbig, 512, GS_TOTAL>>>(
        (__half*)p_act, AP, (__half*)p_w1t, AP,
        nullptr, 0, (__half*)p_x16, AP, nullptr,
        (int*)p_list3, (int*)p_n3, NV, EMB, AP, 3);

    // ---- join CSR, then SpMM 1 on S1 rows ----
    cudaStreamWaitEvent(0, evCsr, 0);
    int spmmBlocks = (NV * 32 + TPB - 1) / TPB;
    spmm_f16_kernel<<<spmmBlocks, TPB>>>((__half*)p_x16, (__half*)p_act,
                                         (int*)p_list1, (int*)p_n1);

    // ---- GCN layer 2 GEMM on S1 rows ----
    gemm_f16_kernel<<<gbig, 512, GS_TOTAL>>>(
        (__half*)p_act, AP, (__half*)p_w2t, AP,
        nullptr, 0, (__half*)p_x16, AP, nullptr,
        (int*)p_list1, (int*)p_n1, NV, EMB, AP, 3);

    // ---- SpMM 2 on nodeset rows ----
    int spmm2Blocks = (BATCH * 32 + TPB - 1) / TPB;
    spmm_f16_kernel<<<spmm2Blocks, TPB>>>((__half*)p_x16, (__half*)p_act,
                                          (int*)p_list2, (int*)p_n2);

    // ---- MLP head ----
    fc_build_f16_kernel<<<(BATCH * FCK + TPB - 1) / TPB, TPB>>>(
        (__half*)p_act, node, input);

    dim3 gmlp(4, BATCH / 128);
    gemm_f16_kernel<<<gmlp, 512, GS_TOTAL>>>(
        (__half*)p_fcf16, FCP, (__half*)p_wat, FCP,
        nullptr, 0, (__half*)p_h1f16, HP, ba,
        nullptr, nullptr, BATCH, HID, FCP, 2);
    gemm_f16_kernel<<<gmlp, 512, GS_TOTAL>>>(
        (__half*)p_h1f16, HP, (__half*)p_wbt, HP,
        h2, HID, nullptr, 0, bb,
        nullptr, nullptr, BATCH, HID, HP, 1);

    final_kernel<<<(BATCH * 32 + TPB - 1) / TPB, TPB>>>(h2, Wc, bc, out);
}

// round 11
// speedup vs baseline: 8.8634x; 1.0710x over previous
#include <cuda_runtime.h>
#include <cuda_fp16.h>
#include <math.h>
#include <cstdint>

#define NV 117000
#define NE 468000
#define EMB 300
#define IN_DIM 768
#define BATCH 4096
#define HID 500
#define FCK (EMB + IN_DIM)   // 1068
#define NBLK_SCAN ((NV + 1023) / 1024)   // 115
#define AP 320               // padded fp16 stride for GCN activations/weights
#define FCP 1088             // padded fc width
#define HP 512               // padded hidden width
#define BNROWS 640           // padded N-rows for transposed MLP weights

// ---------------- device scratch (allocation-free, zero-initialized) -------
__device__ float g_vals[NE];
__device__ int   g_cnt[NV];
__device__ int   g_rowstart[NV + 1];
__device__ int   g_tot[256];
__device__ int   g_cursor[NV];
__device__ int   g_scol[NE];
__device__ float g_sval[NE];
__device__ float g_h2[BATCH * HID];
// frontier machinery (generation-stamped flags: flag[i]==g_gen means "set")
__device__ int   g_gen;
__device__ int   g_fnode[NV];
__device__ int   g_f1[NV];       // S1 (1-hop)
__device__ int   g_f2[NV];       // S2 (2-hop)
__device__ int   g_list1[NV];    // compacted S1
__device__ int   g_list3[NV];    // compacted S2
__device__ int   g_n1;
__device__ int   g_n3;
// fp16 buffers (pads stay statically zero — never written)
__device__ __half g_act[(size_t)NV * AP];           // activations ping
__device__ __half g_x16[(size_t)NV * AP];           // GEMM output pong
__device__ __half g_w1t[AP * AP];
__device__ __half g_w2t[AP * AP];
__device__ __half g_fcf16[(size_t)BATCH * FCP];
__device__ __half g_wat[(size_t)BNROWS * FCP];
__device__ __half g_wbt[(size_t)BNROWS * HP];
__device__ __half g_h1f16[(size_t)BATCH * HP];

// ================= helpers =================
__device__ __forceinline__ void mma16816(float* c, const uint32_t* a, const uint32_t* b) {
    asm volatile(
        "mma.sync.aligned.m16n8k16.row.col.f32.f16.f16.f32 "
        "{%0,%1,%2,%3}, {%4,%5,%6,%7}, {%8,%9}, {%0,%1,%2,%3};"
        : "+f"(c[0]), "+f"(c[1]), "+f"(c[2]), "+f"(c[3])
        : "r"(a[0]), "r"(a[1]), "r"(a[2]), "r"(a[3]),
          "r"(b[0]), "r"(b[1]));
}

__device__ __forceinline__ uint32_t cvta_shared_u32(const void* p) {
    uint32_t a;
    asm("{ .reg .u64 t; cvta.to.shared.u64 t, %1; cvt.u32.u64 %0, t; }"
        : "=r"(a) : "l"(p));
    return a;
}

__device__ __forceinline__ void cp_async16(uint32_t dst, const void* src) {
    asm volatile("cp.async.ca.shared.global [%0], [%1], 16;" :: "r"(dst), "l"(src));
}
__device__ __forceinline__ void cp_commit() {
    asm volatile("cp.async.commit_group;");
}
__device__ __forceinline__ void cp_wait0() {
    asm volatile("cp.async.wait_group 0;");
}

// ================= prep kernels =================
// H0 fp32 -> fp16, only rows in rowlist (count in *pcount)
__global__ void pre_act_list_kernel(const float* __restrict__ X,
                                    const int* __restrict__ rowlist,
                                    const int* __restrict__ pcount) {
    int idx = blockIdx.x * blockDim.x + threadIdx.x;
    int cnt = *pcount;
    int i = idx / 75;
    if (i >= cnt) return;
    int q = idx - i * 75;
    int r = rowlist[i];
    float4 v = reinterpret_cast<const float4*>(X)[(size_t)r * 75 + q];
    __half2 p0 = __floats2half2_rn(v.x, v.y);
    __half2 p1 = __floats2half2_rn(v.z, v.w);
    uint2 pk = make_uint2(*reinterpret_cast<uint32_t*>(&p0),
                          *reinterpret_cast<uint32_t*>(&p1));
    *reinterpret_cast<uint2*>(&g_act[(size_t)r * AP + q * 4]) = pk;
}

__global__ void pre_wT_kernel(const float* __restrict__ W, int K, int N, int ldo,
                              __half* __restrict__ t16) {
    int idx = blockIdx.x * blockDim.x + threadIdx.x;
    if (idx >= K * N) return;
    int k = idx / N;
    int n = idx - k * N;
    t16[(size_t)n * ldo + k] = __float2half_rn(W[idx]);
}

// input fp32 [BATCH, IN_DIM] -> fc columns [EMB, EMB+IN_DIM) as fp16
__global__ void pre_input_f16_kernel(const float* __restrict__ input) {
    int idx = blockIdx.x * blockDim.x + threadIdx.x;   // over BATCH*192 float4
    if (idx >= BATCH * 192) return;
    int b = idx / 192;
    int q = idx - b * 192;
    float4 v = reinterpret_cast<const float4*>(input)[(size_t)b * 192 + q];
    __half2 p0 = __floats2half2_rn(v.x, v.y);
    __half2 p1 = __floats2half2_rn(v.z, v.w);
    uint2 pk = make_uint2(*reinterpret_cast<uint32_t*>(&p0),
                          *reinterpret_cast<uint32_t*>(&p1));
    *reinterpret_cast<uint2*>(&g_fcf16[(size_t)b * FCP + EMB + q * 4]) = pk;
}

// ================= frontier kernels =================
__global__ void zero_int_kernel(int* p, int n) {
    int i = blockIdx.x * blockDim.x + threadIdx.x;
    if (i < n) p[i] = 0;
}

__global__ void bump_gen_kernel() {
    g_gen += 1;
    g_n1 = 0;
    g_n3 = 0;
}

__global__ void mark_node_kernel(const int* __restrict__ node) {
    int i = blockIdx.x * blockDim.x + threadIdx.x;
    if (i < BATCH) g_fnode[node[i]] = g_gen;
}

__global__ void mark_1hop_kernel(const int* __restrict__ erow,
                                 const int* __restrict__ ecol) {
    int e = blockIdx.x * blockDim.x + threadIdx.x;
    if (e >= NE) return;
    int gen = g_gen;
    if (g_fnode[erow[e]] == gen) g_f1[ecol[e]] = gen;
}

__global__ void mark_2hop_kernel(const int* __restrict__ erow,
                                 const int* __restrict__ ecol) {
    int e = blockIdx.x * blockDim.x + threadIdx.x;
    if (e >= NE) return;
    int gen = g_gen;
    if (g_f1[erow[e]] == gen) g_f2[ecol[e]] = gen;
}

__global__ void compact_kernel(const int* __restrict__ flags,
                               int* __restrict__ list, int* __restrict__ ctr) {
    int i = blockIdx.x * blockDim.x + threadIdx.x;
    if (i < NV && flags[i] == g_gen) {
        int p = atomicAdd(ctr, 1);
        list[p] = i;
    }
}

// ================= pipelined fp16 tensor-core GEMM ==========================
// C[M,N] = A[rows, K] @ B[K,N]; optional rowlist/pcount select A rows (output
// scattered to the same original indices). BM=128, BN=160, BK=32, 512 thr.
// mode 0: fp32 store  1: bias+sig fp32  2: bias+sig fp16  3: plain fp16
#define GS_ABUF 10240
#define GS_BBUF 12800
#define GS_BOFF (2 * GS_ABUF)                  // 20480
#define GS_TOTAL (GS_BOFF + 2 * GS_BBUF)       // 46080 dynamic

__global__ void __launch_bounds__(512)
gemm_f16_kernel(const __half* __restrict__ a16, int lda,
                const __half* __restrict__ bt, int ldb,
                float* __restrict__ C, int ldc,
                __half* __restrict__ o16, int ldo,
                const float* __restrict__ bias,
                const int* __restrict__ rowlist, const int* __restrict__ pcount,
                int M, int N, int K, int mode) {
    extern __shared__ __align__(16) char sm[];
    __shared__ int rows_sm[128];

    int cnt = pcount ? *pcount : M;
    int bm = blockIdx.y * 128;
    if (bm >= cnt) return;

    int tid = threadIdx.x;
    if (tid < 128) {
        int gi = bm + tid;
        if (gi > cnt - 1) gi = cnt - 1;
        rows_sm[tid] = rowlist ? rowlist[gi] : gi;
    }
    __syncthreads();

    int w = tid >> 5;
    int lane = tid & 31;
    int g = lane >> 2;
    int t2 = (lane & 3) * 2;

    int bn = blockIdx.x * 160;
    int m0 = (w & 3) * 32;
    int n0 = (w >> 2) * 40;
    int nch = K >> 5;

    float acc[2][5][4];
#pragma unroll
    for (int i = 0; i < 2; i++)
#pragma unroll
        for (int j = 0; j < 5; j++)
#pragma unroll
            for (int q = 0; q < 4; q++) acc[i][j][q] = 0.0f;

    auto prefetch = [&](int ch, int buf) {
        int k0 = ch * 32;
        {
            int r = tid >> 2;
            int c = tid & 3;
            size_t so = (size_t)rows_sm[r] * lda + k0 + c * 8;
            uint32_t d = cvta_shared_u32(sm + buf * GS_ABUF + (r * 40 + c * 8) * 2);
            cp_async16(d, a16 + so);
        }
#pragma unroll
        for (int it = 0; it < 2; it++) {
            int idx = tid + it * 512;
            if (idx < 640) {
                int r = idx >> 2;
                int c = idx & 3;
                size_t so = (size_t)(bn + r) * ldb + k0 + c * 8;
                uint32_t d = cvta_shared_u32(sm + GS_BOFF + buf * GS_BBUF +
                                             (r * 40 + c * 8) * 2);
                cp_async16(d, bt + so);
            }
        }
    };

    prefetch(0, 0);
    cp_commit();

    for (int ch = 0; ch < nch; ch++) {
        int buf = ch & 1;
        cp_wait0();
        __syncthreads();
        if (ch < nch - 1) {
            prefetch(ch + 1, buf ^ 1);
            cp_commit();
        }
        const __half* Af = reinterpret_cast<const __half*>(sm + buf * GS_ABUF);
        const __half* Bf = reinterpret_cast<const __half*>(sm + GS_BOFF + buf * GS_BBUF);

#pragma unroll
        for (int kc = 0; kc < 32; kc += 16) {
            uint32_t af[2][4];
#pragma unroll
            for (int i = 0; i < 2; i++) {
                int rm = m0 + i * 16;
                af[i][0] = *reinterpret_cast<const uint32_t*>(&Af[(rm + g)     * 40 + kc + t2]);
                af[i][1] = *reinterpret_cast<const uint32_t*>(&Af[(rm + g + 8) * 40 + kc + t2]);
                af[i][2] = *reinterpret_cast<const uint32_t*>(&Af[(rm + g)     * 40 + kc + t2 + 8]);
                af[i][3] = *reinterpret_cast<const uint32_t*>(&Af[(rm + g + 8) * 40 + kc + t2 + 8]);
            }
#pragma unroll
            for (int j = 0; j < 5; j++) {
                int rn = n0 + j * 8;
                uint32_t bf[2];
                bf[0] = *reinterpret_cast<const uint32_t*>(&Bf[(rn + g) * 40 + kc + t2]);
                bf[1] = *reinterpret_cast<const uint32_t*>(&Bf[(rn + g) * 40 + kc + t2 + 8]);
#pragma unroll
                for (int i = 0; i < 2; i++)
                    mma16816(acc[i][j], af[i], bf);
            }
        }
        __syncthreads();
    }

    // ---- epilogue ----
#pragma unroll
    for (int i = 0; i < 2; i++) {
#pragma unroll
        for (int j = 0; j < 5; j++) {
            int gn = bn + n0 + j * 8 + t2;
            if (gn >= N) continue;
#pragma unroll
            for (int half = 0; half < 2; half++) {
                int gm = bm + m0 + i * 16 + g + half * 8;
                if (gm >= cnt) continue;
                int gr = rows_sm[gm - bm];
                float2 o;
                o.x = acc[i][j][half * 2 + 0];
                o.y = acc[i][j][half * 2 + 1];
                if (mode == 1 || mode == 2) {
                    o.x += bias[gn];
                    o.y += bias[gn + 1];
                    o.x = 1.0f / (1.0f + __expf(-o.x));
                    o.y = 1.0f / (1.0f + __expf(-o.y));
                }
                if (mode >= 2) {
                    __half2 hv = __floats2half2_rn(o.x, o.y);
                    *reinterpret_cast<uint32_t*>(&o16[(size_t)gr * ldo + gn]) =
                        *reinterpret_cast<uint32_t*>(&hv);
                } else {
                    *reinterpret_cast<float2*>(C + (size_t)gr * ldc + gn) = o;
                }
            }
        }
    }
}

// ================= graph preprocessing =================
__global__ void count_kernel(const int* __restrict__ erow) {
    int e = blockIdx.x * blockDim.x + threadIdx.x;
    if (e < NE) atomicAdd(&g_cnt[erow[e]], 1);
}

__global__ void vals_kernel(const int* __restrict__ erow, const int* __restrict__ ecol) {
    int e = blockIdx.x * blockDim.x + threadIdx.x;
    if (e >= NE) return;
    int dr = g_cnt[erow[e]];
    int dc = g_cnt[ecol[e]];
    float a = (dr > 0) ? rsqrtf((float)dr) : 0.0f;
    float b = (dc > 0) ? rsqrtf((float)dc) : 0.0f;
    g_vals[e] = a * b;
}

__global__ void scanA_kernel() {
    __shared__ int s[1024];
    int i = blockIdx.x * 1024 + threadIdx.x;
    int v = (i < NV) ? g_cnt[i] : 0;
    s[threadIdx.x] = v;
    __syncthreads();
    for (int o = 1; o < 1024; o <<= 1) {
        int t = 0;
        if (threadIdx.x >= o) t = s[threadIdx.x - o];
        __syncthreads();
        if (threadIdx.x >= o) s[threadIdx.x] += t;
        __syncthreads();
    }
    if (i < NV) g_rowstart[i] = s[threadIdx.x] - v;
    if (threadIdx.x == 1023) g_tot[blockIdx.x] = s[1023];
}

__global__ void scanB_kernel() {
    __shared__ int s[128];
    int v = (threadIdx.x < NBLK_SCAN) ? g_tot[threadIdx.x] : 0;
    s[threadIdx.x] = v;
    __syncthreads();
    for (int o = 1; o < 128; o <<= 1) {
        int t = 0;
        if (threadIdx.x >= o) t = s[threadIdx.x - o];
        __syncthreads();
        if (threadIdx.x >= o) s[threadIdx.x] += t;
        __syncthreads();
    }
    if (threadIdx.x < NBLK_SCAN) g_tot[threadIdx.x] = s[threadIdx.x] - v;
}

__global__ void scanC_kernel() {
    int i = blockIdx.x * blockDim.x + threadIdx.x;
    if (i < NV) g_rowstart[i] += g_tot[i >> 10];
    if (i == 0) g_rowstart[NV] = NE;
}

__global__ void scatter_kernel(const int* __restrict__ erow, const int* __restrict__ ecol) {
    int e = blockIdx.x * blockDim.x + threadIdx.x;
    if (e >= NE) return;
    int r = erow[e];
    int pos = g_rowstart[r] + atomicAdd(&g_cursor[r], 1);
    g_scol[pos] = ecol[e];
    g_sval[pos] = g_vals[e];
}

// ================= fp16 pull SpMM + fused sigmoid ===========================
__device__ __forceinline__ void fma8(float* acc, uint4 t, float v) {
    __half2 p;
    float2 f;
    *reinterpret_cast<uint32_t*>(&p) = t.x; f = __half22float2(p);
    acc[0] += v * f.x; acc[1] += v * f.y;
    *reinterpret_cast<uint32_t*>(&p) = t.y; f = __half22float2(p);
    acc[2] += v * f.x; acc[3] += v * f.y;
    *reinterpret_cast<uint32_t*>(&p) = t.z; f = __half22float2(p);
    acc[4] += v * f.x; acc[5] += v * f.y;
    *reinterpret_cast<uint32_t*>(&p) = t.w; f = __half22float2(p);
    acc[6] += v * f.x; acc[7] += v * f.y;
}

// core accumulation for one row; a[8] covers features 8*lane..8*lane+7,
// b[8] covers 256+8*lane.. (lanes 0..7 only)
__device__ __forceinline__ void spmm_accum(const __half* __restrict__ X,
                                           int row, int lane, bool lo8,
                                           float* a, float* b) {
    int s = g_rowstart[row];
    int e = g_rowstart[row + 1];
    int j = s;
    for (; j + 1 < e; j += 2) {
        int c0 = g_scol[j];
        float v0 = g_sval[j];
        int c1 = g_scol[j + 1];
        float v1 = g_sval[j + 1];
        const uint4* x0 = reinterpret_cast<const uint4*>(X + (size_t)c0 * AP);
        const uint4* x1 = reinterpret_cast<const uint4*>(X + (size_t)c1 * AP);
        uint4 t0 = x0[lane];
        uint4 t1 = x1[lane];
        fma8(a, t0, v0);
        fma8(a, t1, v1);
        if (lo8) {
            uint4 s0 = x0[32 + lane];
            uint4 s1 = x1[32 + lane];
            fma8(b, s0, v0);
            fma8(b, s1, v1);
        }
    }
    if (j < e) {
        int c = g_scol[j];
        float v = g_sval[j];
        const uint4* x4 = reinterpret_cast<const uint4*>(X + (size_t)c * AP);
        fma8(a, x4[lane], v);
        if (lo8) fma8(b, x4[32 + lane], v);
    }
}

// SpMM over rowlist, fp16 output at stride AP (used for H1 on S1 rows)
__global__ void spmm_f16_kernel(const __half* __restrict__ X, __half* __restrict__ O,
                                const int* __restrict__ rowlist,
                                const int* __restrict__ pcount) {
    int widx = (blockIdx.x * blockDim.x + threadIdx.x) >> 5;
    int lane = threadIdx.x & 31;
    int cnt = *pcount;
    if (widx >= cnt) return;
    int row = rowlist[widx];
    bool lo8 = lane < 8;
    float a[8] = {0,0,0,0,0,0,0,0};
    float b[8] = {0,0,0,0,0,0,0,0};
    spmm_accum(X, row, lane, lo8, a, b);

    __half2 h0 = __floats2half2_rn(1.0f/(1.0f+__expf(-a[0])), 1.0f/(1.0f+__expf(-a[1])));
    __half2 h1 = __floats2half2_rn(1.0f/(1.0f+__expf(-a[2])), 1.0f/(1.0f+__expf(-a[3])));
    __half2 h2 = __floats2half2_rn(1.0f/(1.0f+__expf(-a[4])), 1.0f/(1.0f+__expf(-a[5])));
    __half2 h3 = __floats2half2_rn(1.0f/(1.0f+__expf(-a[6])), 1.0f/(1.0f+__expf(-a[7])));
    uint4 pk;
    pk.x = *reinterpret_cast<uint32_t*>(&h0);
    pk.y = *reinterpret_cast<uint32_t*>(&h1);
    pk.z = *reinterpret_cast<uint32_t*>(&h2);
    pk.w = *reinterpret_cast<uint32_t*>(&h3);
    __stcs(reinterpret_cast<uint4*>(O + (size_t)row * AP) + lane, pk);
    if (lo8) {
        int fb = 256 + lane * 8;
        float o[8];
#pragma unroll
        for (int t = 0; t < 8; t++)
            o[t] = (fb + t < EMB) ? 1.0f/(1.0f+__expf(-b[t])) : 0.0f;
        h0 = __floats2half2_rn(o[0], o[1]);
        h1 = __floats2half2_rn(o[2], o[3]);
        h2 = __floats2half2_rn(o[4], o[5]);
        h3 = __floats2half2_rn(o[6], o[7]);
        pk.x = *reinterpret_cast<uint32_t*>(&h0);
        pk.y = *reinterpret_cast<uint32_t*>(&h1);
        pk.z = *reinterpret_cast<uint32_t*>(&h2);
        pk.w = *reinterpret_cast<uint32_t*>(&h3);
        __stcs(reinterpret_cast<uint4*>(O + (size_t)row * AP) + 32 + lane, pk);
    }
}

// fused spmm2 + fc EMB-part: warp b computes H2[node[b]] and writes fp16
// directly into g_fcf16[b, 0:300]. Group-2 stores pair-masked at 300.
__global__ void spmm_fc_kernel(const __half* __restrict__ X,
                               const int* __restrict__ node) {
    int b = (blockIdx.x * blockDim.x + threadIdx.x) >> 5;
    int lane = threadIdx.x & 31;
    if (b >= BATCH) return;
    int row = node[b];
    bool lo8 = lane < 8;
    float a[8] = {0,0,0,0,0,0,0,0};
    float bb[8] = {0,0,0,0,0,0,0,0};
    spmm_accum(X, row, lane, lo8, a, bb);

    __half* fc = g_fcf16 + (size_t)b * FCP;
    __half2 h0 = __floats2half2_rn(1.0f/(1.0f+__expf(-a[0])), 1.0f/(1.0f+__expf(-a[1])));
    __half2 h1 = __floats2half2_rn(1.0f/(1.0f+__expf(-a[2])), 1.0f/(1.0f+__expf(-a[3])));
    __half2 h2 = __floats2half2_rn(1.0f/(1.0f+__expf(-a[4])), 1.0f/(1.0f+__expf(-a[5])));
    __half2 h3 = __floats2half2_rn(1.0f/(1.0f+__expf(-a[6])), 1.0f/(1.0f+__expf(-a[7])));
    uint4 pk;
    pk.x = *reinterpret_cast<uint32_t*>(&h0);
    pk.y = *reinterpret_cast<uint32_t*>(&h1);
    pk.z = *reinterpret_cast<uint32_t*>(&h2);
    pk.w = *reinterpret_cast<uint32_t*>(&h3);
    *(reinterpret_cast<uint4*>(fc) + lane) = pk;   // features 8*lane..8*lane+7 < 256
    if (lo8) {
        int fb = 256 + lane * 8;
#pragma unroll
        for (int t = 0; t < 4; t++) {
            int f = fb + 2 * t;
            if (f < EMB) {   // EMB even -> pair never straddles
                __half2 hv = __floats2half2_rn(1.0f/(1.0f+__expf(-bb[2*t])),
                                               1.0f/(1.0f+__expf(-bb[2*t+1])));
                *reinterpret_cast<uint32_t*>(fc + f) = *reinterpret_cast<uint32_t*>(&hv);
            }
        }
    }
}

// final layer
__global__ void final_kernel(const float* __restrict__ h,
                             const float* __restrict__ Wc,
                             const float* __restrict__ bc,
                             float* __restrict__ out) {
    int warp = (blockIdx.x * blockDim.x + threadIdx.x) >> 5;
    int lane = threadIdx.x & 31;
    if (warp >= BATCH) return;
    const float* hr = h + (size_t)warp * HID;
    float a0 = 0.f, a1 = 0.f;
    for (int k = lane; k < HID; k += 32) {
        float hv = hr[k];
        a0 += hv * Wc[k * 2 + 0];
        a1 += hv * Wc[k * 2 + 1];
    }
#pragma unroll
    for (int o = 16; o > 0; o >>= 1) {
        a0 += __shfl_down_sync(0xFFFFFFFFu, a0, o);
        a1 += __shfl_down_sync(0xFFFFFFFFu, a1, o);
    }
    if (lane == 0) {
        out[warp * 2 + 0] = a0 + bc[0];
        out[warp * 2 + 1] = a1 + bc[1];
    }
}

// ================= host launch =================
extern "C" void kernel_launch(void* const* d_in, const int* in_sizes, int n_in,
                              void* d_out, int out_size) {
    const float* input = (const float*)d_in[0];
    const int*   node  = (const int*)d_in[1];
    const int*   erow  = (const int*)d_in[2];
    const int*   ecol  = (const int*)d_in[3];
    const float* H0    = (const float*)d_in[4];
    const float* W1    = (const float*)d_in[5];
    const float* W2    = (const float*)d_in[6];
    const float* Wa    = (const float*)d_in[7];
    const float* ba    = (const float*)d_in[8];
    const float* Wb    = (const float*)d_in[9];
    const float* bb    = (const float*)d_in[10];
    const float* Wc    = (const float*)d_in[11];
    const float* bc    = (const float*)d_in[12];
    float*       out   = (float*)d_out;

    void *p_cnt, *p_cursor, *p_h2;
    void *p_act, *p_x16, *p_w1t, *p_w2t, *p_fcf16, *p_wat, *p_wbt, *p_h1f16;
    void *p_f1, *p_f2, *p_list1, *p_list3, *p_n1, *p_n3;
    cudaGetSymbolAddress(&p_cnt,    g_cnt);
    cudaGetSymbolAddress(&p_cursor, g_cursor);
    cudaGetSymbolAddress(&p_h2,     g_h2);
    cudaGetSymbolAddress(&p_act,    g_act);
    cudaGetSymbolAddress(&p_x16,    g_x16);
    cudaGetSymbolAddress(&p_w1t,    g_w1t);
    cudaGetSymbolAddress(&p_w2t,    g_w2t);
    cudaGetSymbolAddress(&p_fcf16,  g_fcf16);
    cudaGetSymbolAddress(&p_wat,    g_wat);
    cudaGetSymbolAddress(&p_wbt,    g_wbt);
    cudaGetSymbolAddress(&p_h1f16,  g_h1f16);
    cudaGetSymbolAddress(&p_f1,     g_f1);
    cudaGetSymbolAddress(&p_f2,     g_f2);
    cudaGetSymbolAddress(&p_list1,  g_list1);
    cudaGetSymbolAddress(&p_list3,  g_list3);
    cudaGetSymbolAddress(&p_n1,     g_n1);
    cudaGetSymbolAddress(&p_n3,     g_n3);

    float* h2 = (float*)p_h2;

    cudaFuncSetAttribute(gemm_f16_kernel,
                         cudaFuncAttributeMaxDynamicSharedMemorySize, GS_TOTAL);

    static cudaStream_t s2 = nullptr, s3 = nullptr;
    static cudaEvent_t evF = nullptr, evS2 = nullptr, evS1 = nullptr, evCsr = nullptr;
    if (!s2) {
        cudaStreamCreateWithFlags(&s2, cudaStreamNonBlocking);
        cudaStreamCreateWithFlags(&s3, cudaStreamNonBlocking);
        cudaEventCreateWithFlags(&evF, cudaEventDisableTiming);
        cudaEventCreateWithFlags(&evS2, cudaEventDisableTiming);
        cudaEventCreateWithFlags(&evS1, cudaEventDisableTiming);
        cudaEventCreateWithFlags(&evCsr, cudaEventDisableTiming);
    }

    const int TPB = 256;
    const int nvBlocks = (NV + TPB - 1) / TPB;
    const int neBlocks = (NE + TPB - 1) / TPB;

    cudaEventRecord(evF, 0);

    // ---- s2: frontier construction (generation flags, no zeroing) ----
    cudaStreamWaitEvent(s2, evF, 0);
    bump_gen_kernel<<<1, 1, 0, s2>>>();
    mark_node_kernel<<<(BATCH + TPB - 1) / TPB, TPB, 0, s2>>>(node);
    mark_1hop_kernel<<<neBlocks, TPB, 0, s2>>>(erow, ecol);
    mark_2hop_kernel<<<neBlocks, TPB, 0, s2>>>(erow, ecol);
    compact_kernel<<<nvBlocks, TPB, 0, s2>>>((int*)p_f2, (int*)p_list3, (int*)p_n3);
    cudaEventRecord(evS2, s2);
    compact_kernel<<<nvBlocks, TPB, 0, s2>>>((int*)p_f1, (int*)p_list1, (int*)p_n1);
    cudaEventRecord(evS1, s2);

    // ---- s3: CSR build ----
    cudaStreamWaitEvent(s3, evF, 0);
    zero_int_kernel<<<nvBlocks, TPB, 0, s3>>>((int*)p_cnt, NV);
    zero_int_kernel<<<nvBlocks, TPB, 0, s3>>>((int*)p_cursor, NV);
    count_kernel<<<neBlocks, TPB, 0, s3>>>(erow);
    vals_kernel<<<neBlocks, TPB, 0, s3>>>(erow, ecol);
    scanA_kernel<<<NBLK_SCAN, 1024, 0, s3>>>();
    scanB_kernel<<<1, 128, 0, s3>>>();
    scanC_kernel<<<nvBlocks, TPB, 0, s3>>>();
    scatter_kernel<<<neBlocks, TPB, 0, s3>>>(erow, ecol);
    cudaEventRecord(evCsr, s3);

    // ---- main stream: weight + input conversions (fully independent) ----
    pre_wT_kernel<<<(EMB * EMB + TPB - 1) / TPB, TPB>>>(W1, EMB, EMB, AP, (__half*)p_w1t);
    pre_wT_kernel<<<(EMB * EMB + TPB - 1) / TPB, TPB>>>(W2, EMB, EMB, AP, (__half*)p_w2t);
    pre_wT_kernel<<<(FCK * HID + TPB - 1) / TPB, TPB>>>(Wa, FCK, HID, FCP, (__half*)p_wat);
    pre_wT_kernel<<<(HID * HID + TPB - 1) / TPB, TPB>>>(Wb, HID, HID, HP, (__half*)p_wbt);
    pre_input_f16_kernel<<<(BATCH * 192 + TPB - 1) / TPB, TPB>>>(input);

    // ---- join S2 frontier, then pre_act + GEMM1 on S2 rows ----
    cudaStreamWaitEvent(0, evS2, 0);
    pre_act_list_kernel<<<(NV * 75 + TPB - 1) / TPB, TPB>>>(H0, (int*)p_list3, (int*)p_n3);

    dim3 gbig(2, (NV + 127) / 128);
    gemm_f16_kernel<<<gbig, 512, GS_TOTAL>>>(
        (__half*)p_act, AP, (__half*)p_w1t, AP,
        nullptr, 0, (__half*)p_x16, AP, nullptr,
        (int*)p_list3, (int*)p_n3, NV, EMB, AP, 3);

    // ---- join CSR + S1, then SpMM 1 on S1 rows ----
    cudaStreamWaitEvent(0, evCsr, 0);
    cudaStreamWaitEvent(0, evS1, 0);
    int spmmBlocks = (NV * 32 + TPB - 1) / TPB;
    spmm_f16_kernel<<<spmmBlocks, TPB>>>((__half*)p_x16, (__half*)p_act,
                                         (int*)p_list1, (int*)p_n1);

    // ---- GCN layer 2 GEMM on S1 rows ----
    gemm_f16_kernel<<<gbig, 512, GS_TOTAL>>>(
        (__half*)p_act, AP, (__half*)p_w2t, AP,
        nullptr, 0, (__half*)p_x16, AP, nullptr,
        (int*)p_list1, (int*)p_n1, NV, EMB, AP, 3);

    // ---- fused SpMM2 + fc EMB-part (warp per batch element) ----
    spmm_fc_kernel<<<(BATCH * 32 + TPB - 1) / TPB, TPB>>>((__half*)p_x16, node);

    // ---- MLP head ----
    dim3 gmlp(4, BATCH / 128);
    gemm_f16_kernel<<<gmlp, 512, GS_TOTAL>>>(
        (__half*)p_fcf16, FCP, (__half*)p_wat, FCP,
        nullptr, 0, (__half*)p_h1f16, HP, ba,
        nullptr, nullptr, BATCH, HID, FCP, 2);
    gemm_f16_kernel<<<gmlp, 512, GS_TOTAL>>>(
        (__half*)p_h1f16, HP, (__half*)p_wbt, HP,
        h2, HID, nullptr, 0, bb,
        nullptr, nullptr, BATCH, HID, HP, 1);

    final_kernel<<<(BATCH * 32 + TPB - 1) / TPB, TPB>>>(h2, Wc, bc, out);
}